// round 6
// baseline (speedup 1.0000x reference)
#include <cuda_runtime.h>
#include <cuda_bf16.h>
#include <math.h>
#include <stdint.h>

#define D_MODEL 1024
#define HEADS 16
#define HD 64
#define BATCH 2
#define SEQ 2048
#define BL (BATCH * SEQ)      /* 4096 */
#define D3 (3 * D_MODEL)      /* 3072 */
#define NROWS (BATCH * HEADS * SEQ)

typedef __nv_bfloat16 bf16;

// ---------------------------------------------------------------------------
// Scratch (allocation-free: __device__ globals)
// ---------------------------------------------------------------------------
__device__ bf16  g_qkv_hi[(size_t)BL * D3];
__device__ bf16  g_qkv_lo[(size_t)BL * D3];
__device__ float g_psum[(size_t)NROWS * 16];
__device__ float g_inv[(size_t)NROWS];
__device__ float g_ao_f[(size_t)BL * D_MODEL];

// int8 2-digit operands
__device__ int8_t g_xd0[(size_t)BL * D_MODEL];
__device__ int8_t g_xd1[(size_t)BL * D_MODEL];
__device__ int8_t g_wqd0[(size_t)D3 * D_MODEL];
__device__ int8_t g_wqd1[(size_t)D3 * D_MODEL];
__device__ int8_t g_whd0[(size_t)D_MODEL * D_MODEL];
__device__ int8_t g_whd1[(size_t)D_MODEL * D_MODEL];
__device__ int8_t g_aod0[(size_t)BL * D_MODEL];
__device__ int8_t g_aod1[(size_t)BL * D_MODEL];
// scales
__device__ float g_rs_x[BL];
__device__ float g_s_wq[D3];
__device__ float g_rs_wq[D3];
__device__ float g_s_wh[D_MODEL];
__device__ float g_rs_wh[D_MODEL];
__device__ float g_rs_ao[BL];

// ---------------------------------------------------------------------------
// Portable PTX helpers
// ---------------------------------------------------------------------------
__device__ __forceinline__ uint32_t smem_u32(const void* p) {
    uint32_t a;
    asm("{ .reg .u64 t; cvta.to.shared.u64 t, %1; cvt.u32.u64 %0, t; }"
        : "=r"(a) : "l"(p));
    return a;
}
__device__ __forceinline__ void cp_async16(uint32_t s, const void* g) {
    asm volatile("cp.async.cg.shared.global [%0], [%1], 16;" :: "r"(s), "l"(g));
}
#define CP_COMMIT() asm volatile("cp.async.commit_group;" ::: "memory")
#define CP_WAIT(n)  asm volatile("cp.async.wait_group %0;" :: "n"(n) : "memory")

__device__ __forceinline__ void ldm_x4(uint32_t addr, uint32_t* r) {
    asm volatile("ldmatrix.sync.aligned.m8n8.x4.shared.b16 {%0,%1,%2,%3}, [%4];"
        : "=r"(r[0]), "=r"(r[1]), "=r"(r[2]), "=r"(r[3]) : "r"(addr));
}
__device__ __forceinline__ void ldm_x4_trans(uint32_t addr, uint32_t* r) {
    asm volatile("ldmatrix.sync.aligned.m8n8.x4.trans.shared.b16 {%0,%1,%2,%3}, [%4];"
        : "=r"(r[0]), "=r"(r[1]), "=r"(r[2]), "=r"(r[3]) : "r"(addr));
}
__device__ __forceinline__ void mma_bf16(float* c, const uint32_t* a, const uint32_t* b) {
    asm volatile(
        "mma.sync.aligned.m16n8k16.row.col.f32.bf16.bf16.f32 "
        "{%0,%1,%2,%3}, {%4,%5,%6,%7}, {%8,%9}, {%0,%1,%2,%3};"
        : "+f"(c[0]), "+f"(c[1]), "+f"(c[2]), "+f"(c[3])
        : "r"(a[0]), "r"(a[1]), "r"(a[2]), "r"(a[3]), "r"(b[0]), "r"(b[1]));
}
__device__ __forceinline__ void mma_s8(int* c, const uint32_t* a, const uint32_t* b) {
    asm volatile(
        "mma.sync.aligned.m16n8k32.row.col.s32.s8.s8.s32 "
        "{%0,%1,%2,%3}, {%4,%5,%6,%7}, {%8,%9}, {%0,%1,%2,%3};"
        : "+r"(c[0]), "+r"(c[1]), "+r"(c[2]), "+r"(c[3])
        : "r"(a[0]), "r"(a[1]), "r"(a[2]), "r"(a[3]), "r"(b[0]), "r"(b[1]));
}
__device__ __forceinline__ void split_store2(bf16* hi, bf16* lo, size_t idx,
                                             float a, float b) {
    bf16 ha = __float2bfloat16(a), hb = __float2bfloat16(b);
    bf16 la = __float2bfloat16(a - __bfloat162float(ha));
    bf16 lb = __float2bfloat16(b - __bfloat162float(hb));
    __nv_bfloat162 hv; hv.x = ha; hv.y = hb;
    __nv_bfloat162 lv; lv.x = la; lv.y = lb;
    *(__nv_bfloat162*)(hi + idx) = hv;
    *(__nv_bfloat162*)(lo + idx) = lv;
}
__device__ __forceinline__ float fexp(float x) {
    float t = x * 1.4426950408889634f;
    t = fmaxf(t, -126.0f);
    float n = rintf(t);
    float f = t - n;
    float p = 1.5403530e-4f;
    p = fmaf(p, f, 1.3333558e-3f);
    p = fmaf(p, f, 9.6181291e-3f);
    p = fmaf(p, f, 5.5504109e-2f);
    p = fmaf(p, f, 2.4022651e-1f);
    p = fmaf(p, f, 6.9314718e-1f);
    p = fmaf(p, f, 1.0f);
    return p * __int_as_float(((int)n + 127) << 23);
}
__device__ __forceinline__ void quant2(float X, int8_t& q0, int8_t& q1) {
    float d0f = rintf(X * 0.00390625f);
    float r = fmaf(d0f, -256.0f, X);
    int i1 = (int)rintf(r);
    i1 = max(-128, min(127, i1));
    q0 = (int8_t)(int)d0f;
    q1 = (int8_t)i1;
}

// ---------------------------------------------------------------------------
// Row quantizer: in fp32 [R,1024] -> d0,d1 int8 + rs[row]. One CTA per row.
// ---------------------------------------------------------------------------
__global__ __launch_bounds__(256) void quant_rows_kernel(
    const float* __restrict__ in, int8_t* __restrict__ d0,
    int8_t* __restrict__ d1, float* __restrict__ rs)
{
    const int row = blockIdx.x;
    const int t = threadIdx.x;
    const float* p = in + (size_t)row * 1024;
    float4 v = ((const float4*)p)[t];
    float m = fmaxf(fmaxf(fabsf(v.x), fabsf(v.y)), fmaxf(fabsf(v.z), fabsf(v.w)));
    #pragma unroll
    for (int o = 16; o > 0; o >>= 1) m = fmaxf(m, __shfl_xor_sync(0xffffffffu, m, o));
    __shared__ float red[8];
    if ((t & 31) == 0) red[t >> 5] = m;
    __syncthreads();
    float mx = red[0];
    #pragma unroll
    for (int w = 1; w < 8; w++) mx = fmaxf(mx, red[w]);
    mx = fmaxf(mx, 1e-30f);
    float s = 32000.0f / mx;
    if (t == 0) rs[row] = mx * (1.0f / 32000.0f);
    char4 c0, c1;
    quant2(v.x * s, (int8_t&)c0.x, (int8_t&)c1.x);
    quant2(v.y * s, (int8_t&)c0.y, (int8_t&)c1.y);
    quant2(v.z * s, (int8_t&)c0.z, (int8_t&)c1.z);
    quant2(v.w * s, (int8_t&)c0.w, (int8_t&)c1.w);
    ((char4*)(d0 + (size_t)row * 1024))[t] = c0;
    ((char4*)(d1 + (size_t)row * 1024))[t] = c1;
}

// ---------------------------------------------------------------------------
// Weight column max: W [K,N] -> s[col], rs[col]. Block = 32 cols.
// ---------------------------------------------------------------------------
__global__ __launch_bounds__(256) void wcolmax_kernel(
    const float* __restrict__ W, float* __restrict__ s, float* __restrict__ rs,
    int K, int N)
{
    const int t = threadIdx.x;
    const int col = blockIdx.x * 32 + (t & 31);
    const int ty = t >> 5;
    float m = 0.0f;
    for (int r = ty; r < K; r += 8)
        m = fmaxf(m, fabsf(W[(size_t)r * N + col]));
    __shared__ float sm_[8][32];
    sm_[ty][t & 31] = m;
    __syncthreads();
    if (t < 32) {
        float mx = sm_[0][t];
        #pragma unroll
        for (int i = 1; i < 8; i++) mx = fmaxf(mx, sm_[i][t]);
        mx = fmaxf(mx, 1e-30f);
        int c = blockIdx.x * 32 + t;
        s[c] = 32000.0f / mx;
        rs[c] = mx * (1.0f / 32000.0f);
    }
}

// ---------------------------------------------------------------------------
// Transpose + quantize: W [K,N] -> d0,d1 [N,K] int8 using s[col].
// ---------------------------------------------------------------------------
__global__ __launch_bounds__(256) void transpose_quant_kernel(
    const float* __restrict__ W, const float* __restrict__ s,
    int8_t* __restrict__ d0, int8_t* __restrict__ d1, int K, int N)
{
    __shared__ float tile[32][33];
    const int nx = blockIdx.x * 32;
    const int ky = blockIdx.y * 32;
    const int tx = threadIdx.x & 31;
    const int ty = threadIdx.x >> 5;
    #pragma unroll
    for (int i = 0; i < 4; i++)
        tile[ty + 8 * i][tx] = W[(size_t)(ky + ty + 8 * i) * N + nx + tx];
    __syncthreads();
    #pragma unroll
    for (int i = 0; i < 4; i++) {
        int n = nx + ty + 8 * i;
        float X = tile[tx][ty + 8 * i] * s[n];
        int8_t q0, q1;
        quant2(X, q0, q1);
        size_t o = (size_t)n * K + ky + tx;
        d0[o] = q0;
        d1[o] = q1;
    }
}

// ---------------------------------------------------------------------------
// int8 2-digit IMMA GEMM: C[M,N] = A[M,K] @ B[N,K]^T (reconstructed fp32)
// CTA 128x128, 512 threads (16 warps, warp tile 16x64), BK=64, 2-stage.
// EPI 0: split-store bf16 hi/lo.  EPI 1: fp32 + bias.
// ---------------------------------------------------------------------------
#define IP 80                       /* smem pitch bytes (64 data + 16 pad) */
#define IT_BYTES (128 * IP)         /* 10240 */
#define IS_BYTES (4 * IT_BYTES)     /* 40960 */
#define SMEM_IMMA (2 * IS_BYTES)    /* 81920 */

template <int EPI>
__global__ __launch_bounds__(512, 1) void imma_gemm_kernel(
    const int8_t* __restrict__ Ad0, const int8_t* __restrict__ Ad1,
    const int8_t* __restrict__ Bd0, const int8_t* __restrict__ Bd1,
    const float* __restrict__ rsA, const float* __restrict__ rsB,
    float* __restrict__ C, bf16* __restrict__ Chi, bf16* __restrict__ Clo,
    const float* __restrict__ bias, int M, int N, int K)
{
    extern __shared__ char sm8[];
    const uint32_t sbase = smem_u32(sm8);
    const int t = threadIdx.x;
    const int warp = t >> 5, lane = t & 31;
    const int bm = blockIdx.y * 128;
    const int bn = blockIdx.x * 128;
    const int wm = (warp >> 1) * 16;
    const int wn = (warp & 1) * 64;

    const int8_t* srcs[4] = { Ad0, Ad1, Bd0, Bd1 };

    auto load_stage = [&](int buf, int k0) {
        uint32_t sdst = sbase + (uint32_t)buf * IS_BYTES;
        #pragma unroll
        for (int m = 0; m < 4; m++) {
            const int rbase = (m < 2) ? bm : bn;
            const int8_t* S = srcs[m] + (size_t)rbase * K + k0;
            uint32_t td = sdst + (uint32_t)m * IT_BYTES;
            int row = t >> 2, seg = t & 3;           // 512 segs, 1 per thread
            cp_async16(td + (uint32_t)(row * IP + seg * 16),
                       S + (size_t)row * K + seg * 16);
        }
        CP_COMMIT();
    };

    int acc0[8][4], acc1[8][4];
    #pragma unroll
    for (int nj = 0; nj < 8; nj++)
        #pragma unroll
        for (int e = 0; e < 4; e++) { acc0[nj][e] = 0; acc1[nj][e] = 0; }

    const int nch = K >> 6;
    load_stage(0, 0);
    load_stage(1, 64);

    const int a_r = (lane & 7) + ((lane >> 3) & 1) * 8;
    const int a_c16 = (lane >> 4) * 16;              // byte offset
    const int b_r = (lane & 7) + (lane >> 4) * 8;
    const int b_c16 = ((lane >> 3) & 1) * 16;

    for (int c = 0; c < nch; c++) {
        if (c < nch - 1) { CP_WAIT(1); } else { CP_WAIT(0); }
        __syncthreads();

        const uint32_t stg = sbase + (uint32_t)(c & 1) * IS_BYTES;
        const uint32_t tA0 = stg;
        const uint32_t tA1 = stg + IT_BYTES;
        const uint32_t tB0 = stg + 2 * IT_BYTES;
        const uint32_t tB1 = stg + 3 * IT_BYTES;

        #pragma unroll
        for (int ks = 0; ks < 2; ks++) {
            uint32_t a0[4], a1[4], b0[16], b1[16];
            uint32_t aoff = (uint32_t)((wm + a_r) * IP + ks * 32 + a_c16);
            ldm_x4(tA0 + aoff, a0);
            ldm_x4(tA1 + aoff, a1);
            #pragma unroll
            for (int nj2 = 0; nj2 < 4; nj2++) {
                uint32_t boff =
                    (uint32_t)((wn + nj2 * 16 + b_r) * IP + ks * 32 + b_c16);
                ldm_x4(tB0 + boff, b0 + nj2 * 4);
                ldm_x4(tB1 + boff, b1 + nj2 * 4);
            }
            #pragma unroll
            for (int nj = 0; nj < 8; nj++) {
                mma_s8(acc0[nj], a0, b0 + nj * 2);   // d0*e0
                mma_s8(acc1[nj], a0, b1 + nj * 2);   // d0*e1
                mma_s8(acc1[nj], a1, b0 + nj * 2);   // d1*e0
            }
        }
        __syncthreads();
        if (c + 2 < nch) load_stage(c & 1, (c + 2) * 64);
    }

    const int group = lane >> 2, tid4 = lane & 3;
    const int r0 = bm + wm + group;
    const float ra0 = rsA[r0], ra1 = rsA[r0 + 8];
    #pragma unroll
    for (int nj = 0; nj < 8; nj++) {
        int cc = bn + wn + nj * 8 + tid4 * 2;
        float rb0 = rsB[cc], rb1 = rsB[cc + 1];
        float v00 = fmaf(65536.0f, (float)acc0[nj][0], 256.0f * (float)acc1[nj][0]) * (ra0 * rb0);
        float v01 = fmaf(65536.0f, (float)acc0[nj][1], 256.0f * (float)acc1[nj][1]) * (ra0 * rb1);
        float v10 = fmaf(65536.0f, (float)acc0[nj][2], 256.0f * (float)acc1[nj][2]) * (ra1 * rb0);
        float v11 = fmaf(65536.0f, (float)acc0[nj][3], 256.0f * (float)acc1[nj][3]) * (ra1 * rb1);
        if (EPI == 1) {
            float2 bb = *(const float2*)(bias + cc);
            *(float2*)(C + (size_t)r0 * N + cc) = make_float2(v00 + bb.x, v01 + bb.y);
            *(float2*)(C + (size_t)(r0 + 8) * N + cc) = make_float2(v10 + bb.x, v11 + bb.y);
        } else {
            split_store2(Chi, Clo, (size_t)r0 * N + cc, v00, v01);
            split_store2(Chi, Clo, (size_t)(r0 + 8) * N + cc, v10, v11);
        }
    }
}

// ---------------------------------------------------------------------------
// Scores via bf16 HMMA, fused mask+scale+exp; unnormalized out + psums.
// ---------------------------------------------------------------------------
#define SP 72
#define ST_ELEMS (128 * SP)
#define SMEM_SCORES (4 * ST_ELEMS * 2)

__global__ __launch_bounds__(256) void scores_mma_kernel(
    const float* __restrict__ mask, float* __restrict__ attn,
    const bf16* __restrict__ qhi, const bf16* __restrict__ qlo,
    float* __restrict__ psum)
{
    extern __shared__ bf16 sm[];
    const uint32_t sbase = smem_u32(sm);
    const int t = threadIdx.x;
    const int warp = t >> 5, lane = t & 31;
    const int bh = blockIdx.z;
    const int b = bh / HEADS, h = bh % HEADS;
    const int bm = blockIdx.y * 128;
    const int bn = blockIdx.x * 128;
    const int wm = (warp >> 1) * 32;
    const int wn = (warp & 1) * 64;

    const bf16* bases[4] = {
        qhi + ((size_t)(b * SEQ + bm)) * D3 + h * HD,
        qlo + ((size_t)(b * SEQ + bm)) * D3 + h * HD,
        qhi + ((size_t)(b * SEQ + bn)) * D3 + D_MODEL + h * HD,
        qlo + ((size_t)(b * SEQ + bn)) * D3 + D_MODEL + h * HD };
    #pragma unroll
    for (int m = 0; m < 4; m++) {
        uint32_t td = sbase + (uint32_t)m * ST_ELEMS * 2;
        #pragma unroll
        for (int i = 0; i < 4; i++) {
            int id = t + i * 256;
            int r = id >> 3, c = id & 7;
            cp_async16(td + (uint32_t)(r * SP + c * 8) * 2,
                       bases[m] + (size_t)r * D3 + c * 8);
        }
    }
    CP_COMMIT();

    float acc[2][8][4];
    #pragma unroll
    for (int mi = 0; mi < 2; mi++)
        #pragma unroll
        for (int nj = 0; nj < 8; nj++)
            #pragma unroll
            for (int e = 0; e < 4; e++) acc[mi][nj][e] = 0.0f;

    const int a_r = (lane & 7) + ((lane >> 3) & 1) * 8;
    const int a_c = (lane >> 4) * 8;
    const int b_r = (lane & 7) + (lane >> 4) * 8;
    const int b_c = ((lane >> 3) & 1) * 8;

    const uint32_t tQhi = sbase;
    const uint32_t tQlo = sbase + ST_ELEMS * 2;
    const uint32_t tKhi = sbase + 2 * ST_ELEMS * 2;
    const uint32_t tKlo = sbase + 3 * ST_ELEMS * 2;

    CP_WAIT(0);
    __syncthreads();

    #pragma unroll
    for (int ks = 0; ks < 4; ks++) {
        uint32_t ah[2][4], al[2][4], bhf[16], blf[16];
        #pragma unroll
        for (int mi = 0; mi < 2; mi++) {
            uint32_t off = (uint32_t)((wm + mi * 16 + a_r) * SP + ks * 16 + a_c) * 2;
            ldm_x4(tQhi + off, ah[mi]);
            ldm_x4(tQlo + off, al[mi]);
        }
        #pragma unroll
        for (int nj2 = 0; nj2 < 4; nj2++) {
            uint32_t off = (uint32_t)((wn + nj2 * 16 + b_r) * SP + ks * 16 + b_c) * 2;
            ldm_x4(tKhi + off, bhf + nj2 * 4);
            ldm_x4(tKlo + off, blf + nj2 * 4);
        }
        #pragma unroll
        for (int mi = 0; mi < 2; mi++)
            #pragma unroll
            for (int nj = 0; nj < 8; nj++) {
                mma_bf16(acc[mi][nj], ah[mi], bhf + nj * 2);
                mma_bf16(acc[mi][nj], ah[mi], blf + nj * 2);
                mma_bf16(acc[mi][nj], al[mi], bhf + nj * 2);
            }
    }

    const int group = lane >> 2, tid4 = lane & 3;
    float mq[4];
    #pragma unroll
    for (int mi = 0; mi < 2; mi++) {
        mq[mi * 2 + 0] = mask[b * SEQ + bm + wm + mi * 16 + group];
        mq[mi * 2 + 1] = mask[b * SEQ + bm + wm + mi * 16 + group + 8];
    }
    float* out = attn + (size_t)bh * SEQ * SEQ;
    float srow[2][2];
    srow[0][0] = srow[0][1] = srow[1][0] = srow[1][1] = 0.0f;
    #pragma unroll
    for (int nj = 0; nj < 8; nj++) {
        int cc = bn + wn + nj * 8 + tid4 * 2;
        float2 mk = *(const float2*)(mask + b * SEQ + cc);
        #pragma unroll
        for (int mi = 0; mi < 2; mi++) {
            int r0 = bm + wm + mi * 16 + group;
            float v0 = acc[mi][nj][0], v1 = acc[mi][nj][1];
            float v2 = acc[mi][nj][2], v3 = acc[mi][nj][3];
            if (mq[mi * 2 + 0] * mk.x == 0.0f) v0 = -100000.0f;
            if (mq[mi * 2 + 0] * mk.y == 0.0f) v1 = -100000.0f;
            if (mq[mi * 2 + 1] * mk.x == 0.0f) v2 = -100000.0f;
            if (mq[mi * 2 + 1] * mk.y == 0.0f) v3 = -100000.0f;
            float e0 = fexp(v0 * 0.03125f), e1 = fexp(v1 * 0.03125f);
            float e2 = fexp(v2 * 0.03125f), e3 = fexp(v3 * 0.03125f);
            *(float2*)(out + (size_t)r0 * SEQ + cc) = make_float2(e0, e1);
            *(float2*)(out + (size_t)(r0 + 8) * SEQ + cc) = make_float2(e2, e3);
            srow[mi][0] += e0 + e1;
            srow[mi][1] += e2 + e3;
        }
    }
    #pragma unroll
    for (int mi = 0; mi < 2; mi++) {
        #pragma unroll
        for (int s = 0; s < 2; s++) {
            srow[mi][s] += __shfl_xor_sync(0xffffffffu, srow[mi][s], 1);
            srow[mi][s] += __shfl_xor_sync(0xffffffffu, srow[mi][s], 2);
        }
    }
    __syncthreads();
    float* rs = (float*)sm;
    if (tid4 == 0) {
        #pragma unroll
        for (int mi = 0; mi < 2; mi++) {
            rs[(wm + mi * 16 + group) * 2 + (warp & 1)] = srow[mi][0];
            rs[(wm + mi * 16 + group + 8) * 2 + (warp & 1)] = srow[mi][1];
        }
    }
    __syncthreads();
    if (t < 128)
        psum[((size_t)bh * SEQ + bm + t) * 16 + blockIdx.x] = rs[t * 2] + rs[t * 2 + 1];
}

// ---------------------------------------------------------------------------
__global__ __launch_bounds__(256) void rowinv_kernel(
    const float* __restrict__ psum, float* __restrict__ inv)
{
    int r = blockIdx.x * 256 + threadIdx.x;
    if (r >= NROWS) return;
    float4 a = *(const float4*)(psum + (size_t)r * 16);
    float4 b2 = *(const float4*)(psum + (size_t)r * 16 + 4);
    float4 c = *(const float4*)(psum + (size_t)r * 16 + 8);
    float4 d = *(const float4*)(psum + (size_t)r * 16 + 12);
    float s = a.x + a.y + a.z + a.w + b2.x + b2.y + b2.z + b2.w
            + c.x + c.y + c.z + c.w + d.x + d.y + d.z + d.w;
    inv[r] = 1.0f / s;
}

// ---------------------------------------------------------------------------
// attn @ V via bf16 HMMA; normalizes attn in place; fp32 ao out.
// ---------------------------------------------------------------------------
#define AVP 72
#define AV_STAGEF 0
#define AV_AHI    34816
#define AV_ALO    (34816 + 18432)
#define AV_VHI(i) (71680 + (i) * 9216)
#define AV_VLO(i) (90112 + (i) * 9216)
#define AV_INV    108544
#define SMEM_AV   (108544 + 512)

__global__ __launch_bounds__(256) void av_mma_kernel(
    float* __restrict__ attn,
    const bf16* __restrict__ qhi, const bf16* __restrict__ qlo,
    float* __restrict__ aoF, const float* __restrict__ inv)
{
    extern __shared__ char smc[];
    const uint32_t sbase = smem_u32(smc);
    const int t = threadIdx.x;
    const int warp = t >> 5, lane = t & 31;
    const int bh = blockIdx.y;
    const int b = bh / HEADS, h = bh % HEADS;
    const int bm = blockIdx.x * 128;
    const int wm = warp * 16;

    float* Abase = attn + (size_t)bh * SEQ * SEQ + (size_t)bm * SEQ;
    const bf16* Vhi = qhi + (size_t)b * SEQ * D3 + 2 * D_MODEL + h * HD;
    const bf16* Vlo = qlo + (size_t)b * SEQ * D3 + 2 * D_MODEL + h * HD;

    float* inv_s = (float*)(smc + AV_INV);
    if (t < 128) inv_s[t] = inv[(size_t)bh * SEQ + bm + t];

    auto load_chunk = [&](int c) {
        const int k0 = c * 64;
        #pragma unroll
        for (int i = 0; i < 8; i++) {
            int id = t + i * 256;
            int r = id >> 4, c4 = id & 15;
            cp_async16(sbase + AV_STAGEF + (uint32_t)(r * 68 + c4 * 4) * 4,
                       Abase + (size_t)r * SEQ + k0 + c4 * 4);
        }
        const uint32_t vb = c & 1;
        #pragma unroll
        for (int i = 0; i < 2; i++) {
            int id = t + i * 256;
            int r = id >> 3, cs = id & 7;
            cp_async16(sbase + AV_VHI(vb) + (uint32_t)(r * AVP + cs * 8) * 2,
                       Vhi + (size_t)(k0 + r) * D3 + cs * 8);
            cp_async16(sbase + AV_VLO(vb) + (uint32_t)(r * AVP + cs * 8) * 2,
                       Vlo + (size_t)(k0 + r) * D3 + cs * 8);
        }
        CP_COMMIT();
    };

    float acc[8][4];
    #pragma unroll
    for (int nj = 0; nj < 8; nj++)
        #pragma unroll
        for (int e = 0; e < 4; e++) acc[nj][e] = 0.0f;

    load_chunk(0);

    const int a_r = (lane & 7) + ((lane >> 3) & 1) * 8;
    const int a_c = (lane >> 4) * 8;
    const int tb_r = lane & 15;
    const int tb_c = (lane >> 4) * 8;

    const float* stageF = (const float*)(smc + AV_STAGEF);
    bf16* Ahi_s = (bf16*)(smc + AV_AHI);
    bf16* Alo_s = (bf16*)(smc + AV_ALO);

    for (int c = 0; c < SEQ / 64; c++) {
        CP_WAIT(0);
        __syncthreads();
        const int k0 = c * 64;
        #pragma unroll
        for (int i = 0; i < 8; i++) {
            int id = t + i * 256;
            int r = id >> 4, c4 = id & 15;
            float4 v = *(const float4*)(stageF + r * 68 + c4 * 4);
            float s = inv_s[r];
            v.x *= s; v.y *= s; v.z *= s; v.w *= s;
            *(float4*)(Abase + (size_t)r * SEQ + k0 + c4 * 4) = v;
            bf16 h4[4], l4[4];
            float vv[4] = { v.x, v.y, v.z, v.w };
            #pragma unroll
            for (int j = 0; j < 4; j++) {
                h4[j] = __float2bfloat16(vv[j]);
                l4[j] = __float2bfloat16(vv[j] - __bfloat162float(h4[j]));
            }
            *(uint2*)(Ahi_s + r * AVP + c4 * 4) = *(uint2*)h4;
            *(uint2*)(Alo_s + r * AVP + c4 * 4) = *(uint2*)l4;
        }
        __syncthreads();
        if (c + 1 < SEQ / 64) load_chunk(c + 1);

        const uint32_t tAhi = sbase + AV_AHI;
        const uint32_t tAlo = sbase + AV_ALO;
        const uint32_t tVhi = sbase + AV_VHI(c & 1);
        const uint32_t tVlo = sbase + AV_VLO(c & 1);

        #pragma unroll
        for (int ks = 0; ks < 4; ks++) {
            uint32_t ah[4], al[4], bhf[16], blf[16];
            uint32_t aoff = (uint32_t)((wm + a_r) * AVP + ks * 16 + a_c) * 2;
            ldm_x4(tAhi + aoff, ah);
            ldm_x4(tAlo + aoff, al);
            #pragma unroll
            for (int nj2 = 0; nj2 < 4; nj2++) {
                uint32_t boff =
                    (uint32_t)((ks * 16 + tb_r) * AVP + nj2 * 16 + tb_c) * 2;
                ldm_x4_trans(tVhi + boff, bhf + nj2 * 4);
                ldm_x4_trans(tVlo + boff, blf + nj2 * 4);
            }
            #pragma unroll
            for (int nj = 0; nj < 8; nj++) {
                mma_bf16(acc[nj], ah, bhf + nj * 2);
                mma_bf16(acc[nj], ah, blf + nj * 2);
                mma_bf16(acc[nj], al, bhf + nj * 2);
            }
        }
    }

    const int group = lane >> 2, tid4 = lane & 3;
    #pragma unroll
    for (int nj = 0; nj < 8; nj++) {
        int cc = h * HD + nj * 8 + tid4 * 2;
        size_t r0 = (size_t)(b * SEQ + bm + wm + group) * D_MODEL + cc;
        size_t r1 = r0 + (size_t)8 * D_MODEL;
        *(float2*)(aoF + r0) = make_float2(acc[nj][0], acc[nj][1]);
        *(float2*)(aoF + r1) = make_float2(acc[nj][2], acc[nj][3]);
    }
}

// ---------------------------------------------------------------------------
extern "C" void kernel_launch(void* const* d_in, const int* in_sizes, int n_in,
                              void* d_out, int out_size)
{
    const float* x     = (const float*)d_in[0];
    const float* mask  = (const float*)d_in[1];
    const float* W_qkv = (const float*)d_in[2];
    const float* W_h   = (const float*)d_in[3];
    const float* b_h   = (const float*)d_in[4];

    float* out  = (float*)d_out;
    float* attn = out + (size_t)BL * D_MODEL;

    bf16 *qhi, *qlo;
    float *psum, *inv, *aoF;
    int8_t *xd0, *xd1, *wqd0, *wqd1, *whd0, *whd1, *aod0, *aod1;
    float *rs_x, *s_wq, *rs_wq, *s_wh, *rs_wh, *rs_ao;
    cudaGetSymbolAddress((void**)&qhi, g_qkv_hi);
    cudaGetSymbolAddress((void**)&qlo, g_qkv_lo);
    cudaGetSymbolAddress((void**)&psum, g_psum);
    cudaGetSymbolAddress((void**)&inv, g_inv);
    cudaGetSymbolAddress((void**)&aoF, g_ao_f);
    cudaGetSymbolAddress((void**)&xd0, g_xd0);
    cudaGetSymbolAddress((void**)&xd1, g_xd1);
    cudaGetSymbolAddress((void**)&wqd0, g_wqd0);
    cudaGetSymbolAddress((void**)&wqd1, g_wqd1);
    cudaGetSymbolAddress((void**)&whd0, g_whd0);
    cudaGetSymbolAddress((void**)&whd1, g_whd1);
    cudaGetSymbolAddress((void**)&aod0, g_aod0);
    cudaGetSymbolAddress((void**)&aod1, g_aod1);
    cudaGetSymbolAddress((void**)&rs_x, g_rs_x);
    cudaGetSymbolAddress((void**)&s_wq, g_s_wq);
    cudaGetSymbolAddress((void**)&rs_wq, g_rs_wq);
    cudaGetSymbolAddress((void**)&s_wh, g_s_wh);
    cudaGetSymbolAddress((void**)&rs_wh, g_rs_wh);
    cudaGetSymbolAddress((void**)&rs_ao, g_rs_ao);

    cudaFuncSetAttribute(imma_gemm_kernel<0>, cudaFuncAttributeMaxDynamicSharedMemorySize, SMEM_IMMA);
    cudaFuncSetAttribute(imma_gemm_kernel<1>, cudaFuncAttributeMaxDynamicSharedMemorySize, SMEM_IMMA);
    cudaFuncSetAttribute(scores_mma_kernel, cudaFuncAttributeMaxDynamicSharedMemorySize, SMEM_SCORES);
    cudaFuncSetAttribute(av_mma_kernel, cudaFuncAttributeMaxDynamicSharedMemorySize, SMEM_AV);

    // 0) quantize x and weights
    quant_rows_kernel<<<BL, 256>>>(x, xd0, xd1, rs_x);
    wcolmax_kernel<<<D3 / 32, 256>>>(W_qkv, s_wq, rs_wq, D_MODEL, D3);
    transpose_quant_kernel<<<dim3(D3 / 32, D_MODEL / 32), 256>>>(W_qkv, s_wq, wqd0, wqd1, D_MODEL, D3);
    wcolmax_kernel<<<D_MODEL / 32, 256>>>(W_h, s_wh, rs_wh, D_MODEL, D_MODEL);
    transpose_quant_kernel<<<dim3(D_MODEL / 32, D_MODEL / 32), 256>>>(W_h, s_wh, whd0, whd1, D_MODEL, D_MODEL);

    // 1) QKV = x @ W_qkv (int8 IMMA) -> bf16 hi/lo
    imma_gemm_kernel<0><<<dim3(D3 / 128, BL / 128), 512, SMEM_IMMA>>>(
        xd0, xd1, wqd0, wqd1, rs_x, rs_wq, nullptr, qhi, qlo, nullptr,
        BL, D3, D_MODEL);

    // 2) scores + fused exp -> unnormalized attn + psums
    scores_mma_kernel<<<dim3(SEQ / 128, SEQ / 128, BATCH * HEADS), 256, SMEM_SCORES>>>(
        mask, attn, qhi, qlo, psum);

    // 3) row-sum inverse
    rowinv_kernel<<<NROWS / 256, 256>>>(psum, inv);

    // 4) attn @ V (normalizes attn in place) -> ao fp32
    av_mma_kernel<<<dim3(SEQ / 128, BATCH * HEADS), 256, SMEM_AV>>>(
        attn, qhi, qlo, aoF, inv);

    // 5) quantize ao, then output = ao @ W_h + b_h (int8 IMMA)
    quant_rows_kernel<<<BL, 256>>>(aoF, aod0, aod1, rs_ao);
    imma_gemm_kernel<1><<<dim3(D_MODEL / 128, BL / 128), 512, SMEM_IMMA>>>(
        aod0, aod1, whd0, whd1, rs_ao, rs_wh, out, nullptr, nullptr, b_h,
        BL, D_MODEL, D_MODEL);
}

// round 8
// speedup vs baseline: 1.7832x; 1.7832x over previous
#include <cuda_runtime.h>
#include <cuda_bf16.h>
#include <cuda_fp16.h>
#include <math.h>
#include <stdint.h>

#define D_MODEL 1024
#define HEADS 16
#define HD 64
#define BATCH 2
#define SEQ 2048
#define BL (BATCH * SEQ)      /* 4096 */
#define D3 (3 * D_MODEL)      /* 3072 */
#define NROWS (BATCH * HEADS * SEQ)

typedef __nv_bfloat16 bf16;

// ---------------------------------------------------------------------------
// Scratch (allocation-free: __device__ globals)
// ---------------------------------------------------------------------------
__device__ bf16  g_x_hi[(size_t)BL * D_MODEL];
__device__ bf16  g_x_lo[(size_t)BL * D_MODEL];
__device__ bf16  g_wqkvT_hi[(size_t)D3 * D_MODEL];
__device__ bf16  g_wqkvT_lo[(size_t)D3 * D_MODEL];
__device__ bf16  g_whT_hi[(size_t)D_MODEL * D_MODEL];
__device__ bf16  g_whT_lo[(size_t)D_MODEL * D_MODEL];
__device__ __half g_q16h[(size_t)BL * D3];     // QKV fp16 hi
__device__ __half g_q16l[(size_t)BL * D3];     // QKV fp16 lo
__device__ bf16  g_ao_hi[(size_t)BL * D_MODEL];
__device__ bf16  g_ao_lo[(size_t)BL * D_MODEL];
__device__ float g_psum[(size_t)NROWS * 16];
__device__ float g_inv[(size_t)NROWS];

// ---------------------------------------------------------------------------
// Portable PTX helpers
// ---------------------------------------------------------------------------
__device__ __forceinline__ uint32_t smem_u32(const void* p) {
    uint32_t a;
    asm("{ .reg .u64 t; cvta.to.shared.u64 t, %1; cvt.u32.u64 %0, t; }"
        : "=r"(a) : "l"(p));
    return a;
}
__device__ __forceinline__ void cp_async16(uint32_t s, const void* g) {
    asm volatile("cp.async.cg.shared.global [%0], [%1], 16;" :: "r"(s), "l"(g));
}
#define CP_COMMIT() asm volatile("cp.async.commit_group;" ::: "memory")
#define CP_WAIT(n)  asm volatile("cp.async.wait_group %0;" :: "n"(n) : "memory")

__device__ __forceinline__ void ldm_x4(uint32_t addr, uint32_t* r) {
    asm volatile("ldmatrix.sync.aligned.m8n8.x4.shared.b16 {%0,%1,%2,%3}, [%4];"
        : "=r"(r[0]), "=r"(r[1]), "=r"(r[2]), "=r"(r[3]) : "r"(addr));
}
__device__ __forceinline__ void ldm_x4_trans(uint32_t addr, uint32_t* r) {
    asm volatile("ldmatrix.sync.aligned.m8n8.x4.trans.shared.b16 {%0,%1,%2,%3}, [%4];"
        : "=r"(r[0]), "=r"(r[1]), "=r"(r[2]), "=r"(r[3]) : "r"(addr));
}
__device__ __forceinline__ void mma_bf16(float* c, const uint32_t* a, const uint32_t* b) {
    asm volatile(
        "mma.sync.aligned.m16n8k16.row.col.f32.bf16.bf16.f32 "
        "{%0,%1,%2,%3}, {%4,%5,%6,%7}, {%8,%9}, {%0,%1,%2,%3};"
        : "+f"(c[0]), "+f"(c[1]), "+f"(c[2]), "+f"(c[3])
        : "r"(a[0]), "r"(a[1]), "r"(a[2]), "r"(a[3]), "r"(b[0]), "r"(b[1]));
}
__device__ __forceinline__ void mma_f16(float* c, const uint32_t* a, const uint32_t* b) {
    asm volatile(
        "mma.sync.aligned.m16n8k16.row.col.f32.f16.f16.f32 "
        "{%0,%1,%2,%3}, {%4,%5,%6,%7}, {%8,%9}, {%0,%1,%2,%3};"
        : "+f"(c[0]), "+f"(c[1]), "+f"(c[2]), "+f"(c[3])
        : "r"(a[0]), "r"(a[1]), "r"(a[2]), "r"(a[3]), "r"(b[0]), "r"(b[1]));
}
__device__ __forceinline__ void split_store2_bf(bf16* hi, bf16* lo, size_t idx,
                                                float a, float b) {
    bf16 ha = __float2bfloat16(a), hb = __float2bfloat16(b);
    bf16 la = __float2bfloat16(a - __bfloat162float(ha));
    bf16 lb = __float2bfloat16(b - __bfloat162float(hb));
    __nv_bfloat162 hv; hv.x = ha; hv.y = hb;
    __nv_bfloat162 lv; lv.x = la; lv.y = lb;
    *(__nv_bfloat162*)(hi + idx) = hv;
    *(__nv_bfloat162*)(lo + idx) = lv;
}
__device__ __forceinline__ void split_store2_h(__half* hi, __half* lo, size_t idx,
                                               float a, float b) {
    __half ha = __float2half_rn(a), hb = __float2half_rn(b);
    __half la = __float2half_rn(a - __half2float(ha));
    __half lb = __float2half_rn(b - __half2float(hb));
    __half2 hv; hv.x = ha; hv.y = hb;
    __half2 lv; lv.x = la; lv.y = lb;
    *(__half2*)(hi + idx) = hv;
    *(__half2*)(lo + idx) = lv;
}
__device__ __forceinline__ float fexp(float x) {
    float t = x * 1.4426950408889634f;
    t = fmaxf(t, -126.0f);
    float n = rintf(t);
    float f = t - n;
    float p = 1.5403530e-4f;
    p = fmaf(p, f, 1.3333558e-3f);
    p = fmaf(p, f, 9.6181291e-3f);
    p = fmaf(p, f, 5.5504109e-2f);
    p = fmaf(p, f, 2.4022651e-1f);
    p = fmaf(p, f, 6.9314718e-1f);
    p = fmaf(p, f, 1.0f);
    return p * __int_as_float(((int)n + 127) << 23);
}

// ---------------------------------------------------------------------------
// bf16-split MMA GEMM: 128x128 tile, BK=32, 256 thr, double buffer.
// EPI 0: split-store fp16 hi/lo.  EPI 1: fp32 store + bias.
// ---------------------------------------------------------------------------
#define BK 32
#define GP 40
#define GT_ELEMS (128 * GP)
#define GS_ELEMS (4 * GT_ELEMS)
#define SMEM_GEMM (2 * GS_ELEMS * 2)

template <int EPI>
__global__ __launch_bounds__(256, 2) void mma_gemm_kernel(
    const bf16* __restrict__ Ahi, const bf16* __restrict__ Alo,
    const bf16* __restrict__ Bhi, const bf16* __restrict__ Blo,
    float* __restrict__ C, __half* __restrict__ Chi, __half* __restrict__ Clo,
    const float* __restrict__ bias, int M, int N, int K)
{
    extern __shared__ bf16 sm[];
    const uint32_t sbase = smem_u32(sm);
    const int t = threadIdx.x;
    const int warp = t >> 5, lane = t & 31;
    const int bm = blockIdx.y * 128;
    const int bn = blockIdx.x * 128;
    const int wm = (warp >> 1) * 32;
    const int wn = (warp & 1) * 64;

    const bf16* srcs[4] = { Ahi, Alo, Bhi, Blo };

    auto load_stage = [&](int buf, int k0) {
        uint32_t sdst = sbase + (uint32_t)buf * GS_ELEMS * 2;
        #pragma unroll
        for (int m = 0; m < 4; m++) {
            const int rbase = (m < 2) ? bm : bn;
            const bf16* S = srcs[m] + (size_t)rbase * K + k0;
            uint32_t td = sdst + (uint32_t)m * GT_ELEMS * 2;
            #pragma unroll
            for (int i = 0; i < 2; i++) {
                int id = t + i * 256;
                int row = id >> 2, c = id & 3;
                cp_async16(td + (uint32_t)(row * GP + c * 8) * 2,
                           S + (size_t)row * K + c * 8);
            }
        }
        CP_COMMIT();
    };

    float acc[2][8][4];
    #pragma unroll
    for (int mi = 0; mi < 2; mi++)
        #pragma unroll
        for (int nj = 0; nj < 8; nj++)
            #pragma unroll
            for (int e = 0; e < 4; e++) acc[mi][nj][e] = 0.0f;

    const int nch = K >> 5;
    load_stage(0, 0);
    load_stage(1, BK);

    const int a_r = (lane & 7) + ((lane >> 3) & 1) * 8;
    const int a_c = (lane >> 4) * 8;
    const int b_r = (lane & 7) + (lane >> 4) * 8;
    const int b_c = ((lane >> 3) & 1) * 8;

    for (int c = 0; c < nch; c++) {
        if (c < nch - 1) { CP_WAIT(1); } else { CP_WAIT(0); }
        __syncthreads();

        const uint32_t stg = sbase + (uint32_t)(c & 1) * GS_ELEMS * 2;
        const uint32_t tAhi = stg;
        const uint32_t tAlo = stg + GT_ELEMS * 2;
        const uint32_t tBhi = stg + 2 * GT_ELEMS * 2;
        const uint32_t tBlo = stg + 3 * GT_ELEMS * 2;

        #pragma unroll
        for (int ks = 0; ks < BK; ks += 16) {
            uint32_t ah[2][4], al[2][4], bh[16], bl[16];
            #pragma unroll
            for (int mi = 0; mi < 2; mi++) {
                uint32_t off = (uint32_t)((wm + mi * 16 + a_r) * GP + ks + a_c) * 2;
                ldm_x4(tAhi + off, ah[mi]);
                ldm_x4(tAlo + off, al[mi]);
            }
            #pragma unroll
            for (int nj2 = 0; nj2 < 4; nj2++) {
                uint32_t off = (uint32_t)((wn + nj2 * 16 + b_r) * GP + ks + b_c) * 2;
                ldm_x4(tBhi + off, bh + nj2 * 4);
                ldm_x4(tBlo + off, bl + nj2 * 4);
            }
            #pragma unroll
            for (int mi = 0; mi < 2; mi++)
                #pragma unroll
                for (int nj = 0; nj < 8; nj++)
                    mma_bf16(acc[mi][nj], ah[mi], bh + nj * 2);
            #pragma unroll
            for (int mi = 0; mi < 2; mi++)
                #pragma unroll
                for (int nj = 0; nj < 8; nj++)
                    mma_bf16(acc[mi][nj], ah[mi], bl + nj * 2);
            #pragma unroll
            for (int mi = 0; mi < 2; mi++)
                #pragma unroll
                for (int nj = 0; nj < 8; nj++)
                    mma_bf16(acc[mi][nj], al[mi], bh + nj * 2);
        }
        __syncthreads();
        if (c + 2 < nch) load_stage(c & 1, (c + 2) * BK);
    }

    const int group = lane >> 2, tid4 = lane & 3;
    #pragma unroll
    for (int mi = 0; mi < 2; mi++) {
        int r0 = bm + wm + mi * 16 + group;
        #pragma unroll
        for (int nj = 0; nj < 8; nj++) {
            int cc = bn + wn + nj * 8 + tid4 * 2;
            if (EPI == 1) {
                float2 bb = *(const float2*)(bias + cc);
                float2 v0 = make_float2(acc[mi][nj][0] + bb.x, acc[mi][nj][1] + bb.y);
                float2 v1 = make_float2(acc[mi][nj][2] + bb.x, acc[mi][nj][3] + bb.y);
                *(float2*)(C + (size_t)r0 * N + cc) = v0;
                *(float2*)(C + (size_t)(r0 + 8) * N + cc) = v1;
            } else {
                split_store2_h(Chi, Clo, (size_t)r0 * N + cc,
                               acc[mi][nj][0], acc[mi][nj][1]);
                split_store2_h(Chi, Clo, (size_t)(r0 + 8) * N + cc,
                               acc[mi][nj][2], acc[mi][nj][3]);
            }
        }
    }
}

// ---------------------------------------------------------------------------
// Scores via fp16 HMMA 2-term: S = (Qhi+Qlo) . Khi^T; fused mask+scale+exp;
// unnormalized out + psums. SMEM: Qhi,Qlo,Khi [128][72] half.
// ---------------------------------------------------------------------------
#define SP 72
#define ST_ELEMS (128 * SP)
#define SMEM_SCORES (3 * ST_ELEMS * 2)

__global__ __launch_bounds__(256) void scores_mma_kernel(
    const float* __restrict__ mask, float* __restrict__ attn,
    const __half* __restrict__ q16h, const __half* __restrict__ q16l,
    float* __restrict__ psum)
{
    extern __shared__ __half smh[];
    const uint32_t sbase = smem_u32(smh);
    const int t = threadIdx.x;
    const int warp = t >> 5, lane = t & 31;
    const int bh = blockIdx.z;
    const int b = bh / HEADS, h = bh % HEADS;
    const int bm = blockIdx.y * 128;
    const int bn = blockIdx.x * 128;
    const int wm = (warp >> 1) * 32;
    const int wn = (warp & 1) * 64;

    const __half* bases[3] = {
        q16h + ((size_t)(b * SEQ + bm)) * D3 + h * HD,
        q16l + ((size_t)(b * SEQ + bm)) * D3 + h * HD,
        q16h + ((size_t)(b * SEQ + bn)) * D3 + D_MODEL + h * HD };
    #pragma unroll
    for (int m = 0; m < 3; m++) {
        uint32_t td = sbase + (uint32_t)m * ST_ELEMS * 2;
        #pragma unroll
        for (int i = 0; i < 4; i++) {
            int id = t + i * 256;
            int r = id >> 3, c = id & 7;
            cp_async16(td + (uint32_t)(r * SP + c * 8) * 2,
                       bases[m] + (size_t)r * D3 + c * 8);
        }
    }
    CP_COMMIT();

    float acc[2][8][4];
    #pragma unroll
    for (int mi = 0; mi < 2; mi++)
        #pragma unroll
        for (int nj = 0; nj < 8; nj++)
            #pragma unroll
            for (int e = 0; e < 4; e++) acc[mi][nj][e] = 0.0f;

    const int a_r = (lane & 7) + ((lane >> 3) & 1) * 8;
    const int a_c = (lane >> 4) * 8;
    const int b_r = (lane & 7) + (lane >> 4) * 8;
    const int b_c = ((lane >> 3) & 1) * 8;

    const uint32_t tQhi = sbase;
    const uint32_t tQlo = sbase + ST_ELEMS * 2;
    const uint32_t tKhi = sbase + 2 * ST_ELEMS * 2;

    CP_WAIT(0);
    __syncthreads();

    #pragma unroll
    for (int ks = 0; ks < 4; ks++) {
        uint32_t ah[2][4], al[2][4], bhf[16];
        #pragma unroll
        for (int mi = 0; mi < 2; mi++) {
            uint32_t off = (uint32_t)((wm + mi * 16 + a_r) * SP + ks * 16 + a_c) * 2;
            ldm_x4(tQhi + off, ah[mi]);
            ldm_x4(tQlo + off, al[mi]);
        }
        #pragma unroll
        for (int nj2 = 0; nj2 < 4; nj2++) {
            uint32_t off = (uint32_t)((wn + nj2 * 16 + b_r) * SP + ks * 16 + b_c) * 2;
            ldm_x4(tKhi + off, bhf + nj2 * 4);
        }
        #pragma unroll
        for (int mi = 0; mi < 2; mi++)
            #pragma unroll
            for (int nj = 0; nj < 8; nj++) {
                mma_f16(acc[mi][nj], ah[mi], bhf + nj * 2);
                mma_f16(acc[mi][nj], al[mi], bhf + nj * 2);
            }
    }

    const int group = lane >> 2, tid4 = lane & 3;
    float mq[4];
    #pragma unroll
    for (int mi = 0; mi < 2; mi++) {
        mq[mi * 2 + 0] = mask[b * SEQ + bm + wm + mi * 16 + group];
        mq[mi * 2 + 1] = mask[b * SEQ + bm + wm + mi * 16 + group + 8];
    }
    float* out = attn + (size_t)bh * SEQ * SEQ;
    float srow[2][2];
    srow[0][0] = srow[0][1] = srow[1][0] = srow[1][1] = 0.0f;
    #pragma unroll
    for (int nj = 0; nj < 8; nj++) {
        int cc = bn + wn + nj * 8 + tid4 * 2;
        float2 mk = *(const float2*)(mask + b * SEQ + cc);
        #pragma unroll
        for (int mi = 0; mi < 2; mi++) {
            int r0 = bm + wm + mi * 16 + group;
            float v0 = acc[mi][nj][0], v1 = acc[mi][nj][1];
            float v2 = acc[mi][nj][2], v3 = acc[mi][nj][3];
            if (mq[mi * 2 + 0] * mk.x == 0.0f) v0 = -100000.0f;
            if (mq[mi * 2 + 0] * mk.y == 0.0f) v1 = -100000.0f;
            if (mq[mi * 2 + 1] * mk.x == 0.0f) v2 = -100000.0f;
            if (mq[mi * 2 + 1] * mk.y == 0.0f) v3 = -100000.0f;
            float e0 = fexp(v0 * 0.03125f), e1 = fexp(v1 * 0.03125f);
            float e2 = fexp(v2 * 0.03125f), e3 = fexp(v3 * 0.03125f);
            *(float2*)(out + (size_t)r0 * SEQ + cc) = make_float2(e0, e1);
            *(float2*)(out + (size_t)(r0 + 8) * SEQ + cc) = make_float2(e2, e3);
            srow[mi][0] += e0 + e1;
            srow[mi][1] += e2 + e3;
        }
    }
    #pragma unroll
    for (int mi = 0; mi < 2; mi++) {
        #pragma unroll
        for (int s = 0; s < 2; s++) {
            srow[mi][s] += __shfl_xor_sync(0xffffffffu, srow[mi][s], 1);
            srow[mi][s] += __shfl_xor_sync(0xffffffffu, srow[mi][s], 2);
        }
    }
    __syncthreads();
    float* rs = (float*)smh;
    if (tid4 == 0) {
        #pragma unroll
        for (int mi = 0; mi < 2; mi++) {
            rs[(wm + mi * 16 + group) * 2 + (warp & 1)] = srow[mi][0];
            rs[(wm + mi * 16 + group + 8) * 2 + (warp & 1)] = srow[mi][1];
        }
    }
    __syncthreads();
    if (t < 128)
        psum[((size_t)bh * SEQ + bm + t) * 16 + blockIdx.x] = rs[t * 2] + rs[t * 2 + 1];
}

// ---------------------------------------------------------------------------
__global__ __launch_bounds__(256) void rowinv_kernel(
    const float* __restrict__ psum, float* __restrict__ inv)
{
    int r = blockIdx.x * 256 + threadIdx.x;
    if (r >= NROWS) return;
    float4 a = *(const float4*)(psum + (size_t)r * 16);
    float4 b2 = *(const float4*)(psum + (size_t)r * 16 + 4);
    float4 c = *(const float4*)(psum + (size_t)r * 16 + 8);
    float4 d = *(const float4*)(psum + (size_t)r * 16 + 12);
    float s = a.x + a.y + a.z + a.w + b2.x + b2.y + b2.z + b2.w
            + c.x + c.y + c.z + c.w + d.x + d.y + d.z + d.w;
    inv[r] = 1.0f / s;
}

// ---------------------------------------------------------------------------
// attn @ V via fp16 HMMA 2-term: ao = (Ahi+Alo) . Vhi.
// Normalizes attn in place; split-stores ao bf16 hi/lo.
// ---------------------------------------------------------------------------
#define AVP 72
#define AV_STAGEF 0                              /* 34816 B */
#define AV_AHI    34816                          /* 18432 B */
#define AV_ALO    (34816 + 18432)                /* 18432 B */
#define AV_VHI(i) (71680 + (i) * 9216)           /* 2x 9216 */
#define AV_INV    90112
#define SMEM_AV   (90112 + 512)

__global__ __launch_bounds__(256) void av_mma_kernel(
    float* __restrict__ attn,
    const __half* __restrict__ q16h,
    bf16* __restrict__ aohi, bf16* __restrict__ aolo,
    const float* __restrict__ inv)
{
    extern __shared__ char smc[];
    const uint32_t sbase = smem_u32(smc);
    const int t = threadIdx.x;
    const int warp = t >> 5, lane = t & 31;
    const int bh = blockIdx.y;
    const int b = bh / HEADS, h = bh % HEADS;
    const int bm = blockIdx.x * 128;
    const int wm = warp * 16;

    float* Abase = attn + (size_t)bh * SEQ * SEQ + (size_t)bm * SEQ;
    const __half* Vhi = q16h + (size_t)b * SEQ * D3 + 2 * D_MODEL + h * HD;

    float* inv_s = (float*)(smc + AV_INV);
    if (t < 128) inv_s[t] = inv[(size_t)bh * SEQ + bm + t];

    auto load_chunk = [&](int c) {
        const int k0 = c * 64;
        #pragma unroll
        for (int i = 0; i < 8; i++) {
            int id = t + i * 256;
            int r = id >> 4, c4 = id & 15;
            cp_async16(sbase + AV_STAGEF + (uint32_t)(r * 68 + c4 * 4) * 4,
                       Abase + (size_t)r * SEQ + k0 + c4 * 4);
        }
        const uint32_t vb = c & 1;
        #pragma unroll
        for (int i = 0; i < 2; i++) {           // 512 segs: 2 per thread
            int id = t + i * 256;
            int r = id >> 3, cs = id & 7;
            cp_async16(sbase + AV_VHI(vb) + (uint32_t)(r * AVP + cs * 8) * 2,
                       Vhi + (size_t)(k0 + r) * D3 + cs * 8);
        }
        CP_COMMIT();
    };

    float acc[8][4];
    #pragma unroll
    for (int nj = 0; nj < 8; nj++)
        #pragma unroll
        for (int e = 0; e < 4; e++) acc[nj][e] = 0.0f;

    load_chunk(0);

    const int a_r = (lane & 7) + ((lane >> 3) & 1) * 8;
    const int a_c = (lane >> 4) * 8;
    const int tb_r = lane & 15;
    const int tb_c = (lane >> 4) * 8;

    const float* stageF = (const float*)(smc + AV_STAGEF);
    __half* Ahi_s = (__half*)(smc + AV_AHI);
    __half* Alo_s = (__half*)(smc + AV_ALO);

    for (int c = 0; c < SEQ / 64; c++) {
        CP_WAIT(0);
        __syncthreads();
        const int k0 = c * 64;
        #pragma unroll
        for (int i = 0; i < 8; i++) {
            int id = t + i * 256;
            int r = id >> 4, c4 = id & 15;
            float4 v = *(const float4*)(stageF + r * 68 + c4 * 4);
            float s = inv_s[r];
            v.x *= s; v.y *= s; v.z *= s; v.w *= s;
            *(float4*)(Abase + (size_t)r * SEQ + k0 + c4 * 4) = v;
            __half h4[4], l4[4];
            float vv[4] = { v.x, v.y, v.z, v.w };
            #pragma unroll
            for (int j = 0; j < 4; j++) {
                h4[j] = __float2half_rn(vv[j]);
                l4[j] = __float2half_rn(vv[j] - __half2float(h4[j]));
            }
            *(uint2*)(Ahi_s + r * AVP + c4 * 4) = *(uint2*)h4;
            *(uint2*)(Alo_s + r * AVP + c4 * 4) = *(uint2*)l4;
        }
        __syncthreads();
        if (c + 1 < SEQ / 64) load_chunk(c + 1);

        const uint32_t tAhi = sbase + AV_AHI;
        const uint32_t tAlo = sbase + AV_ALO;
        const uint32_t tVhi = sbase + AV_VHI(c & 1);

        #pragma unroll
        for (int ks = 0; ks < 4; ks++) {
            uint32_t ah[4], al[4], bhf[16];
            uint32_t aoff = (uint32_t)((wm + a_r) * AVP + ks * 16 + a_c) * 2;
            ldm_x4(tAhi + aoff, ah);
            ldm_x4(tAlo + aoff, al);
            #pragma unroll
            for (int nj2 = 0; nj2 < 4; nj2++) {
                uint32_t boff =
                    (uint32_t)((ks * 16 + tb_r) * AVP + nj2 * 16 + tb_c) * 2;
                ldm_x4_trans(tVhi + boff, bhf + nj2 * 4);
            }
            #pragma unroll
            for (int nj = 0; nj < 8; nj++) {
                mma_f16(acc[nj], ah, bhf + nj * 2);
                mma_f16(acc[nj], al, bhf + nj * 2);
            }
        }
    }

    const int group = lane >> 2, tid4 = lane & 3;
    #pragma unroll
    for (int nj = 0; nj < 8; nj++) {
        int cc = h * HD + nj * 8 + tid4 * 2;
        size_t r0 = (size_t)(b * SEQ + bm + wm + group) * D_MODEL + cc;
        size_t r1 = r0 + (size_t)8 * D_MODEL;
        split_store2_bf(aohi, aolo, r0, acc[nj][0], acc[nj][1]);
        split_store2_bf(aohi, aolo, r1, acc[nj][2], acc[nj][3]);
    }
}

// ---------------------------------------------------------------------------
// Out-proj GEMM with bf16 inputs (3-term, fp32 + bias epilogue).
// ---------------------------------------------------------------------------
__global__ __launch_bounds__(256, 2) void mma_gemm_bias_kernel(
    const bf16* __restrict__ Ahi, const bf16* __restrict__ Alo,
    const bf16* __restrict__ Bhi, const bf16* __restrict__ Blo,
    float* __restrict__ C, const float* __restrict__ bias,
    int M, int N, int K)
{
    extern __shared__ bf16 sm[];
    const uint32_t sbase = smem_u32(sm);
    const int t = threadIdx.x;
    const int warp = t >> 5, lane = t & 31;
    const int bm = blockIdx.y * 128;
    const int bn = blockIdx.x * 128;
    const int wm = (warp >> 1) * 32;
    const int wn = (warp & 1) * 64;

    const bf16* srcs[4] = { Ahi, Alo, Bhi, Blo };

    auto load_stage = [&](int buf, int k0) {
        uint32_t sdst = sbase + (uint32_t)buf * GS_ELEMS * 2;
        #pragma unroll
        for (int m = 0; m < 4; m++) {
            const int rbase = (m < 2) ? bm : bn;
            const bf16* S = srcs[m] + (size_t)rbase * K + k0;
            uint32_t td = sdst + (uint32_t)m * GT_ELEMS * 2;
            #pragma unroll
            for (int i = 0; i < 2; i++) {
                int id = t + i * 256;
                int row = id >> 2, c = id & 3;
                cp_async16(td + (uint32_t)(row * GP + c * 8) * 2,
                           S + (size_t)row * K + c * 8);
            }
        }
        CP_COMMIT();
    };

    float acc[2][8][4];
    #pragma unroll
    for (int mi = 0; mi < 2; mi++)
        #pragma unroll
        for (int nj = 0; nj < 8; nj++)
            #pragma unroll
            for (int e = 0; e < 4; e++) acc[mi][nj][e] = 0.0f;

    const int nch = K >> 5;
    load_stage(0, 0);
    load_stage(1, BK);

    const int a_r = (lane & 7) + ((lane >> 3) & 1) * 8;
    const int a_c = (lane >> 4) * 8;
    const int b_r = (lane & 7) + (lane >> 4) * 8;
    const int b_c = ((lane >> 3) & 1) * 8;

    for (int c = 0; c < nch; c++) {
        if (c < nch - 1) { CP_WAIT(1); } else { CP_WAIT(0); }
        __syncthreads();

        const uint32_t stg = sbase + (uint32_t)(c & 1) * GS_ELEMS * 2;
        const uint32_t tAhi = stg;
        const uint32_t tAlo = stg + GT_ELEMS * 2;
        const uint32_t tBhi = stg + 2 * GT_ELEMS * 2;
        const uint32_t tBlo = stg + 3 * GT_ELEMS * 2;

        #pragma unroll
        for (int ks = 0; ks < BK; ks += 16) {
            uint32_t ah[2][4], al[2][4], bh[16], bl[16];
            #pragma unroll
            for (int mi = 0; mi < 2; mi++) {
                uint32_t off = (uint32_t)((wm + mi * 16 + a_r) * GP + ks + a_c) * 2;
                ldm_x4(tAhi + off, ah[mi]);
                ldm_x4(tAlo + off, al[mi]);
            }
            #pragma unroll
            for (int nj2 = 0; nj2 < 4; nj2++) {
                uint32_t off = (uint32_t)((wn + nj2 * 16 + b_r) * GP + ks + b_c) * 2;
                ldm_x4(tBhi + off, bh + nj2 * 4);
                ldm_x4(tBlo + off, bl + nj2 * 4);
            }
            #pragma unroll
            for (int mi = 0; mi < 2; mi++)
                #pragma unroll
                for (int nj = 0; nj < 8; nj++)
                    mma_bf16(acc[mi][nj], ah[mi], bh + nj * 2);
            #pragma unroll
            for (int mi = 0; mi < 2; mi++)
                #pragma unroll
                for (int nj = 0; nj < 8; nj++)
                    mma_bf16(acc[mi][nj], ah[mi], bl + nj * 2);
            #pragma unroll
            for (int mi = 0; mi < 2; mi++)
                #pragma unroll
                for (int nj = 0; nj < 8; nj++)
                    mma_bf16(acc[mi][nj], al[mi], bh + nj * 2);
        }
        __syncthreads();
        if (c + 2 < nch) load_stage(c & 1, (c + 2) * BK);
    }

    const int group = lane >> 2, tid4 = lane & 3;
    #pragma unroll
    for (int mi = 0; mi < 2; mi++) {
        int r0 = bm + wm + mi * 16 + group;
        #pragma unroll
        for (int nj = 0; nj < 8; nj++) {
            int cc = bn + wn + nj * 8 + tid4 * 2;
            float2 bb = *(const float2*)(bias + cc);
            *(float2*)(C + (size_t)r0 * N + cc) =
                make_float2(acc[mi][nj][0] + bb.x, acc[mi][nj][1] + bb.y);
            *(float2*)(C + (size_t)(r0 + 8) * N + cc) =
                make_float2(acc[mi][nj][2] + bb.x, acc[mi][nj][3] + bb.y);
        }
    }
}

// ---------------------------------------------------------------------------
// fp32 -> bf16 hi/lo split (x input)
// ---------------------------------------------------------------------------
__global__ __launch_bounds__(256) void split_kernel(
    const float* __restrict__ in, bf16* __restrict__ hi,
    bf16* __restrict__ lo, int n4)
{
    int i = blockIdx.x * 256 + threadIdx.x;
    if (i >= n4) return;
    float4 v = ((const float4*)in)[i];
    bf16 h[4], l[4];
    float vv[4] = { v.x, v.y, v.z, v.w };
    #pragma unroll
    for (int j = 0; j < 4; j++) {
        h[j] = __float2bfloat16(vv[j]);
        l[j] = __float2bfloat16(vv[j] - __bfloat162float(h[j]));
    }
    ((uint2*)hi)[i] = *(uint2*)h;
    ((uint2*)lo)[i] = *(uint2*)l;
}

// ---------------------------------------------------------------------------
// W[K,N] fp32 -> Wt[N,K] bf16 hi/lo (transpose + split)
// ---------------------------------------------------------------------------
__global__ __launch_bounds__(256) void transpose_split_kernel(
    const float* __restrict__ W, bf16* __restrict__ hi,
    bf16* __restrict__ lo, int K, int N)
{
    __shared__ float tile[32][33];
    const int nx = blockIdx.x * 32;
    const int ky = blockIdx.y * 32;
    const int tx = threadIdx.x & 31;
    const int ty = threadIdx.x >> 5;
    #pragma unroll
    for (int i = 0; i < 4; i++)
        tile[ty + 8 * i][tx] = W[(size_t)(ky + ty + 8 * i) * N + nx + tx];
    __syncthreads();
    #pragma unroll
    for (int i = 0; i < 4; i++) {
        float v = tile[tx][ty + 8 * i];
        bf16 h = __float2bfloat16(v);
        bf16 l = __float2bfloat16(v - __bfloat162float(h));
        size_t o = (size_t)(nx + ty + 8 * i) * K + ky + tx;
        hi[o] = h;
        lo[o] = l;
    }
}

// ---------------------------------------------------------------------------
extern "C" void kernel_launch(void* const* d_in, const int* in_sizes, int n_in,
                              void* d_out, int out_size)
{
    const float* x     = (const float*)d_in[0];
    const float* mask  = (const float*)d_in[1];
    const float* W_qkv = (const float*)d_in[2];
    const float* W_h   = (const float*)d_in[3];
    const float* b_h   = (const float*)d_in[4];

    float* out  = (float*)d_out;
    float* attn = out + (size_t)BL * D_MODEL;

    bf16 *xhi, *xlo, *wqhi, *wqlo, *whhi, *whlo, *aohi, *aolo;
    __half *q16h, *q16l;
    float *psum, *inv;
    cudaGetSymbolAddress((void**)&xhi, g_x_hi);
    cudaGetSymbolAddress((void**)&xlo, g_x_lo);
    cudaGetSymbolAddress((void**)&wqhi, g_wqkvT_hi);
    cudaGetSymbolAddress((void**)&wqlo, g_wqkvT_lo);
    cudaGetSymbolAddress((void**)&whhi, g_whT_hi);
    cudaGetSymbolAddress((void**)&whlo, g_whT_lo);
    cudaGetSymbolAddress((void**)&q16h, g_q16h);
    cudaGetSymbolAddress((void**)&q16l, g_q16l);
    cudaGetSymbolAddress((void**)&aohi, g_ao_hi);
    cudaGetSymbolAddress((void**)&aolo, g_ao_lo);
    cudaGetSymbolAddress((void**)&psum, g_psum);
    cudaGetSymbolAddress((void**)&inv, g_inv);

    cudaFuncSetAttribute(mma_gemm_kernel<0>, cudaFuncAttributeMaxDynamicSharedMemorySize, SMEM_GEMM);
    cudaFuncSetAttribute(mma_gemm_bias_kernel, cudaFuncAttributeMaxDynamicSharedMemorySize, SMEM_GEMM);
    cudaFuncSetAttribute(scores_mma_kernel, cudaFuncAttributeMaxDynamicSharedMemorySize, SMEM_SCORES);
    cudaFuncSetAttribute(av_mma_kernel, cudaFuncAttributeMaxDynamicSharedMemorySize, SMEM_AV);

    // 0) input conversions
    split_kernel<<<(BL * D_MODEL / 4 + 255) / 256, 256>>>(x, xhi, xlo, BL * D_MODEL / 4);
    transpose_split_kernel<<<dim3(D3 / 32, D_MODEL / 32), 256>>>(W_qkv, wqhi, wqlo, D_MODEL, D3);
    transpose_split_kernel<<<dim3(D_MODEL / 32, D_MODEL / 32), 256>>>(W_h, whhi, whlo, D_MODEL, D_MODEL);

    // 1) QKV = x @ W_qkv (bf16 3-term) -> fp16 hi/lo
    mma_gemm_kernel<0><<<dim3(D3 / 128, BL / 128), 256, SMEM_GEMM>>>(
        xhi, xlo, wqhi, wqlo, nullptr, q16h, q16l, nullptr, BL, D3, D_MODEL);

    // 2) scores (fp16 2-term) + fused exp -> unnormalized attn + psums
    scores_mma_kernel<<<dim3(SEQ / 128, SEQ / 128, BATCH * HEADS), 256, SMEM_SCORES>>>(
        mask, attn, q16h, q16l, psum);

    // 3) row-sum inverse
    rowinv_kernel<<<NROWS / 256, 256>>>(psum, inv);

    // 4) attn @ V (fp16 2-term, normalizes attn in place) -> ao bf16 hi/lo
    av_mma_kernel<<<dim3(SEQ / 128, BATCH * HEADS), 256, SMEM_AV>>>(
        attn, q16h, aohi, aolo, inv);

    // 5) output = ao @ W_h + b_h (bf16 3-term)
    mma_gemm_bias_kernel<<<dim3(D_MODEL / 128, BL / 128), 256, SMEM_GEMM>>>(
        aohi, aolo, whhi, whlo, out, b_h, BL, D_MODEL, D_MODEL);
}

// round 9
// speedup vs baseline: 1.9625x; 1.1006x over previous
#include <cuda_runtime.h>
#include <cuda_bf16.h>
#include <cuda_fp16.h>
#include <math.h>
#include <stdint.h>

#define D_MODEL 1024
#define HEADS 16
#define HD 64
#define BATCH 2
#define SEQ 2048
#define BL (BATCH * SEQ)      /* 4096 */
#define D3 (3 * D_MODEL)      /* 3072 */
#define NROWS (BATCH * HEADS * SEQ)

typedef __nv_bfloat16 bf16;

// ---------------------------------------------------------------------------
// Scratch (allocation-free: __device__ globals)
// ---------------------------------------------------------------------------
__device__ __half g_x16h[(size_t)BL * D_MODEL];
__device__ __half g_x16l[(size_t)BL * D_MODEL];
__device__ __half g_wq16[(size_t)D3 * D_MODEL];      // W_qkvT fp16 single
__device__ bf16  g_whT_hi[(size_t)D_MODEL * D_MODEL];
__device__ bf16  g_whT_lo[(size_t)D_MODEL * D_MODEL];
__device__ __half g_q16h[(size_t)BL * D3];           // QKV fp16 hi
__device__ __half g_q16l[(size_t)BL * D3];           // QKV fp16 lo
__device__ bf16  g_ao_hi[(size_t)BL * D_MODEL];
__device__ bf16  g_ao_lo[(size_t)BL * D_MODEL];
__device__ float g_psum[(size_t)NROWS * 16];
__device__ float g_inv[(size_t)NROWS];

// ---------------------------------------------------------------------------
// Portable PTX helpers
// ---------------------------------------------------------------------------
__device__ __forceinline__ uint32_t smem_u32(const void* p) {
    uint32_t a;
    asm("{ .reg .u64 t; cvta.to.shared.u64 t, %1; cvt.u32.u64 %0, t; }"
        : "=r"(a) : "l"(p));
    return a;
}
__device__ __forceinline__ void cp_async16(uint32_t s, const void* g) {
    asm volatile("cp.async.cg.shared.global [%0], [%1], 16;" :: "r"(s), "l"(g));
}
#define CP_COMMIT() asm volatile("cp.async.commit_group;" ::: "memory")
#define CP_WAIT(n)  asm volatile("cp.async.wait_group %0;" :: "n"(n) : "memory")

__device__ __forceinline__ void ldm_x4(uint32_t addr, uint32_t* r) {
    asm volatile("ldmatrix.sync.aligned.m8n8.x4.shared.b16 {%0,%1,%2,%3}, [%4];"
        : "=r"(r[0]), "=r"(r[1]), "=r"(r[2]), "=r"(r[3]) : "r"(addr));
}
__device__ __forceinline__ void ldm_x4_trans(uint32_t addr, uint32_t* r) {
    asm volatile("ldmatrix.sync.aligned.m8n8.x4.trans.shared.b16 {%0,%1,%2,%3}, [%4];"
        : "=r"(r[0]), "=r"(r[1]), "=r"(r[2]), "=r"(r[3]) : "r"(addr));
}
__device__ __forceinline__ void mma_bf16(float* c, const uint32_t* a, const uint32_t* b) {
    asm volatile(
        "mma.sync.aligned.m16n8k16.row.col.f32.bf16.bf16.f32 "
        "{%0,%1,%2,%3}, {%4,%5,%6,%7}, {%8,%9}, {%0,%1,%2,%3};"
        : "+f"(c[0]), "+f"(c[1]), "+f"(c[2]), "+f"(c[3])
        : "r"(a[0]), "r"(a[1]), "r"(a[2]), "r"(a[3]), "r"(b[0]), "r"(b[1]));
}
__device__ __forceinline__ void mma_f16(float* c, const uint32_t* a, const uint32_t* b) {
    asm volatile(
        "mma.sync.aligned.m16n8k16.row.col.f32.f16.f16.f32 "
        "{%0,%1,%2,%3}, {%4,%5,%6,%7}, {%8,%9}, {%0,%1,%2,%3};"
        : "+f"(c[0]), "+f"(c[1]), "+f"(c[2]), "+f"(c[3])
        : "r"(a[0]), "r"(a[1]), "r"(a[2]), "r"(a[3]), "r"(b[0]), "r"(b[1]));
}
__device__ __forceinline__ void split_store2_bf(bf16* hi, bf16* lo, size_t idx,
                                                float a, float b) {
    bf16 ha = __float2bfloat16(a), hb = __float2bfloat16(b);
    bf16 la = __float2bfloat16(a - __bfloat162float(ha));
    bf16 lb = __float2bfloat16(b - __bfloat162float(hb));
    __nv_bfloat162 hv; hv.x = ha; hv.y = hb;
    __nv_bfloat162 lv; lv.x = la; lv.y = lb;
    *(__nv_bfloat162*)(hi + idx) = hv;
    *(__nv_bfloat162*)(lo + idx) = lv;
}
__device__ __forceinline__ void split_store2_h(__half* hi, __half* lo, size_t idx,
                                               float a, float b) {
    __half ha = __float2half_rn(a), hb = __float2half_rn(b);
    __half la = __float2half_rn(a - __half2float(ha));
    __half lb = __float2half_rn(b - __half2float(hb));
    __half2 hv; hv.x = ha; hv.y = hb;
    __half2 lv; lv.x = la; lv.y = lb;
    *(__half2*)(hi + idx) = hv;
    *(__half2*)(lo + idx) = lv;
}
__device__ __forceinline__ float fexp(float x) {
    float t = x * 1.4426950408889634f;
    t = fmaxf(t, -126.0f);
    float n = rintf(t);
    float f = t - n;
    float p = 1.5403530e-4f;
    p = fmaf(p, f, 1.3333558e-3f);
    p = fmaf(p, f, 9.6181291e-3f);
    p = fmaf(p, f, 5.5504109e-2f);
    p = fmaf(p, f, 2.4022651e-1f);
    p = fmaf(p, f, 6.9314718e-1f);
    p = fmaf(p, f, 1.0f);
    return p * __int_as_float(((int)n + 127) << 23);
}

// ---------------------------------------------------------------------------
// fp16 2-term QKV GEMM: C = (Ahi+Alo) @ Bhi^T. 128x128 tile, BK=32,
// 256 thr, double buffer, 3 smem tiles/stage. Epilogue: split fp16 hi/lo.
// ---------------------------------------------------------------------------
#define BK 32
#define GP 40
#define GT_ELEMS (128 * GP)
#define QS_ELEMS (3 * GT_ELEMS)
#define SMEM_QKV (2 * QS_ELEMS * 2)      /* 61440 B */

__global__ __launch_bounds__(256, 2) void qkv_gemm_f16_kernel(
    const __half* __restrict__ Ahi, const __half* __restrict__ Alo,
    const __half* __restrict__ Bhi,
    __half* __restrict__ Chi, __half* __restrict__ Clo,
    int M, int N, int K)
{
    extern __shared__ __half smq[];
    const uint32_t sbase = smem_u32(smq);
    const int t = threadIdx.x;
    const int warp = t >> 5, lane = t & 31;
    const int bm = blockIdx.y * 128;
    const int bn = blockIdx.x * 128;
    const int wm = (warp >> 1) * 32;
    const int wn = (warp & 1) * 64;

    const __half* srcs[3] = { Ahi, Alo, Bhi };

    auto load_stage = [&](int buf, int k0) {
        uint32_t sdst = sbase + (uint32_t)buf * QS_ELEMS * 2;
        #pragma unroll
        for (int m = 0; m < 3; m++) {
            const int rbase = (m < 2) ? bm : bn;
            const __half* S = srcs[m] + (size_t)rbase * K + k0;
            uint32_t td = sdst + (uint32_t)m * GT_ELEMS * 2;
            #pragma unroll
            for (int i = 0; i < 2; i++) {
                int id = t + i * 256;
                int row = id >> 2, c = id & 3;
                cp_async16(td + (uint32_t)(row * GP + c * 8) * 2,
                           S + (size_t)row * K + c * 8);
            }
        }
        CP_COMMIT();
    };

    float acc[2][8][4];
    #pragma unroll
    for (int mi = 0; mi < 2; mi++)
        #pragma unroll
        for (int nj = 0; nj < 8; nj++)
            #pragma unroll
            for (int e = 0; e < 4; e++) acc[mi][nj][e] = 0.0f;

    const int nch = K >> 5;
    load_stage(0, 0);
    load_stage(1, BK);

    const int a_r = (lane & 7) + ((lane >> 3) & 1) * 8;
    const int a_c = (lane >> 4) * 8;
    const int b_r = (lane & 7) + (lane >> 4) * 8;
    const int b_c = ((lane >> 3) & 1) * 8;

    for (int c = 0; c < nch; c++) {
        if (c < nch - 1) { CP_WAIT(1); } else { CP_WAIT(0); }
        __syncthreads();

        const uint32_t stg = sbase + (uint32_t)(c & 1) * QS_ELEMS * 2;
        const uint32_t tAhi = stg;
        const uint32_t tAlo = stg + GT_ELEMS * 2;
        const uint32_t tBhi = stg + 2 * GT_ELEMS * 2;

        #pragma unroll
        for (int ks = 0; ks < BK; ks += 16) {
            uint32_t ah[2][4], al[2][4], bh[16];
            #pragma unroll
            for (int mi = 0; mi < 2; mi++) {
                uint32_t off = (uint32_t)((wm + mi * 16 + a_r) * GP + ks + a_c) * 2;
                ldm_x4(tAhi + off, ah[mi]);
                ldm_x4(tAlo + off, al[mi]);
            }
            #pragma unroll
            for (int nj2 = 0; nj2 < 4; nj2++) {
                uint32_t off = (uint32_t)((wn + nj2 * 16 + b_r) * GP + ks + b_c) * 2;
                ldm_x4(tBhi + off, bh + nj2 * 4);
            }
            #pragma unroll
            for (int mi = 0; mi < 2; mi++)
                #pragma unroll
                for (int nj = 0; nj < 8; nj++) {
                    mma_f16(acc[mi][nj], ah[mi], bh + nj * 2);
                    mma_f16(acc[mi][nj], al[mi], bh + nj * 2);
                }
        }
        __syncthreads();
        if (c + 2 < nch) load_stage(c & 1, (c + 2) * BK);
    }

    const int group = lane >> 2, tid4 = lane & 3;
    #pragma unroll
    for (int mi = 0; mi < 2; mi++) {
        int r0 = bm + wm + mi * 16 + group;
        #pragma unroll
        for (int nj = 0; nj < 8; nj++) {
            int cc = bn + wn + nj * 8 + tid4 * 2;
            split_store2_h(Chi, Clo, (size_t)r0 * N + cc,
                           acc[mi][nj][0], acc[mi][nj][1]);
            split_store2_h(Chi, Clo, (size_t)(r0 + 8) * N + cc,
                           acc[mi][nj][2], acc[mi][nj][3]);
        }
    }
}

// ---------------------------------------------------------------------------
// Scores via fp16 HMMA 2-term (R8-proven).
// ---------------------------------------------------------------------------
#define SP 72
#define ST_ELEMS (128 * SP)
#define SMEM_SCORES (3 * ST_ELEMS * 2)

__global__ __launch_bounds__(256) void scores_mma_kernel(
    const float* __restrict__ mask, float* __restrict__ attn,
    const __half* __restrict__ q16h, const __half* __restrict__ q16l,
    float* __restrict__ psum)
{
    extern __shared__ __half smh[];
    const uint32_t sbase = smem_u32(smh);
    const int t = threadIdx.x;
    const int warp = t >> 5, lane = t & 31;
    const int bh = blockIdx.z;
    const int b = bh / HEADS, h = bh % HEADS;
    const int bm = blockIdx.y * 128;
    const int bn = blockIdx.x * 128;
    const int wm = (warp >> 1) * 32;
    const int wn = (warp & 1) * 64;

    const __half* bases[3] = {
        q16h + ((size_t)(b * SEQ + bm)) * D3 + h * HD,
        q16l + ((size_t)(b * SEQ + bm)) * D3 + h * HD,
        q16h + ((size_t)(b * SEQ + bn)) * D3 + D_MODEL + h * HD };
    #pragma unroll
    for (int m = 0; m < 3; m++) {
        uint32_t td = sbase + (uint32_t)m * ST_ELEMS * 2;
        #pragma unroll
        for (int i = 0; i < 4; i++) {
            int id = t + i * 256;
            int r = id >> 3, c = id & 7;
            cp_async16(td + (uint32_t)(r * SP + c * 8) * 2,
                       bases[m] + (size_t)r * D3 + c * 8);
        }
    }
    CP_COMMIT();

    float acc[2][8][4];
    #pragma unroll
    for (int mi = 0; mi < 2; mi++)
        #pragma unroll
        for (int nj = 0; nj < 8; nj++)
            #pragma unroll
            for (int e = 0; e < 4; e++) acc[mi][nj][e] = 0.0f;

    const int a_r = (lane & 7) + ((lane >> 3) & 1) * 8;
    const int a_c = (lane >> 4) * 8;
    const int b_r = (lane & 7) + (lane >> 4) * 8;
    const int b_c = ((lane >> 3) & 1) * 8;

    const uint32_t tQhi = sbase;
    const uint32_t tQlo = sbase + ST_ELEMS * 2;
    const uint32_t tKhi = sbase + 2 * ST_ELEMS * 2;

    CP_WAIT(0);
    __syncthreads();

    #pragma unroll
    for (int ks = 0; ks < 4; ks++) {
        uint32_t ah[2][4], al[2][4], bhf[16];
        #pragma unroll
        for (int mi = 0; mi < 2; mi++) {
            uint32_t off = (uint32_t)((wm + mi * 16 + a_r) * SP + ks * 16 + a_c) * 2;
            ldm_x4(tQhi + off, ah[mi]);
            ldm_x4(tQlo + off, al[mi]);
        }
        #pragma unroll
        for (int nj2 = 0; nj2 < 4; nj2++) {
            uint32_t off = (uint32_t)((wn + nj2 * 16 + b_r) * SP + ks * 16 + b_c) * 2;
            ldm_x4(tKhi + off, bhf + nj2 * 4);
        }
        #pragma unroll
        for (int mi = 0; mi < 2; mi++)
            #pragma unroll
            for (int nj = 0; nj < 8; nj++) {
                mma_f16(acc[mi][nj], ah[mi], bhf + nj * 2);
                mma_f16(acc[mi][nj], al[mi], bhf + nj * 2);
            }
    }

    const int group = lane >> 2, tid4 = lane & 3;
    float mq[4];
    #pragma unroll
    for (int mi = 0; mi < 2; mi++) {
        mq[mi * 2 + 0] = mask[b * SEQ + bm + wm + mi * 16 + group];
        mq[mi * 2 + 1] = mask[b * SEQ + bm + wm + mi * 16 + group + 8];
    }
    float* out = attn + (size_t)bh * SEQ * SEQ;
    float srow[2][2];
    srow[0][0] = srow[0][1] = srow[1][0] = srow[1][1] = 0.0f;
    #pragma unroll
    for (int nj = 0; nj < 8; nj++) {
        int cc = bn + wn + nj * 8 + tid4 * 2;
        float2 mk = *(const float2*)(mask + b * SEQ + cc);
        #pragma unroll
        for (int mi = 0; mi < 2; mi++) {
            int r0 = bm + wm + mi * 16 + group;
            float v0 = acc[mi][nj][0], v1 = acc[mi][nj][1];
            float v2 = acc[mi][nj][2], v3 = acc[mi][nj][3];
            if (mq[mi * 2 + 0] * mk.x == 0.0f) v0 = -100000.0f;
            if (mq[mi * 2 + 0] * mk.y == 0.0f) v1 = -100000.0f;
            if (mq[mi * 2 + 1] * mk.x == 0.0f) v2 = -100000.0f;
            if (mq[mi * 2 + 1] * mk.y == 0.0f) v3 = -100000.0f;
            float e0 = fexp(v0 * 0.03125f), e1 = fexp(v1 * 0.03125f);
            float e2 = fexp(v2 * 0.03125f), e3 = fexp(v3 * 0.03125f);
            *(float2*)(out + (size_t)r0 * SEQ + cc) = make_float2(e0, e1);
            *(float2*)(out + (size_t)(r0 + 8) * SEQ + cc) = make_float2(e2, e3);
            srow[mi][0] += e0 + e1;
            srow[mi][1] += e2 + e3;
        }
    }
    #pragma unroll
    for (int mi = 0; mi < 2; mi++) {
        #pragma unroll
        for (int s = 0; s < 2; s++) {
            srow[mi][s] += __shfl_xor_sync(0xffffffffu, srow[mi][s], 1);
            srow[mi][s] += __shfl_xor_sync(0xffffffffu, srow[mi][s], 2);
        }
    }
    __syncthreads();
    float* rs = (float*)smh;
    if (tid4 == 0) {
        #pragma unroll
        for (int mi = 0; mi < 2; mi++) {
            rs[(wm + mi * 16 + group) * 2 + (warp & 1)] = srow[mi][0];
            rs[(wm + mi * 16 + group + 8) * 2 + (warp & 1)] = srow[mi][1];
        }
    }
    __syncthreads();
    if (t < 128)
        psum[((size_t)bh * SEQ + bm + t) * 16 + blockIdx.x] = rs[t * 2] + rs[t * 2 + 1];
}

// ---------------------------------------------------------------------------
__global__ __launch_bounds__(256) void rowinv_kernel(
    const float* __restrict__ psum, float* __restrict__ inv)
{
    int r = blockIdx.x * 256 + threadIdx.x;
    if (r >= NROWS) return;
    float4 a = *(const float4*)(psum + (size_t)r * 16);
    float4 b2 = *(const float4*)(psum + (size_t)r * 16 + 4);
    float4 c = *(const float4*)(psum + (size_t)r * 16 + 8);
    float4 d = *(const float4*)(psum + (size_t)r * 16 + 12);
    float s = a.x + a.y + a.z + a.w + b2.x + b2.y + b2.z + b2.w
            + c.x + c.y + c.z + c.w + d.x + d.y + d.z + d.w;
    inv[r] = 1.0f / s;
}

// ---------------------------------------------------------------------------
// attn @ V via fp16 HMMA 2-term (R8-proven).
// ---------------------------------------------------------------------------
#define AVP 72
#define AV_STAGEF 0
#define AV_AHI    34816
#define AV_ALO    (34816 + 18432)
#define AV_VHI(i) (71680 + (i) * 9216)
#define AV_INV    90112
#define SMEM_AV   (90112 + 512)

__global__ __launch_bounds__(256) void av_mma_kernel(
    float* __restrict__ attn,
    const __half* __restrict__ q16h,
    bf16* __restrict__ aohi, bf16* __restrict__ aolo,
    const float* __restrict__ inv)
{
    extern __shared__ char smc[];
    const uint32_t sbase = smem_u32(smc);
    const int t = threadIdx.x;
    const int warp = t >> 5, lane = t & 31;
    const int bh = blockIdx.y;
    const int b = bh / HEADS, h = bh % HEADS;
    const int bm = blockIdx.x * 128;
    const int wm = warp * 16;

    float* Abase = attn + (size_t)bh * SEQ * SEQ + (size_t)bm * SEQ;
    const __half* Vhi = q16h + (size_t)b * SEQ * D3 + 2 * D_MODEL + h * HD;

    float* inv_s = (float*)(smc + AV_INV);
    if (t < 128) inv_s[t] = inv[(size_t)bh * SEQ + bm + t];

    auto load_chunk = [&](int c) {
        const int k0 = c * 64;
        #pragma unroll
        for (int i = 0; i < 8; i++) {
            int id = t + i * 256;
            int r = id >> 4, c4 = id & 15;
            cp_async16(sbase + AV_STAGEF + (uint32_t)(r * 68 + c4 * 4) * 4,
                       Abase + (size_t)r * SEQ + k0 + c4 * 4);
        }
        const uint32_t vb = c & 1;
        #pragma unroll
        for (int i = 0; i < 2; i++) {
            int id = t + i * 256;
            int r = id >> 3, cs = id & 7;
            cp_async16(sbase + AV_VHI(vb) + (uint32_t)(r * AVP + cs * 8) * 2,
                       Vhi + (size_t)(k0 + r) * D3 + cs * 8);
        }
        CP_COMMIT();
    };

    float acc[8][4];
    #pragma unroll
    for (int nj = 0; nj < 8; nj++)
        #pragma unroll
        for (int e = 0; e < 4; e++) acc[nj][e] = 0.0f;

    load_chunk(0);

    const int a_r = (lane & 7) + ((lane >> 3) & 1) * 8;
    const int a_c = (lane >> 4) * 8;
    const int tb_r = lane & 15;
    const int tb_c = (lane >> 4) * 8;

    const float* stageF = (const float*)(smc + AV_STAGEF);
    __half* Ahi_s = (__half*)(smc + AV_AHI);
    __half* Alo_s = (__half*)(smc + AV_ALO);

    for (int c = 0; c < SEQ / 64; c++) {
        CP_WAIT(0);
        __syncthreads();
        const int k0 = c * 64;
        #pragma unroll
        for (int i = 0; i < 8; i++) {
            int id = t + i * 256;
            int r = id >> 4, c4 = id & 15;
            float4 v = *(const float4*)(stageF + r * 68 + c4 * 4);
            float s = inv_s[r];
            v.x *= s; v.y *= s; v.z *= s; v.w *= s;
            *(float4*)(Abase + (size_t)r * SEQ + k0 + c4 * 4) = v;
            __half h4[4], l4[4];
            float vv[4] = { v.x, v.y, v.z, v.w };
            #pragma unroll
            for (int j = 0; j < 4; j++) {
                h4[j] = __float2half_rn(vv[j]);
                l4[j] = __float2half_rn(vv[j] - __half2float(h4[j]));
            }
            *(uint2*)(Ahi_s + r * AVP + c4 * 4) = *(uint2*)h4;
            *(uint2*)(Alo_s + r * AVP + c4 * 4) = *(uint2*)l4;
        }
        __syncthreads();
        if (c + 1 < SEQ / 64) load_chunk(c + 1);

        const uint32_t tAhi = sbase + AV_AHI;
        const uint32_t tAlo = sbase + AV_ALO;
        const uint32_t tVhi = sbase + AV_VHI(c & 1);

        #pragma unroll
        for (int ks = 0; ks < 4; ks++) {
            uint32_t ah[4], al[4], bhf[16];
            uint32_t aoff = (uint32_t)((wm + a_r) * AVP + ks * 16 + a_c) * 2;
            ldm_x4(tAhi + aoff, ah);
            ldm_x4(tAlo + aoff, al);
            #pragma unroll
            for (int nj2 = 0; nj2 < 4; nj2++) {
                uint32_t boff =
                    (uint32_t)((ks * 16 + tb_r) * AVP + nj2 * 16 + tb_c) * 2;
                ldm_x4_trans(tVhi + boff, bhf + nj2 * 4);
            }
            #pragma unroll
            for (int nj = 0; nj < 8; nj++) {
                mma_f16(acc[nj], ah, bhf + nj * 2);
                mma_f16(acc[nj], al, bhf + nj * 2);
            }
        }
    }

    const int group = lane >> 2, tid4 = lane & 3;
    #pragma unroll
    for (int nj = 0; nj < 8; nj++) {
        int cc = h * HD + nj * 8 + tid4 * 2;
        size_t r0 = (size_t)(b * SEQ + bm + wm + group) * D_MODEL + cc;
        size_t r1 = r0 + (size_t)8 * D_MODEL;
        split_store2_bf(aohi, aolo, r0, acc[nj][0], acc[nj][1]);
        split_store2_bf(aohi, aolo, r1, acc[nj][2], acc[nj][3]);
    }
}

// ---------------------------------------------------------------------------
// Out-proj GEMM, bf16 3-term, fp32 + bias epilogue (R5/R8-proven).
// ---------------------------------------------------------------------------
#define GS_ELEMS (4 * GT_ELEMS)
#define SMEM_GEMM (2 * GS_ELEMS * 2)

__global__ __launch_bounds__(256, 2) void mma_gemm_bias_kernel(
    const bf16* __restrict__ Ahi, const bf16* __restrict__ Alo,
    const bf16* __restrict__ Bhi, const bf16* __restrict__ Blo,
    float* __restrict__ C, const float* __restrict__ bias,
    int M, int N, int K)
{
    extern __shared__ bf16 sm[];
    const uint32_t sbase = smem_u32(sm);
    const int t = threadIdx.x;
    const int warp = t >> 5, lane = t & 31;
    const int bm = blockIdx.y * 128;
    const int bn = blockIdx.x * 128;
    const int wm = (warp >> 1) * 32;
    const int wn = (warp & 1) * 64;

    const bf16* srcs[4] = { Ahi, Alo, Bhi, Blo };

    auto load_stage = [&](int buf, int k0) {
        uint32_t sdst = sbase + (uint32_t)buf * GS_ELEMS * 2;
        #pragma unroll
        for (int m = 0; m < 4; m++) {
            const int rbase = (m < 2) ? bm : bn;
            const bf16* S = srcs[m] + (size_t)rbase * K + k0;
            uint32_t td = sdst + (uint32_t)m * GT_ELEMS * 2;
            #pragma unroll
            for (int i = 0; i < 2; i++) {
                int id = t + i * 256;
                int row = id >> 2, c = id & 3;
                cp_async16(td + (uint32_t)(row * GP + c * 8) * 2,
                           S + (size_t)row * K + c * 8);
            }
        }
        CP_COMMIT();
    };

    float acc[2][8][4];
    #pragma unroll
    for (int mi = 0; mi < 2; mi++)
        #pragma unroll
        for (int nj = 0; nj < 8; nj++)
            #pragma unroll
            for (int e = 0; e < 4; e++) acc[mi][nj][e] = 0.0f;

    const int nch = K >> 5;
    load_stage(0, 0);
    load_stage(1, BK);

    const int a_r = (lane & 7) + ((lane >> 3) & 1) * 8;
    const int a_c = (lane >> 4) * 8;
    const int b_r = (lane & 7) + (lane >> 4) * 8;
    const int b_c = ((lane >> 3) & 1) * 8;

    for (int c = 0; c < nch; c++) {
        if (c < nch - 1) { CP_WAIT(1); } else { CP_WAIT(0); }
        __syncthreads();

        const uint32_t stg = sbase + (uint32_t)(c & 1) * GS_ELEMS * 2;
        const uint32_t tAhi = stg;
        const uint32_t tAlo = stg + GT_ELEMS * 2;
        const uint32_t tBhi = stg + 2 * GT_ELEMS * 2;
        const uint32_t tBlo = stg + 3 * GT_ELEMS * 2;

        #pragma unroll
        for (int ks = 0; ks < BK; ks += 16) {
            uint32_t ah[2][4], al[2][4], bh[16], bl[16];
            #pragma unroll
            for (int mi = 0; mi < 2; mi++) {
                uint32_t off = (uint32_t)((wm + mi * 16 + a_r) * GP + ks + a_c) * 2;
                ldm_x4(tAhi + off, ah[mi]);
                ldm_x4(tAlo + off, al[mi]);
            }
            #pragma unroll
            for (int nj2 = 0; nj2 < 4; nj2++) {
                uint32_t off = (uint32_t)((wn + nj2 * 16 + b_r) * GP + ks + b_c) * 2;
                ldm_x4(tBhi + off, bh + nj2 * 4);
                ldm_x4(tBlo + off, bl + nj2 * 4);
            }
            #pragma unroll
            for (int mi = 0; mi < 2; mi++)
                #pragma unroll
                for (int nj = 0; nj < 8; nj++)
                    mma_bf16(acc[mi][nj], ah[mi], bh + nj * 2);
            #pragma unroll
            for (int mi = 0; mi < 2; mi++)
                #pragma unroll
                for (int nj = 0; nj < 8; nj++)
                    mma_bf16(acc[mi][nj], ah[mi], bl + nj * 2);
            #pragma unroll
            for (int mi = 0; mi < 2; mi++)
                #pragma unroll
                for (int nj = 0; nj < 8; nj++)
                    mma_bf16(acc[mi][nj], al[mi], bh + nj * 2);
        }
        __syncthreads();
        if (c + 2 < nch) load_stage(c & 1, (c + 2) * BK);
    }

    const int group = lane >> 2, tid4 = lane & 3;
    #pragma unroll
    for (int mi = 0; mi < 2; mi++) {
        int r0 = bm + wm + mi * 16 + group;
        #pragma unroll
        for (int nj = 0; nj < 8; nj++) {
            int cc = bn + wn + nj * 8 + tid4 * 2;
            float2 bb = *(const float2*)(bias + cc);
            *(float2*)(C + (size_t)r0 * N + cc) =
                make_float2(acc[mi][nj][0] + bb.x, acc[mi][nj][1] + bb.y);
            *(float2*)(C + (size_t)(r0 + 8) * N + cc) =
                make_float2(acc[mi][nj][2] + bb.x, acc[mi][nj][3] + bb.y);
        }
    }
}

// ---------------------------------------------------------------------------
// fp32 -> fp16 hi/lo split (x input)
// ---------------------------------------------------------------------------
__global__ __launch_bounds__(256) void split_h_kernel(
    const float* __restrict__ in, __half* __restrict__ hi,
    __half* __restrict__ lo, int n4)
{
    int i = blockIdx.x * 256 + threadIdx.x;
    if (i >= n4) return;
    float4 v = ((const float4*)in)[i];
    __half h[4], l[4];
    float vv[4] = { v.x, v.y, v.z, v.w };
    #pragma unroll
    for (int j = 0; j < 4; j++) {
        h[j] = __float2half_rn(vv[j]);
        l[j] = __float2half_rn(vv[j] - __half2float(h[j]));
    }
    ((uint2*)hi)[i] = *(uint2*)h;
    ((uint2*)lo)[i] = *(uint2*)l;
}

// ---------------------------------------------------------------------------
// W[K,N] fp32 -> Wt[N,K] fp16 single (transpose + round)
// ---------------------------------------------------------------------------
__global__ __launch_bounds__(256) void transpose_h_kernel(
    const float* __restrict__ W, __half* __restrict__ o16, int K, int N)
{
    __shared__ float tile[32][33];
    const int nx = blockIdx.x * 32;
    const int ky = blockIdx.y * 32;
    const int tx = threadIdx.x & 31;
    const int ty = threadIdx.x >> 5;
    #pragma unroll
    for (int i = 0; i < 4; i++)
        tile[ty + 8 * i][tx] = W[(size_t)(ky + ty + 8 * i) * N + nx + tx];
    __syncthreads();
    #pragma unroll
    for (int i = 0; i < 4; i++) {
        float v = tile[tx][ty + 8 * i];
        o16[(size_t)(nx + ty + 8 * i) * K + ky + tx] = __float2half_rn(v);
    }
}

// ---------------------------------------------------------------------------
// W[K,N] fp32 -> Wt[N,K] bf16 hi/lo (transpose + split) — for W_h
// ---------------------------------------------------------------------------
__global__ __launch_bounds__(256) void transpose_split_kernel(
    const float* __restrict__ W, bf16* __restrict__ hi,
    bf16* __restrict__ lo, int K, int N)
{
    __shared__ float tile[32][33];
    const int nx = blockIdx.x * 32;
    const int ky = blockIdx.y * 32;
    const int tx = threadIdx.x & 31;
    const int ty = threadIdx.x >> 5;
    #pragma unroll
    for (int i = 0; i < 4; i++)
        tile[ty + 8 * i][tx] = W[(size_t)(ky + ty + 8 * i) * N + nx + tx];
    __syncthreads();
    #pragma unroll
    for (int i = 0; i < 4; i++) {
        float v = tile[tx][ty + 8 * i];
        bf16 h = __float2bfloat16(v);
        bf16 l = __float2bfloat16(v - __bfloat162float(h));
        size_t o = (size_t)(nx + ty + 8 * i) * K + ky + tx;
        hi[o] = h;
        lo[o] = l;
    }
}

// ---------------------------------------------------------------------------
extern "C" void kernel_launch(void* const* d_in, const int* in_sizes, int n_in,
                              void* d_out, int out_size)
{
    const float* x     = (const float*)d_in[0];
    const float* mask  = (const float*)d_in[1];
    const float* W_qkv = (const float*)d_in[2];
    const float* W_h   = (const float*)d_in[3];
    const float* b_h   = (const float*)d_in[4];

    float* out  = (float*)d_out;
    float* attn = out + (size_t)BL * D_MODEL;

    bf16 *whhi, *whlo, *aohi, *aolo;
    __half *x16h, *x16l, *wq16, *q16h, *q16l;
    float *psum, *inv;
    cudaGetSymbolAddress((void**)&x16h, g_x16h);
    cudaGetSymbolAddress((void**)&x16l, g_x16l);
    cudaGetSymbolAddress((void**)&wq16, g_wq16);
    cudaGetSymbolAddress((void**)&whhi, g_whT_hi);
    cudaGetSymbolAddress((void**)&whlo, g_whT_lo);
    cudaGetSymbolAddress((void**)&q16h, g_q16h);
    cudaGetSymbolAddress((void**)&q16l, g_q16l);
    cudaGetSymbolAddress((void**)&aohi, g_ao_hi);
    cudaGetSymbolAddress((void**)&aolo, g_ao_lo);
    cudaGetSymbolAddress((void**)&psum, g_psum);
    cudaGetSymbolAddress((void**)&inv, g_inv);

    cudaFuncSetAttribute(qkv_gemm_f16_kernel, cudaFuncAttributeMaxDynamicSharedMemorySize, SMEM_QKV);
    cudaFuncSetAttribute(mma_gemm_bias_kernel, cudaFuncAttributeMaxDynamicSharedMemorySize, SMEM_GEMM);
    cudaFuncSetAttribute(scores_mma_kernel, cudaFuncAttributeMaxDynamicSharedMemorySize, SMEM_SCORES);
    cudaFuncSetAttribute(av_mma_kernel, cudaFuncAttributeMaxDynamicSharedMemorySize, SMEM_AV);

    // 0) input conversions
    split_h_kernel<<<(BL * D_MODEL / 4 + 255) / 256, 256>>>(x, x16h, x16l, BL * D_MODEL / 4);
    transpose_h_kernel<<<dim3(D3 / 32, D_MODEL / 32), 256>>>(W_qkv, wq16, D_MODEL, D3);
    transpose_split_kernel<<<dim3(D_MODEL / 32, D_MODEL / 32), 256>>>(W_h, whhi, whlo, D_MODEL, D_MODEL);

    // 1) QKV = x @ W_qkv (fp16 2-term) -> fp16 hi/lo
    qkv_gemm_f16_kernel<<<dim3(D3 / 128, BL / 128), 256, SMEM_QKV>>>(
        x16h, x16l, wq16, q16h, q16l, BL, D3, D_MODEL);

    // 2) scores (fp16 2-term) + fused exp -> unnormalized attn + psums
    scores_mma_kernel<<<dim3(SEQ / 128, SEQ / 128, BATCH * HEADS), 256, SMEM_SCORES>>>(
        mask, attn, q16h, q16l, psum);

    // 3) row-sum inverse
    rowinv_kernel<<<NROWS / 256, 256>>>(psum, inv);

    // 4) attn @ V (fp16 2-term, normalizes attn in place) -> ao bf16 hi/lo
    av_mma_kernel<<<dim3(SEQ / 128, BATCH * HEADS), 256, SMEM_AV>>>(
        attn, q16h, aohi, aolo, inv);

    // 5) output = ao @ W_h + b_h (bf16 3-term)
    mma_gemm_bias_kernel<<<dim3(D_MODEL / 128, BL / 128), 256, SMEM_GEMM>>>(
        aohi, aolo, whhi, whlo, out, b_h, BL, D_MODEL, D_MODEL);
}

// round 10
// speedup vs baseline: 2.1940x; 1.1179x over previous
#include <cuda_runtime.h>
#include <cuda_bf16.h>
#include <cuda_fp16.h>
#include <math.h>
#include <stdint.h>

#define D_MODEL 1024
#define HEADS 16
#define HD 64
#define BATCH 2
#define SEQ 2048
#define BL (BATCH * SEQ)      /* 4096 */
#define D3 (3 * D_MODEL)      /* 3072 */
#define NROWS (BATCH * HEADS * SEQ)

typedef __nv_bfloat16 bf16;

// ---------------------------------------------------------------------------
// Scratch (allocation-free: __device__ globals)
// ---------------------------------------------------------------------------
__device__ __half g_x16h[(size_t)BL * D_MODEL];
__device__ __half g_x16l[(size_t)BL * D_MODEL];
__device__ __half g_wq16[(size_t)D3 * D_MODEL];
__device__ bf16  g_whT_hi[(size_t)D_MODEL * D_MODEL];
__device__ bf16  g_whT_lo[(size_t)D_MODEL * D_MODEL];
__device__ __half g_q16h[(size_t)BL * D3];
__device__ __half g_q16l[(size_t)BL * D3];
__device__ bf16  g_ao_hi[(size_t)BL * D_MODEL];
__device__ bf16  g_ao_lo[(size_t)BL * D_MODEL];
__device__ float g_psum[(size_t)NROWS * 16];
__device__ float g_inv[(size_t)NROWS];
__device__ __half g_e16[(size_t)NROWS * SEQ];   // unnormalized exp, fp16 (256MB)

// ---------------------------------------------------------------------------
// Portable PTX helpers
// ---------------------------------------------------------------------------
__device__ __forceinline__ uint32_t smem_u32(const void* p) {
    uint32_t a;
    asm("{ .reg .u64 t; cvta.to.shared.u64 t, %1; cvt.u32.u64 %0, t; }"
        : "=r"(a) : "l"(p));
    return a;
}
__device__ __forceinline__ void cp_async16(uint32_t s, const void* g) {
    asm volatile("cp.async.cg.shared.global [%0], [%1], 16;" :: "r"(s), "l"(g));
}
#define CP_COMMIT() asm volatile("cp.async.commit_group;" ::: "memory")
#define CP_WAIT(n)  asm volatile("cp.async.wait_group %0;" :: "n"(n) : "memory")

__device__ __forceinline__ void ldm_x4(uint32_t addr, uint32_t* r) {
    asm volatile("ldmatrix.sync.aligned.m8n8.x4.shared.b16 {%0,%1,%2,%3}, [%4];"
        : "=r"(r[0]), "=r"(r[1]), "=r"(r[2]), "=r"(r[3]) : "r"(addr));
}
__device__ __forceinline__ void ldm_x4_trans(uint32_t addr, uint32_t* r) {
    asm volatile("ldmatrix.sync.aligned.m8n8.x4.trans.shared.b16 {%0,%1,%2,%3}, [%4];"
        : "=r"(r[0]), "=r"(r[1]), "=r"(r[2]), "=r"(r[3]) : "r"(addr));
}
__device__ __forceinline__ void mma_bf16(float* c, const uint32_t* a, const uint32_t* b) {
    asm volatile(
        "mma.sync.aligned.m16n8k16.row.col.f32.bf16.bf16.f32 "
        "{%0,%1,%2,%3}, {%4,%5,%6,%7}, {%8,%9}, {%0,%1,%2,%3};"
        : "+f"(c[0]), "+f"(c[1]), "+f"(c[2]), "+f"(c[3])
        : "r"(a[0]), "r"(a[1]), "r"(a[2]), "r"(a[3]), "r"(b[0]), "r"(b[1]));
}
__device__ __forceinline__ void mma_f16(float* c, const uint32_t* a, const uint32_t* b) {
    asm volatile(
        "mma.sync.aligned.m16n8k16.row.col.f32.f16.f16.f32 "
        "{%0,%1,%2,%3}, {%4,%5,%6,%7}, {%8,%9}, {%0,%1,%2,%3};"
        : "+f"(c[0]), "+f"(c[1]), "+f"(c[2]), "+f"(c[3])
        : "r"(a[0]), "r"(a[1]), "r"(a[2]), "r"(a[3]), "r"(b[0]), "r"(b[1]));
}
__device__ __forceinline__ void split_store2_bf(bf16* hi, bf16* lo, size_t idx,
                                                float a, float b) {
    bf16 ha = __float2bfloat16(a), hb = __float2bfloat16(b);
    bf16 la = __float2bfloat16(a - __bfloat162float(ha));
    bf16 lb = __float2bfloat16(b - __bfloat162float(hb));
    __nv_bfloat162 hv; hv.x = ha; hv.y = hb;
    __nv_bfloat162 lv; lv.x = la; lv.y = lb;
    *(__nv_bfloat162*)(hi + idx) = hv;
    *(__nv_bfloat162*)(lo + idx) = lv;
}
__device__ __forceinline__ void split_store2_h(__half* hi, __half* lo, size_t idx,
                                               float a, float b) {
    __half ha = __float2half_rn(a), hb = __float2half_rn(b);
    __half la = __float2half_rn(a - __half2float(ha));
    __half lb = __float2half_rn(b - __half2float(hb));
    __half2 hv; hv.x = ha; hv.y = hb;
    __half2 lv; lv.x = la; lv.y = lb;
    *(__half2*)(hi + idx) = hv;
    *(__half2*)(lo + idx) = lv;
}
__device__ __forceinline__ float fexp(float x) {
    float t = x * 1.4426950408889634f;
    t = fmaxf(t, -126.0f);
    float n = rintf(t);
    float f = t - n;
    float p = 1.5403530e-4f;
    p = fmaf(p, f, 1.3333558e-3f);
    p = fmaf(p, f, 9.6181291e-3f);
    p = fmaf(p, f, 5.5504109e-2f);
    p = fmaf(p, f, 2.4022651e-1f);
    p = fmaf(p, f, 6.9314718e-1f);
    p = fmaf(p, f, 1.0f);
    return p * __int_as_float(((int)n + 127) << 23);
}

// ---------------------------------------------------------------------------
// fp16 2-term QKV GEMM (R9-proven).
// ---------------------------------------------------------------------------
#define BK 32
#define GP 40
#define GT_ELEMS (128 * GP)
#define QS_ELEMS (3 * GT_ELEMS)
#define SMEM_QKV (2 * QS_ELEMS * 2)

__global__ __launch_bounds__(256, 2) void qkv_gemm_f16_kernel(
    const __half* __restrict__ Ahi, const __half* __restrict__ Alo,
    const __half* __restrict__ Bhi,
    __half* __restrict__ Chi, __half* __restrict__ Clo,
    int M, int N, int K)
{
    extern __shared__ __half smq[];
    const uint32_t sbase = smem_u32(smq);
    const int t = threadIdx.x;
    const int warp = t >> 5, lane = t & 31;
    const int bm = blockIdx.y * 128;
    const int bn = blockIdx.x * 128;
    const int wm = (warp >> 1) * 32;
    const int wn = (warp & 1) * 64;

    const __half* srcs[3] = { Ahi, Alo, Bhi };

    auto load_stage = [&](int buf, int k0) {
        uint32_t sdst = sbase + (uint32_t)buf * QS_ELEMS * 2;
        #pragma unroll
        for (int m = 0; m < 3; m++) {
            const int rbase = (m < 2) ? bm : bn;
            const __half* S = srcs[m] + (size_t)rbase * K + k0;
            uint32_t td = sdst + (uint32_t)m * GT_ELEMS * 2;
            #pragma unroll
            for (int i = 0; i < 2; i++) {
                int id = t + i * 256;
                int row = id >> 2, c = id & 3;
                cp_async16(td + (uint32_t)(row * GP + c * 8) * 2,
                           S + (size_t)row * K + c * 8);
            }
        }
        CP_COMMIT();
    };

    float acc[2][8][4];
    #pragma unroll
    for (int mi = 0; mi < 2; mi++)
        #pragma unroll
        for (int nj = 0; nj < 8; nj++)
            #pragma unroll
            for (int e = 0; e < 4; e++) acc[mi][nj][e] = 0.0f;

    const int nch = K >> 5;
    load_stage(0, 0);
    load_stage(1, BK);

    const int a_r = (lane & 7) + ((lane >> 3) & 1) * 8;
    const int a_c = (lane >> 4) * 8;
    const int b_r = (lane & 7) + (lane >> 4) * 8;
    const int b_c = ((lane >> 3) & 1) * 8;

    for (int c = 0; c < nch; c++) {
        if (c < nch - 1) { CP_WAIT(1); } else { CP_WAIT(0); }
        __syncthreads();

        const uint32_t stg = sbase + (uint32_t)(c & 1) * QS_ELEMS * 2;
        const uint32_t tAhi = stg;
        const uint32_t tAlo = stg + GT_ELEMS * 2;
        const uint32_t tBhi = stg + 2 * GT_ELEMS * 2;

        #pragma unroll
        for (int ks = 0; ks < BK; ks += 16) {
            uint32_t ah[2][4], al[2][4], bh[16];
            #pragma unroll
            for (int mi = 0; mi < 2; mi++) {
                uint32_t off = (uint32_t)((wm + mi * 16 + a_r) * GP + ks + a_c) * 2;
                ldm_x4(tAhi + off, ah[mi]);
                ldm_x4(tAlo + off, al[mi]);
            }
            #pragma unroll
            for (int nj2 = 0; nj2 < 4; nj2++) {
                uint32_t off = (uint32_t)((wn + nj2 * 16 + b_r) * GP + ks + b_c) * 2;
                ldm_x4(tBhi + off, bh + nj2 * 4);
            }
            #pragma unroll
            for (int mi = 0; mi < 2; mi++)
                #pragma unroll
                for (int nj = 0; nj < 8; nj++) {
                    mma_f16(acc[mi][nj], ah[mi], bh + nj * 2);
                    mma_f16(acc[mi][nj], al[mi], bh + nj * 2);
                }
        }
        __syncthreads();
        if (c + 2 < nch) load_stage(c & 1, (c + 2) * BK);
    }

    const int group = lane >> 2, tid4 = lane & 3;
    #pragma unroll
    for (int mi = 0; mi < 2; mi++) {
        int r0 = bm + wm + mi * 16 + group;
        #pragma unroll
        for (int nj = 0; nj < 8; nj++) {
            int cc = bn + wn + nj * 8 + tid4 * 2;
            split_store2_h(Chi, Clo, (size_t)r0 * N + cc,
                           acc[mi][nj][0], acc[mi][nj][1]);
            split_store2_h(Chi, Clo, (size_t)(r0 + 8) * N + cc,
                           acc[mi][nj][2], acc[mi][nj][3]);
        }
    }
}

// ---------------------------------------------------------------------------
// Scores via fp16 HMMA 2-term; fused mask+scale+exp; writes UNNORMALIZED
// exp as fp16 to scratch e16; psums from the fp16-rounded values.
// ---------------------------------------------------------------------------
#define SP 72
#define ST_ELEMS (128 * SP)
#define SMEM_SCORES (3 * ST_ELEMS * 2)

__global__ __launch_bounds__(256) void scores_mma_kernel(
    const float* __restrict__ mask, __half* __restrict__ e16,
    const __half* __restrict__ q16h, const __half* __restrict__ q16l,
    float* __restrict__ psum)
{
    extern __shared__ __half smh[];
    const uint32_t sbase = smem_u32(smh);
    const int t = threadIdx.x;
    const int warp = t >> 5, lane = t & 31;
    const int bh = blockIdx.z;
    const int b = bh / HEADS, h = bh % HEADS;
    const int bm = blockIdx.y * 128;
    const int bn = blockIdx.x * 128;
    const int wm = (warp >> 1) * 32;
    const int wn = (warp & 1) * 64;

    const __half* bases[3] = {
        q16h + ((size_t)(b * SEQ + bm)) * D3 + h * HD,
        q16l + ((size_t)(b * SEQ + bm)) * D3 + h * HD,
        q16h + ((size_t)(b * SEQ + bn)) * D3 + D_MODEL + h * HD };
    #pragma unroll
    for (int m = 0; m < 3; m++) {
        uint32_t td = sbase + (uint32_t)m * ST_ELEMS * 2;
        #pragma unroll
        for (int i = 0; i < 4; i++) {
            int id = t + i * 256;
            int r = id >> 3, c = id & 7;
            cp_async16(td + (uint32_t)(r * SP + c * 8) * 2,
                       bases[m] + (size_t)r * D3 + c * 8);
        }
    }
    CP_COMMIT();

    float acc[2][8][4];
    #pragma unroll
    for (int mi = 0; mi < 2; mi++)
        #pragma unroll
        for (int nj = 0; nj < 8; nj++)
            #pragma unroll
            for (int e = 0; e < 4; e++) acc[mi][nj][e] = 0.0f;

    const int a_r = (lane & 7) + ((lane >> 3) & 1) * 8;
    const int a_c = (lane >> 4) * 8;
    const int b_r = (lane & 7) + (lane >> 4) * 8;
    const int b_c = ((lane >> 3) & 1) * 8;

    const uint32_t tQhi = sbase;
    const uint32_t tQlo = sbase + ST_ELEMS * 2;
    const uint32_t tKhi = sbase + 2 * ST_ELEMS * 2;

    CP_WAIT(0);
    __syncthreads();

    #pragma unroll
    for (int ks = 0; ks < 4; ks++) {
        uint32_t ah[2][4], al[2][4], bhf[16];
        #pragma unroll
        for (int mi = 0; mi < 2; mi++) {
            uint32_t off = (uint32_t)((wm + mi * 16 + a_r) * SP + ks * 16 + a_c) * 2;
            ldm_x4(tQhi + off, ah[mi]);
            ldm_x4(tQlo + off, al[mi]);
        }
        #pragma unroll
        for (int nj2 = 0; nj2 < 4; nj2++) {
            uint32_t off = (uint32_t)((wn + nj2 * 16 + b_r) * SP + ks * 16 + b_c) * 2;
            ldm_x4(tKhi + off, bhf + nj2 * 4);
        }
        #pragma unroll
        for (int mi = 0; mi < 2; mi++)
            #pragma unroll
            for (int nj = 0; nj < 8; nj++) {
                mma_f16(acc[mi][nj], ah[mi], bhf + nj * 2);
                mma_f16(acc[mi][nj], al[mi], bhf + nj * 2);
            }
    }

    const int group = lane >> 2, tid4 = lane & 3;
    float mq[4];
    #pragma unroll
    for (int mi = 0; mi < 2; mi++) {
        mq[mi * 2 + 0] = mask[b * SEQ + bm + wm + mi * 16 + group];
        mq[mi * 2 + 1] = mask[b * SEQ + bm + wm + mi * 16 + group + 8];
    }
    __half* out = e16 + (size_t)bh * SEQ * SEQ;
    float srow[2][2];
    srow[0][0] = srow[0][1] = srow[1][0] = srow[1][1] = 0.0f;
    #pragma unroll
    for (int nj = 0; nj < 8; nj++) {
        int cc = bn + wn + nj * 8 + tid4 * 2;
        float2 mk = *(const float2*)(mask + b * SEQ + cc);
        #pragma unroll
        for (int mi = 0; mi < 2; mi++) {
            int r0 = bm + wm + mi * 16 + group;
            float v0 = acc[mi][nj][0], v1 = acc[mi][nj][1];
            float v2 = acc[mi][nj][2], v3 = acc[mi][nj][3];
            if (mq[mi * 2 + 0] * mk.x == 0.0f) v0 = -100000.0f;
            if (mq[mi * 2 + 0] * mk.y == 0.0f) v1 = -100000.0f;
            if (mq[mi * 2 + 1] * mk.x == 0.0f) v2 = -100000.0f;
            if (mq[mi * 2 + 1] * mk.y == 0.0f) v3 = -100000.0f;
            // exp, floored so fp16 never rounds to exactly 0 (inv safety)
            __half h0 = __float2half_rn(fmaxf(fexp(v0 * 0.03125f), 1e-7f));
            __half h1 = __float2half_rn(fmaxf(fexp(v1 * 0.03125f), 1e-7f));
            __half h2 = __float2half_rn(fmaxf(fexp(v2 * 0.03125f), 1e-7f));
            __half h3 = __float2half_rn(fmaxf(fexp(v3 * 0.03125f), 1e-7f));
            __half2 p01; p01.x = h0; p01.y = h1;
            __half2 p23; p23.x = h2; p23.y = h3;
            *(__half2*)(out + (size_t)r0 * SEQ + cc) = p01;
            *(__half2*)(out + (size_t)(r0 + 8) * SEQ + cc) = p23;
            srow[mi][0] += __half2float(h0) + __half2float(h1);
            srow[mi][1] += __half2float(h2) + __half2float(h3);
        }
    }
    #pragma unroll
    for (int mi = 0; mi < 2; mi++) {
        #pragma unroll
        for (int s = 0; s < 2; s++) {
            srow[mi][s] += __shfl_xor_sync(0xffffffffu, srow[mi][s], 1);
            srow[mi][s] += __shfl_xor_sync(0xffffffffu, srow[mi][s], 2);
        }
    }
    __syncthreads();
    float* rs = (float*)smh;
    if (tid4 == 0) {
        #pragma unroll
        for (int mi = 0; mi < 2; mi++) {
            rs[(wm + mi * 16 + group) * 2 + (warp & 1)] = srow[mi][0];
            rs[(wm + mi * 16 + group + 8) * 2 + (warp & 1)] = srow[mi][1];
        }
    }
    __syncthreads();
    if (t < 128)
        psum[((size_t)bh * SEQ + bm + t) * 16 + blockIdx.x] = rs[t * 2] + rs[t * 2 + 1];
}

// ---------------------------------------------------------------------------
__global__ __launch_bounds__(256) void rowinv_kernel(
    const float* __restrict__ psum, float* __restrict__ inv)
{
    int r = blockIdx.x * 256 + threadIdx.x;
    if (r >= NROWS) return;
    float4 a = *(const float4*)(psum + (size_t)r * 16);
    float4 b2 = *(const float4*)(psum + (size_t)r * 16 + 4);
    float4 c = *(const float4*)(psum + (size_t)r * 16 + 8);
    float4 d = *(const float4*)(psum + (size_t)r * 16 + 12);
    float s = a.x + a.y + a.z + a.w + b2.x + b2.y + b2.z + b2.w
            + c.x + c.y + c.z + c.w + d.x + d.y + d.z + d.w;
    inv[r] = 1.0f / s;
}

// ---------------------------------------------------------------------------
// av v2: reads fp16 e-scratch (exact A operand, 1-term MMA with V_hi),
// writes the normalized fp32 attn OUTPUT (e16*inv), scales ao acc by inv.
// SMEM: E bufs 2x[128][72]h | V bufs 2x[64][72]h | inv[128]
// ---------------------------------------------------------------------------
#define EP 72
#define AVE(i) ((i) * 18432)
#define AVV(i) (36864 + (i) * 9216)
#define AVINV  55296
#define SMEM_AV (55296 + 512)

__global__ __launch_bounds__(256) void av_mma_kernel(
    const __half* __restrict__ e16, float* __restrict__ attn,
    const __half* __restrict__ q16h,
    bf16* __restrict__ aohi, bf16* __restrict__ aolo,
    const float* __restrict__ inv)
{
    extern __shared__ char smc[];
    const uint32_t sbase = smem_u32(smc);
    const int t = threadIdx.x;
    const int warp = t >> 5, lane = t & 31;
    const int bh = blockIdx.y;
    const int b = bh / HEADS, h = bh % HEADS;
    const int bm = blockIdx.x * 128;
    const int wm = warp * 16;

    const __half* Ebase = e16 + (size_t)bh * SEQ * SEQ + (size_t)bm * SEQ;
    float* Abase = attn + (size_t)bh * SEQ * SEQ + (size_t)bm * SEQ;
    const __half* Vhi = q16h + (size_t)b * SEQ * D3 + 2 * D_MODEL + h * HD;

    float* inv_s = (float*)(smc + AVINV);
    if (t < 128) inv_s[t] = inv[(size_t)bh * SEQ + bm + t];
    __syncthreads();

    auto load_chunk = [&](int c) {
        const int k0 = c * 64;
        const uint32_t buf = c & 1;
        #pragma unroll
        for (int i = 0; i < 4; i++) {           // E: 128 rows x 8 segs
            int id = t + i * 256;
            int r = id >> 3, cs = id & 7;
            cp_async16(sbase + AVE(buf) + (uint32_t)(r * EP + cs * 8) * 2,
                       Ebase + (size_t)r * SEQ + k0 + cs * 8);
        }
        #pragma unroll
        for (int i = 0; i < 2; i++) {           // V: 64 rows x 8 segs
            int id = t + i * 256;
            int r = id >> 3, cs = id & 7;
            cp_async16(sbase + AVV(buf) + (uint32_t)(r * EP + cs * 8) * 2,
                       Vhi + (size_t)(k0 + r) * D3 + cs * 8);
        }
        CP_COMMIT();
    };

    float acc[8][4];
    #pragma unroll
    for (int nj = 0; nj < 8; nj++)
        #pragma unroll
        for (int e = 0; e < 4; e++) acc[nj][e] = 0.0f;

    load_chunk(0);

    const int a_r = (lane & 7) + ((lane >> 3) & 1) * 8;
    const int a_c = (lane >> 4) * 8;
    const int tb_r = lane & 15;
    const int tb_c = (lane >> 4) * 8;

    for (int c = 0; c < SEQ / 64; c++) {
        CP_WAIT(0);
        __syncthreads();
        const int k0 = c * 64;
        const uint32_t buf = c & 1;
        if (c + 1 < SEQ / 64) load_chunk(c + 1);

        // normalized fp32 attn write-back from fp16 SMEM
        const __half* Es = (const __half*)(smc + AVE(buf));
        #pragma unroll
        for (int i = 0; i < 8; i++) {
            int id = t + i * 256;
            int r = id >> 4, c4 = id & 15;
            uint2 raw = *(const uint2*)(Es + r * EP + c4 * 4);
            __half2 p01 = *(__half2*)&raw.x;
            __half2 p23 = *(__half2*)&raw.y;
            float s = inv_s[r];
            float4 o;
            o.x = __half2float(p01.x) * s;
            o.y = __half2float(p01.y) * s;
            o.z = __half2float(p23.x) * s;
            o.w = __half2float(p23.y) * s;
            *(float4*)(Abase + (size_t)r * SEQ + k0 + c4 * 4) = o;
        }

        // MMA: 1-term (E exact fp16) x V_hi
        const uint32_t tA = sbase + AVE(buf);
        const uint32_t tV = sbase + AVV(buf);
        #pragma unroll
        for (int ks = 0; ks < 4; ks++) {
            uint32_t ah[4], bhf[16];
            uint32_t aoff = (uint32_t)((wm + a_r) * EP + ks * 16 + a_c) * 2;
            ldm_x4(tA + aoff, ah);
            #pragma unroll
            for (int nj2 = 0; nj2 < 4; nj2++) {
                uint32_t boff =
                    (uint32_t)((ks * 16 + tb_r) * EP + nj2 * 16 + tb_c) * 2;
                ldm_x4_trans(tV + boff, bhf + nj2 * 4);
            }
            #pragma unroll
            for (int nj = 0; nj < 8; nj++)
                mma_f16(acc[nj], ah, bhf + nj * 2);
        }
    }

    const int group = lane >> 2, tid4 = lane & 3;
    const float ia = inv_s[wm + group];
    const float ib = inv_s[wm + group + 8];
    #pragma unroll
    for (int nj = 0; nj < 8; nj++) {
        int cc = h * HD + nj * 8 + tid4 * 2;
        size_t r0 = (size_t)(b * SEQ + bm + wm + group) * D_MODEL + cc;
        size_t r1 = r0 + (size_t)8 * D_MODEL;
        split_store2_bf(aohi, aolo, r0, acc[nj][0] * ia, acc[nj][1] * ia);
        split_store2_bf(aohi, aolo, r1, acc[nj][2] * ib, acc[nj][3] * ib);
    }
}

// ---------------------------------------------------------------------------
// Out-proj GEMM, bf16 3-term, fp32 + bias epilogue (proven).
// ---------------------------------------------------------------------------
#define GS_ELEMS (4 * GT_ELEMS)
#define SMEM_GEMM (2 * GS_ELEMS * 2)

__global__ __launch_bounds__(256, 2) void mma_gemm_bias_kernel(
    const bf16* __restrict__ Ahi, const bf16* __restrict__ Alo,
    const bf16* __restrict__ Bhi, const bf16* __restrict__ Blo,
    float* __restrict__ C, const float* __restrict__ bias,
    int M, int N, int K)
{
    extern __shared__ bf16 sm[];
    const uint32_t sbase = smem_u32(sm);
    const int t = threadIdx.x;
    const int warp = t >> 5, lane = t & 31;
    const int bm = blockIdx.y * 128;
    const int bn = blockIdx.x * 128;
    const int wm = (warp >> 1) * 32;
    const int wn = (warp & 1) * 64;

    const bf16* srcs[4] = { Ahi, Alo, Bhi, Blo };

    auto load_stage = [&](int buf, int k0) {
        uint32_t sdst = sbase + (uint32_t)buf * GS_ELEMS * 2;
        #pragma unroll
        for (int m = 0; m < 4; m++) {
            const int rbase = (m < 2) ? bm : bn;
            const bf16* S = srcs[m] + (size_t)rbase * K + k0;
            uint32_t td = sdst + (uint32_t)m * GT_ELEMS * 2;
            #pragma unroll
            for (int i = 0; i < 2; i++) {
                int id = t + i * 256;
                int row = id >> 2, c = id & 3;
                cp_async16(td + (uint32_t)(row * GP + c * 8) * 2,
                           S + (size_t)row * K + c * 8);
            }
        }
        CP_COMMIT();
    };

    float acc[2][8][4];
    #pragma unroll
    for (int mi = 0; mi < 2; mi++)
        #pragma unroll
        for (int nj = 0; nj < 8; nj++)
            #pragma unroll
            for (int e = 0; e < 4; e++) acc[mi][nj][e] = 0.0f;

    const int nch = K >> 5;
    load_stage(0, 0);
    load_stage(1, BK);

    const int a_r = (lane & 7) + ((lane >> 3) & 1) * 8;
    const int a_c = (lane >> 4) * 8;
    const int b_r = (lane & 7) + (lane >> 4) * 8;
    const int b_c = ((lane >> 3) & 1) * 8;

    for (int c = 0; c < nch; c++) {
        if (c < nch - 1) { CP_WAIT(1); } else { CP_WAIT(0); }
        __syncthreads();

        const uint32_t stg = sbase + (uint32_t)(c & 1) * GS_ELEMS * 2;
        const uint32_t tAhi = stg;
        const uint32_t tAlo = stg + GT_ELEMS * 2;
        const uint32_t tBhi = stg + 2 * GT_ELEMS * 2;
        const uint32_t tBlo = stg + 3 * GT_ELEMS * 2;

        #pragma unroll
        for (int ks = 0; ks < BK; ks += 16) {
            uint32_t ah[2][4], al[2][4], bh[16], bl[16];
            #pragma unroll
            for (int mi = 0; mi < 2; mi++) {
                uint32_t off = (uint32_t)((wm + mi * 16 + a_r) * GP + ks + a_c) * 2;
                ldm_x4(tAhi + off, ah[mi]);
                ldm_x4(tAlo + off, al[mi]);
            }
            #pragma unroll
            for (int nj2 = 0; nj2 < 4; nj2++) {
                uint32_t off = (uint32_t)((wn + nj2 * 16 + b_r) * GP + ks + b_c) * 2;
                ldm_x4(tBhi + off, bh + nj2 * 4);
                ldm_x4(tBlo + off, bl + nj2 * 4);
            }
            #pragma unroll
            for (int mi = 0; mi < 2; mi++)
                #pragma unroll
                for (int nj = 0; nj < 8; nj++)
                    mma_bf16(acc[mi][nj], ah[mi], bh + nj * 2);
            #pragma unroll
            for (int mi = 0; mi < 2; mi++)
                #pragma unroll
                for (int nj = 0; nj < 8; nj++)
                    mma_bf16(acc[mi][nj], ah[mi], bl + nj * 2);
            #pragma unroll
            for (int mi = 0; mi < 2; mi++)
                #pragma unroll
                for (int nj = 0; nj < 8; nj++)
                    mma_bf16(acc[mi][nj], al[mi], bh + nj * 2);
        }
        __syncthreads();
        if (c + 2 < nch) load_stage(c & 1, (c + 2) * BK);
    }

    const int group = lane >> 2, tid4 = lane & 3;
    #pragma unroll
    for (int mi = 0; mi < 2; mi++) {
        int r0 = bm + wm + mi * 16 + group;
        #pragma unroll
        for (int nj = 0; nj < 8; nj++) {
            int cc = bn + wn + nj * 8 + tid4 * 2;
            float2 bb = *(const float2*)(bias + cc);
            *(float2*)(C + (size_t)r0 * N + cc) =
                make_float2(acc[mi][nj][0] + bb.x, acc[mi][nj][1] + bb.y);
            *(float2*)(C + (size_t)(r0 + 8) * N + cc) =
                make_float2(acc[mi][nj][2] + bb.x, acc[mi][nj][3] + bb.y);
        }
    }
}

// ---------------------------------------------------------------------------
// fp32 -> fp16 hi/lo split (x input)
// ---------------------------------------------------------------------------
__global__ __launch_bounds__(256) void split_h_kernel(
    const float* __restrict__ in, __half* __restrict__ hi,
    __half* __restrict__ lo, int n4)
{
    int i = blockIdx.x * 256 + threadIdx.x;
    if (i >= n4) return;
    float4 v = ((const float4*)in)[i];
    __half h[4], l[4];
    float vv[4] = { v.x, v.y, v.z, v.w };
    #pragma unroll
    for (int j = 0; j < 4; j++) {
        h[j] = __float2half_rn(vv[j]);
        l[j] = __float2half_rn(vv[j] - __half2float(h[j]));
    }
    ((uint2*)hi)[i] = *(uint2*)h;
    ((uint2*)lo)[i] = *(uint2*)l;
}

// ---------------------------------------------------------------------------
// W[K,N] fp32 -> Wt[N,K] fp16 single (transpose + round)
// ---------------------------------------------------------------------------
__global__ __launch_bounds__(256) void transpose_h_kernel(
    const float* __restrict__ W, __half* __restrict__ o16, int K, int N)
{
    __shared__ float tile[32][33];
    const int nx = blockIdx.x * 32;
    const int ky = blockIdx.y * 32;
    const int tx = threadIdx.x & 31;
    const int ty = threadIdx.x >> 5;
    #pragma unroll
    for (int i = 0; i < 4; i++)
        tile[ty + 8 * i][tx] = W[(size_t)(ky + ty + 8 * i) * N + nx + tx];
    __syncthreads();
    #pragma unroll
    for (int i = 0; i < 4; i++) {
        float v = tile[tx][ty + 8 * i];
        o16[(size_t)(nx + ty + 8 * i) * K + ky + tx] = __float2half_rn(v);
    }
}

// ---------------------------------------------------------------------------
// W[K,N] fp32 -> Wt[N,K] bf16 hi/lo (transpose + split) — for W_h
// ---------------------------------------------------------------------------
__global__ __launch_bounds__(256) void transpose_split_kernel(
    const float* __restrict__ W, bf16* __restrict__ hi,
    bf16* __restrict__ lo, int K, int N)
{
    __shared__ float tile[32][33];
    const int nx = blockIdx.x * 32;
    const int ky = blockIdx.y * 32;
    const int tx = threadIdx.x & 31;
    const int ty = threadIdx.x >> 5;
    #pragma unroll
    for (int i = 0; i < 4; i++)
        tile[ty + 8 * i][tx] = W[(size_t)(ky + ty + 8 * i) * N + nx + tx];
    __syncthreads();
    #pragma unroll
    for (int i = 0; i < 4; i++) {
        float v = tile[tx][ty + 8 * i];
        bf16 h = __float2bfloat16(v);
        bf16 l = __float2bfloat16(v - __bfloat162float(h));
        size_t o = (size_t)(nx + ty + 8 * i) * K + ky + tx;
        hi[o] = h;
        lo[o] = l;
    }
}

// ---------------------------------------------------------------------------
extern "C" void kernel_launch(void* const* d_in, const int* in_sizes, int n_in,
                              void* d_out, int out_size)
{
    const float* x     = (const float*)d_in[0];
    const float* mask  = (const float*)d_in[1];
    const float* W_qkv = (const float*)d_in[2];
    const float* W_h   = (const float*)d_in[3];
    const float* b_h   = (const float*)d_in[4];

    float* out  = (float*)d_out;
    float* attn = out + (size_t)BL * D_MODEL;

    bf16 *whhi, *whlo, *aohi, *aolo;
    __half *x16h, *x16l, *wq16, *q16h, *q16l, *e16;
    float *psum, *inv;
    cudaGetSymbolAddress((void**)&x16h, g_x16h);
    cudaGetSymbolAddress((void**)&x16l, g_x16l);
    cudaGetSymbolAddress((void**)&wq16, g_wq16);
    cudaGetSymbolAddress((void**)&whhi, g_whT_hi);
    cudaGetSymbolAddress((void**)&whlo, g_whT_lo);
    cudaGetSymbolAddress((void**)&q16h, g_q16h);
    cudaGetSymbolAddress((void**)&q16l, g_q16l);
    cudaGetSymbolAddress((void**)&aohi, g_ao_hi);
    cudaGetSymbolAddress((void**)&aolo, g_ao_lo);
    cudaGetSymbolAddress((void**)&psum, g_psum);
    cudaGetSymbolAddress((void**)&inv, g_inv);
    cudaGetSymbolAddress((void**)&e16, g_e16);

    cudaFuncSetAttribute(qkv_gemm_f16_kernel, cudaFuncAttributeMaxDynamicSharedMemorySize, SMEM_QKV);
    cudaFuncSetAttribute(mma_gemm_bias_kernel, cudaFuncAttributeMaxDynamicSharedMemorySize, SMEM_GEMM);
    cudaFuncSetAttribute(scores_mma_kernel, cudaFuncAttributeMaxDynamicSharedMemorySize, SMEM_SCORES);
    cudaFuncSetAttribute(av_mma_kernel, cudaFuncAttributeMaxDynamicSharedMemorySize, SMEM_AV);

    // 0) input conversions
    split_h_kernel<<<(BL * D_MODEL / 4 + 255) / 256, 256>>>(x, x16h, x16l, BL * D_MODEL / 4);
    transpose_h_kernel<<<dim3(D3 / 32, D_MODEL / 32), 256>>>(W_qkv, wq16, D_MODEL, D3);
    transpose_split_kernel<<<dim3(D_MODEL / 32, D_MODEL / 32), 256>>>(W_h, whhi, whlo, D_MODEL, D_MODEL);

    // 1) QKV = x @ W_qkv (fp16 2-term) -> fp16 hi/lo
    qkv_gemm_f16_kernel<<<dim3(D3 / 128, BL / 128), 256, SMEM_QKV>>>(
        x16h, x16l, wq16, q16h, q16l, BL, D3, D_MODEL);

    // 2) scores + fused exp -> fp16 scratch + psums
    scores_mma_kernel<<<dim3(SEQ / 128, SEQ / 128, BATCH * HEADS), 256, SMEM_SCORES>>>(
        mask, e16, q16h, q16l, psum);

    // 3) row-sum inverse
    rowinv_kernel<<<NROWS / 256, 256>>>(psum, inv);

    // 4) attn @ V (1-term fp16) + normalized fp32 attn write -> ao bf16 hi/lo
    av_mma_kernel<<<dim3(SEQ / 128, BATCH * HEADS), 256, SMEM_AV>>>(
        e16, attn, q16h, aohi, aolo, inv);

    // 5) output = ao @ W_h + b_h (bf16 3-term)
    mma_gemm_bias_kernel<<<dim3(D_MODEL / 128, BL / 128), 256, SMEM_GEMM>>>(
        aohi, aolo, whhi, whlo, out, b_h, BL, D_MODEL, D_MODEL);
}

// round 11
// speedup vs baseline: 2.5862x; 1.1788x over previous
#include <cuda_runtime.h>
#include <cuda_bf16.h>
#include <cuda_fp16.h>
#include <math.h>
#include <stdint.h>

#define D_MODEL 1024
#define HEADS 16
#define HD 64
#define BATCH 2
#define SEQ 2048
#define BL (BATCH * SEQ)      /* 4096 */
#define D3 (3 * D_MODEL)      /* 3072 */
#define NROWS (BATCH * HEADS * SEQ)

typedef __nv_bfloat16 bf16;

// ---------------------------------------------------------------------------
// Scratch (allocation-free: __device__ globals)
// ---------------------------------------------------------------------------
__device__ __half g_x16[(size_t)BL * D_MODEL];
__device__ __half g_wq16[(size_t)D3 * D_MODEL];
__device__ bf16  g_whT_hi[(size_t)D_MODEL * D_MODEL];
__device__ bf16  g_whT_lo[(size_t)D_MODEL * D_MODEL];
__device__ __half g_q16[(size_t)BL * D3];       // QKV fp16
__device__ bf16  g_ao_hi[(size_t)BL * D_MODEL];
__device__ bf16  g_ao_lo[(size_t)BL * D_MODEL];
__device__ float g_psum[(size_t)NROWS * 16];
__device__ float g_inv[(size_t)NROWS];
__device__ __half g_e16[(size_t)NROWS * SEQ];   // unnormalized exp, fp16

// ---------------------------------------------------------------------------
// Portable PTX helpers
// ---------------------------------------------------------------------------
__device__ __forceinline__ uint32_t smem_u32(const void* p) {
    uint32_t a;
    asm("{ .reg .u64 t; cvta.to.shared.u64 t, %1; cvt.u32.u64 %0, t; }"
        : "=r"(a) : "l"(p));
    return a;
}
__device__ __forceinline__ void cp_async16(uint32_t s, const void* g) {
    asm volatile("cp.async.cg.shared.global [%0], [%1], 16;" :: "r"(s), "l"(g));
}
#define CP_COMMIT() asm volatile("cp.async.commit_group;" ::: "memory")
#define CP_WAIT(n)  asm volatile("cp.async.wait_group %0;" :: "n"(n) : "memory")

__device__ __forceinline__ void ldm_x4(uint32_t addr, uint32_t* r) {
    asm volatile("ldmatrix.sync.aligned.m8n8.x4.shared.b16 {%0,%1,%2,%3}, [%4];"
        : "=r"(r[0]), "=r"(r[1]), "=r"(r[2]), "=r"(r[3]) : "r"(addr));
}
__device__ __forceinline__ void ldm_x4_trans(uint32_t addr, uint32_t* r) {
    asm volatile("ldmatrix.sync.aligned.m8n8.x4.trans.shared.b16 {%0,%1,%2,%3}, [%4];"
        : "=r"(r[0]), "=r"(r[1]), "=r"(r[2]), "=r"(r[3]) : "r"(addr));
}
__device__ __forceinline__ void mma_bf16(float* c, const uint32_t* a, const uint32_t* b) {
    asm volatile(
        "mma.sync.aligned.m16n8k16.row.col.f32.bf16.bf16.f32 "
        "{%0,%1,%2,%3}, {%4,%5,%6,%7}, {%8,%9}, {%0,%1,%2,%3};"
        : "+f"(c[0]), "+f"(c[1]), "+f"(c[2]), "+f"(c[3])
        : "r"(a[0]), "r"(a[1]), "r"(a[2]), "r"(a[3]), "r"(b[0]), "r"(b[1]));
}
__device__ __forceinline__ void mma_f16(float* c, const uint32_t* a, const uint32_t* b) {
    asm volatile(
        "mma.sync.aligned.m16n8k16.row.col.f32.f16.f16.f32 "
        "{%0,%1,%2,%3}, {%4,%5,%6,%7}, {%8,%9}, {%0,%1,%2,%3};"
        : "+f"(c[0]), "+f"(c[1]), "+f"(c[2]), "+f"(c[3])
        : "r"(a[0]), "r"(a[1]), "r"(a[2]), "r"(a[3]), "r"(b[0]), "r"(b[1]));
}
__device__ __forceinline__ void split_store2_bf(bf16* hi, bf16* lo, size_t idx,
                                                float a, float b) {
    bf16 ha = __float2bfloat16(a), hb = __float2bfloat16(b);
    bf16 la = __float2bfloat16(a - __bfloat162float(ha));
    bf16 lb = __float2bfloat16(b - __bfloat162float(hb));
    __nv_bfloat162 hv; hv.x = ha; hv.y = hb;
    __nv_bfloat162 lv; lv.x = la; lv.y = lb;
    *(__nv_bfloat162*)(hi + idx) = hv;
    *(__nv_bfloat162*)(lo + idx) = lv;
}
__device__ __forceinline__ float fexp(float x) {
    float t = x * 1.4426950408889634f;
    t = fmaxf(t, -126.0f);
    float n = rintf(t);
    float f = t - n;
    float p = 1.5403530e-4f;
    p = fmaf(p, f, 1.3333558e-3f);
    p = fmaf(p, f, 9.6181291e-3f);
    p = fmaf(p, f, 5.5504109e-2f);
    p = fmaf(p, f, 2.4022651e-1f);
    p = fmaf(p, f, 6.9314718e-1f);
    p = fmaf(p, f, 1.0f);
    return p * __int_as_float(((int)n + 127) << 23);
}

// ---------------------------------------------------------------------------
// fp16 1-term QKV GEMM: C = A @ B^T, fp16 in/out, fp32 accum.
// 128x128 tile, BK=32, 256 thr, double buffer, 2 smem tiles/stage.
// ---------------------------------------------------------------------------
#define BK 32
#define GP 40
#define GT_ELEMS (128 * GP)
#define QS_ELEMS (2 * GT_ELEMS)
#define SMEM_QKV (2 * QS_ELEMS * 2)      /* 40960 B */

__global__ __launch_bounds__(256, 2) void qkv_gemm_f16_kernel(
    const __half* __restrict__ A, const __half* __restrict__ B,
    __half* __restrict__ C, int M, int N, int K)
{
    extern __shared__ __half smq[];
    const uint32_t sbase = smem_u32(smq);
    const int t = threadIdx.x;
    const int warp = t >> 5, lane = t & 31;
    const int bm = blockIdx.y * 128;
    const int bn = blockIdx.x * 128;
    const int wm = (warp >> 1) * 32;
    const int wn = (warp & 1) * 64;

    const __half* srcs[2] = { A, B };

    auto load_stage = [&](int buf, int k0) {
        uint32_t sdst = sbase + (uint32_t)buf * QS_ELEMS * 2;
        #pragma unroll
        for (int m = 0; m < 2; m++) {
            const int rbase = (m == 0) ? bm : bn;
            const __half* S = srcs[m] + (size_t)rbase * K + k0;
            uint32_t td = sdst + (uint32_t)m * GT_ELEMS * 2;
            #pragma unroll
            for (int i = 0; i < 2; i++) {
                int id = t + i * 256;
                int row = id >> 2, c = id & 3;
                cp_async16(td + (uint32_t)(row * GP + c * 8) * 2,
                           S + (size_t)row * K + c * 8);
            }
        }
        CP_COMMIT();
    };

    float acc[2][8][4];
    #pragma unroll
    for (int mi = 0; mi < 2; mi++)
        #pragma unroll
        for (int nj = 0; nj < 8; nj++)
            #pragma unroll
            for (int e = 0; e < 4; e++) acc[mi][nj][e] = 0.0f;

    const int nch = K >> 5;
    load_stage(0, 0);
    load_stage(1, BK);

    const int a_r = (lane & 7) + ((lane >> 3) & 1) * 8;
    const int a_c = (lane >> 4) * 8;
    const int b_r = (lane & 7) + (lane >> 4) * 8;
    const int b_c = ((lane >> 3) & 1) * 8;

    for (int c = 0; c < nch; c++) {
        if (c < nch - 1) { CP_WAIT(1); } else { CP_WAIT(0); }
        __syncthreads();

        const uint32_t stg = sbase + (uint32_t)(c & 1) * QS_ELEMS * 2;
        const uint32_t tA = stg;
        const uint32_t tB = stg + GT_ELEMS * 2;

        #pragma unroll
        for (int ks = 0; ks < BK; ks += 16) {
            uint32_t ah[2][4], bh[16];
            #pragma unroll
            for (int mi = 0; mi < 2; mi++) {
                uint32_t off = (uint32_t)((wm + mi * 16 + a_r) * GP + ks + a_c) * 2;
                ldm_x4(tA + off, ah[mi]);
            }
            #pragma unroll
            for (int nj2 = 0; nj2 < 4; nj2++) {
                uint32_t off = (uint32_t)((wn + nj2 * 16 + b_r) * GP + ks + b_c) * 2;
                ldm_x4(tB + off, bh + nj2 * 4);
            }
            #pragma unroll
            for (int mi = 0; mi < 2; mi++)
                #pragma unroll
                for (int nj = 0; nj < 8; nj++)
                    mma_f16(acc[mi][nj], ah[mi], bh + nj * 2);
        }
        __syncthreads();
        if (c + 2 < nch) load_stage(c & 1, (c + 2) * BK);
    }

    const int group = lane >> 2, tid4 = lane & 3;
    #pragma unroll
    for (int mi = 0; mi < 2; mi++) {
        int r0 = bm + wm + mi * 16 + group;
        #pragma unroll
        for (int nj = 0; nj < 8; nj++) {
            int cc = bn + wn + nj * 8 + tid4 * 2;
            __half2 v0; v0.x = __float2half_rn(acc[mi][nj][0]);
            v0.y = __float2half_rn(acc[mi][nj][1]);
            __half2 v1; v1.x = __float2half_rn(acc[mi][nj][2]);
            v1.y = __float2half_rn(acc[mi][nj][3]);
            *(__half2*)(C + (size_t)r0 * N + cc) = v0;
            *(__half2*)(C + (size_t)(r0 + 8) * N + cc) = v1;
        }
    }
}

// ---------------------------------------------------------------------------
// Scores via fp16 HMMA 1-term (Q.K^T); fused mask+scale+exp; fp16 e out.
// SMEM: Q,K [128][72] half.
// ---------------------------------------------------------------------------
#define SP 72
#define ST_ELEMS (128 * SP)
#define SMEM_SCORES (2 * ST_ELEMS * 2)

__global__ __launch_bounds__(256) void scores_mma_kernel(
    const float* __restrict__ mask, __half* __restrict__ e16,
    const __half* __restrict__ q16, float* __restrict__ psum)
{
    extern __shared__ __half smh[];
    const uint32_t sbase = smem_u32(smh);
    const int t = threadIdx.x;
    const int warp = t >> 5, lane = t & 31;
    const int bh = blockIdx.z;
    const int b = bh / HEADS, h = bh % HEADS;
    const int bm = blockIdx.y * 128;
    const int bn = blockIdx.x * 128;
    const int wm = (warp >> 1) * 32;
    const int wn = (warp & 1) * 64;

    const __half* bases[2] = {
        q16 + ((size_t)(b * SEQ + bm)) * D3 + h * HD,
        q16 + ((size_t)(b * SEQ + bn)) * D3 + D_MODEL + h * HD };
    #pragma unroll
    for (int m = 0; m < 2; m++) {
        uint32_t td = sbase + (uint32_t)m * ST_ELEMS * 2;
        #pragma unroll
        for (int i = 0; i < 4; i++) {
            int id = t + i * 256;
            int r = id >> 3, c = id & 7;
            cp_async16(td + (uint32_t)(r * SP + c * 8) * 2,
                       bases[m] + (size_t)r * D3 + c * 8);
        }
    }
    CP_COMMIT();

    float acc[2][8][4];
    #pragma unroll
    for (int mi = 0; mi < 2; mi++)
        #pragma unroll
        for (int nj = 0; nj < 8; nj++)
            #pragma unroll
            for (int e = 0; e < 4; e++) acc[mi][nj][e] = 0.0f;

    const int a_r = (lane & 7) + ((lane >> 3) & 1) * 8;
    const int a_c = (lane >> 4) * 8;
    const int b_r = (lane & 7) + (lane >> 4) * 8;
    const int b_c = ((lane >> 3) & 1) * 8;

    const uint32_t tQ = sbase;
    const uint32_t tK = sbase + ST_ELEMS * 2;

    CP_WAIT(0);
    __syncthreads();

    #pragma unroll
    for (int ks = 0; ks < 4; ks++) {
        uint32_t ah[2][4], bhf[16];
        #pragma unroll
        for (int mi = 0; mi < 2; mi++) {
            uint32_t off = (uint32_t)((wm + mi * 16 + a_r) * SP + ks * 16 + a_c) * 2;
            ldm_x4(tQ + off, ah[mi]);
        }
        #pragma unroll
        for (int nj2 = 0; nj2 < 4; nj2++) {
            uint32_t off = (uint32_t)((wn + nj2 * 16 + b_r) * SP + ks * 16 + b_c) * 2;
            ldm_x4(tK + off, bhf + nj2 * 4);
        }
        #pragma unroll
        for (int mi = 0; mi < 2; mi++)
            #pragma unroll
            for (int nj = 0; nj < 8; nj++)
                mma_f16(acc[mi][nj], ah[mi], bhf + nj * 2);
    }

    const int group = lane >> 2, tid4 = lane & 3;
    float mq[4];
    #pragma unroll
    for (int mi = 0; mi < 2; mi++) {
        mq[mi * 2 + 0] = mask[b * SEQ + bm + wm + mi * 16 + group];
        mq[mi * 2 + 1] = mask[b * SEQ + bm + wm + mi * 16 + group + 8];
    }
    __half* out = e16 + (size_t)bh * SEQ * SEQ;
    float srow[2][2];
    srow[0][0] = srow[0][1] = srow[1][0] = srow[1][1] = 0.0f;
    #pragma unroll
    for (int nj = 0; nj < 8; nj++) {
        int cc = bn + wn + nj * 8 + tid4 * 2;
        float2 mk = *(const float2*)(mask + b * SEQ + cc);
        #pragma unroll
        for (int mi = 0; mi < 2; mi++) {
            int r0 = bm + wm + mi * 16 + group;
            float v0 = acc[mi][nj][0], v1 = acc[mi][nj][1];
            float v2 = acc[mi][nj][2], v3 = acc[mi][nj][3];
            if (mq[mi * 2 + 0] * mk.x == 0.0f) v0 = -100000.0f;
            if (mq[mi * 2 + 0] * mk.y == 0.0f) v1 = -100000.0f;
            if (mq[mi * 2 + 1] * mk.x == 0.0f) v2 = -100000.0f;
            if (mq[mi * 2 + 1] * mk.y == 0.0f) v3 = -100000.0f;
            __half h0 = __float2half_rn(fmaxf(fexp(v0 * 0.03125f), 1e-7f));
            __half h1 = __float2half_rn(fmaxf(fexp(v1 * 0.03125f), 1e-7f));
            __half h2 = __float2half_rn(fmaxf(fexp(v2 * 0.03125f), 1e-7f));
            __half h3 = __float2half_rn(fmaxf(fexp(v3 * 0.03125f), 1e-7f));
            __half2 p01; p01.x = h0; p01.y = h1;
            __half2 p23; p23.x = h2; p23.y = h3;
            *(__half2*)(out + (size_t)r0 * SEQ + cc) = p01;
            *(__half2*)(out + (size_t)(r0 + 8) * SEQ + cc) = p23;
            srow[mi][0] += __half2float(h0) + __half2float(h1);
            srow[mi][1] += __half2float(h2) + __half2float(h3);
        }
    }
    #pragma unroll
    for (int mi = 0; mi < 2; mi++) {
        #pragma unroll
        for (int s = 0; s < 2; s++) {
            srow[mi][s] += __shfl_xor_sync(0xffffffffu, srow[mi][s], 1);
            srow[mi][s] += __shfl_xor_sync(0xffffffffu, srow[mi][s], 2);
        }
    }
    __syncthreads();
    float* rs = (float*)smh;
    if (tid4 == 0) {
        #pragma unroll
        for (int mi = 0; mi < 2; mi++) {
            rs[(wm + mi * 16 + group) * 2 + (warp & 1)] = srow[mi][0];
            rs[(wm + mi * 16 + group + 8) * 2 + (warp & 1)] = srow[mi][1];
        }
    }
    __syncthreads();
    if (t < 128)
        psum[((size_t)bh * SEQ + bm + t) * 16 + blockIdx.x] = rs[t * 2] + rs[t * 2 + 1];
}

// ---------------------------------------------------------------------------
__global__ __launch_bounds__(256) void rowinv_kernel(
    const float* __restrict__ psum, float* __restrict__ inv)
{
    int r = blockIdx.x * 256 + threadIdx.x;
    if (r >= NROWS) return;
    float4 a = *(const float4*)(psum + (size_t)r * 16);
    float4 b2 = *(const float4*)(psum + (size_t)r * 16 + 4);
    float4 c = *(const float4*)(psum + (size_t)r * 16 + 8);
    float4 d = *(const float4*)(psum + (size_t)r * 16 + 12);
    float s = a.x + a.y + a.z + a.w + b2.x + b2.y + b2.z + b2.w
            + c.x + c.y + c.z + c.w + d.x + d.y + d.z + d.w;
    inv[r] = 1.0f / s;
}

// ---------------------------------------------------------------------------
// av: reads fp16 e-scratch (1-term MMA with V), writes normalized fp32 attn,
// split-stores ao bf16 hi/lo (scaled by inv).
// ---------------------------------------------------------------------------
#define EP 72
#define AVE(i) ((i) * 18432)
#define AVV(i) (36864 + (i) * 9216)
#define AVINV  55296
#define SMEM_AV (55296 + 512)

__global__ __launch_bounds__(256) void av_mma_kernel(
    const __half* __restrict__ e16, float* __restrict__ attn,
    const __half* __restrict__ q16,
    bf16* __restrict__ aohi, bf16* __restrict__ aolo,
    const float* __restrict__ inv)
{
    extern __shared__ char smc[];
    const uint32_t sbase = smem_u32(smc);
    const int t = threadIdx.x;
    const int warp = t >> 5, lane = t & 31;
    const int bh = blockIdx.y;
    const int b = bh / HEADS, h = bh % HEADS;
    const int bm = blockIdx.x * 128;
    const int wm = warp * 16;

    const __half* Ebase = e16 + (size_t)bh * SEQ * SEQ + (size_t)bm * SEQ;
    float* Abase = attn + (size_t)bh * SEQ * SEQ + (size_t)bm * SEQ;
    const __half* V = q16 + (size_t)b * SEQ * D3 + 2 * D_MODEL + h * HD;

    float* inv_s = (float*)(smc + AVINV);
    if (t < 128) inv_s[t] = inv[(size_t)bh * SEQ + bm + t];
    __syncthreads();

    auto load_chunk = [&](int c) {
        const int k0 = c * 64;
        const uint32_t buf = c & 1;
        #pragma unroll
        for (int i = 0; i < 4; i++) {
            int id = t + i * 256;
            int r = id >> 3, cs = id & 7;
            cp_async16(sbase + AVE(buf) + (uint32_t)(r * EP + cs * 8) * 2,
                       Ebase + (size_t)r * SEQ + k0 + cs * 8);
        }
        #pragma unroll
        for (int i = 0; i < 2; i++) {
            int id = t + i * 256;
            int r = id >> 3, cs = id & 7;
            cp_async16(sbase + AVV(buf) + (uint32_t)(r * EP + cs * 8) * 2,
                       V + (size_t)(k0 + r) * D3 + cs * 8);
        }
        CP_COMMIT();
    };

    float acc[8][4];
    #pragma unroll
    for (int nj = 0; nj < 8; nj++)
        #pragma unroll
        for (int e = 0; e < 4; e++) acc[nj][e] = 0.0f;

    load_chunk(0);

    const int a_r = (lane & 7) + ((lane >> 3) & 1) * 8;
    const int a_c = (lane >> 4) * 8;
    const int tb_r = lane & 15;
    const int tb_c = (lane >> 4) * 8;

    for (int c = 0; c < SEQ / 64; c++) {
        CP_WAIT(0);
        __syncthreads();
        const int k0 = c * 64;
        const uint32_t buf = c & 1;
        if (c + 1 < SEQ / 64) load_chunk(c + 1);

        const __half* Es = (const __half*)(smc + AVE(buf));
        #pragma unroll
        for (int i = 0; i < 8; i++) {
            int id = t + i * 256;
            int r = id >> 4, c4 = id & 15;
            uint2 raw = *(const uint2*)(Es + r * EP + c4 * 4);
            __half2 p01 = *(__half2*)&raw.x;
            __half2 p23 = *(__half2*)&raw.y;
            float s = inv_s[r];
            float4 o;
            o.x = __half2float(p01.x) * s;
            o.y = __half2float(p01.y) * s;
            o.z = __half2float(p23.x) * s;
            o.w = __half2float(p23.y) * s;
            *(float4*)(Abase + (size_t)r * SEQ + k0 + c4 * 4) = o;
        }

        const uint32_t tA = sbase + AVE(buf);
        const uint32_t tV = sbase + AVV(buf);
        #pragma unroll
        for (int ks = 0; ks < 4; ks++) {
            uint32_t ah[4], bhf[16];
            uint32_t aoff = (uint32_t)((wm + a_r) * EP + ks * 16 + a_c) * 2;
            ldm_x4(tA + aoff, ah);
            #pragma unroll
            for (int nj2 = 0; nj2 < 4; nj2++) {
                uint32_t boff =
                    (uint32_t)((ks * 16 + tb_r) * EP + nj2 * 16 + tb_c) * 2;
                ldm_x4_trans(tV + boff, bhf + nj2 * 4);
            }
            #pragma unroll
            for (int nj = 0; nj < 8; nj++)
                mma_f16(acc[nj], ah, bhf + nj * 2);
        }
    }

    const int group = lane >> 2, tid4 = lane & 3;
    const float ia = inv_s[wm + group];
    const float ib = inv_s[wm + group + 8];
    #pragma unroll
    for (int nj = 0; nj < 8; nj++) {
        int cc = h * HD + nj * 8 + tid4 * 2;
        size_t r0 = (size_t)(b * SEQ + bm + wm + group) * D_MODEL + cc;
        size_t r1 = r0 + (size_t)8 * D_MODEL;
        split_store2_bf(aohi, aolo, r0, acc[nj][0] * ia, acc[nj][1] * ia);
        split_store2_bf(aohi, aolo, r1, acc[nj][2] * ib, acc[nj][3] * ib);
    }
}

// ---------------------------------------------------------------------------
// Out-proj GEMM, bf16 3-term, fp32 + bias epilogue (proven).
// ---------------------------------------------------------------------------
#define GS_ELEMS (4 * GT_ELEMS)
#define SMEM_GEMM (2 * GS_ELEMS * 2)

__global__ __launch_bounds__(256, 2) void mma_gemm_bias_kernel(
    const bf16* __restrict__ Ahi, const bf16* __restrict__ Alo,
    const bf16* __restrict__ Bhi, const bf16* __restrict__ Blo,
    float* __restrict__ C, const float* __restrict__ bias,
    int M, int N, int K)
{
    extern __shared__ bf16 sm[];
    const uint32_t sbase = smem_u32(sm);
    const int t = threadIdx.x;
    const int warp = t >> 5, lane = t & 31;
    const int bm = blockIdx.y * 128;
    const int bn = blockIdx.x * 128;
    const int wm = (warp >> 1) * 32;
    const int wn = (warp & 1) * 64;

    const bf16* srcs[4] = { Ahi, Alo, Bhi, Blo };

    auto load_stage = [&](int buf, int k0) {
        uint32_t sdst = sbase + (uint32_t)buf * GS_ELEMS * 2;
        #pragma unroll
        for (int m = 0; m < 4; m++) {
            const int rbase = (m < 2) ? bm : bn;
            const bf16* S = srcs[m] + (size_t)rbase * K + k0;
            uint32_t td = sdst + (uint32_t)m * GT_ELEMS * 2;
            #pragma unroll
            for (int i = 0; i < 2; i++) {
                int id = t + i * 256;
                int row = id >> 2, c = id & 3;
                cp_async16(td + (uint32_t)(row * GP + c * 8) * 2,
                           S + (size_t)row * K + c * 8);
            }
        }
        CP_COMMIT();
    };

    float acc[2][8][4];
    #pragma unroll
    for (int mi = 0; mi < 2; mi++)
        #pragma unroll
        for (int nj = 0; nj < 8; nj++)
            #pragma unroll
            for (int e = 0; e < 4; e++) acc[mi][nj][e] = 0.0f;

    const int nch = K >> 5;
    load_stage(0, 0);
    load_stage(1, BK);

    const int a_r = (lane & 7) + ((lane >> 3) & 1) * 8;
    const int a_c = (lane >> 4) * 8;
    const int b_r = (lane & 7) + (lane >> 4) * 8;
    const int b_c = ((lane >> 3) & 1) * 8;

    for (int c = 0; c < nch; c++) {
        if (c < nch - 1) { CP_WAIT(1); } else { CP_WAIT(0); }
        __syncthreads();

        const uint32_t stg = sbase + (uint32_t)(c & 1) * GS_ELEMS * 2;
        const uint32_t tAhi = stg;
        const uint32_t tAlo = stg + GT_ELEMS * 2;
        const uint32_t tBhi = stg + 2 * GT_ELEMS * 2;
        const uint32_t tBlo = stg + 3 * GT_ELEMS * 2;

        #pragma unroll
        for (int ks = 0; ks < BK; ks += 16) {
            uint32_t ah[2][4], al[2][4], bh[16], bl[16];
            #pragma unroll
            for (int mi = 0; mi < 2; mi++) {
                uint32_t off = (uint32_t)((wm + mi * 16 + a_r) * GP + ks + a_c) * 2;
                ldm_x4(tAhi + off, ah[mi]);
                ldm_x4(tAlo + off, al[mi]);
            }
            #pragma unroll
            for (int nj2 = 0; nj2 < 4; nj2++) {
                uint32_t off = (uint32_t)((wn + nj2 * 16 + b_r) * GP + ks + b_c) * 2;
                ldm_x4(tBhi + off, bh + nj2 * 4);
                ldm_x4(tBlo + off, bl + nj2 * 4);
            }
            #pragma unroll
            for (int mi = 0; mi < 2; mi++)
                #pragma unroll
                for (int nj = 0; nj < 8; nj++)
                    mma_bf16(acc[mi][nj], ah[mi], bh + nj * 2);
            #pragma unroll
            for (int mi = 0; mi < 2; mi++)
                #pragma unroll
                for (int nj = 0; nj < 8; nj++)
                    mma_bf16(acc[mi][nj], ah[mi], bl + nj * 2);
            #pragma unroll
            for (int mi = 0; mi < 2; mi++)
                #pragma unroll
                for (int nj = 0; nj < 8; nj++)
                    mma_bf16(acc[mi][nj], al[mi], bh + nj * 2);
        }
        __syncthreads();
        if (c + 2 < nch) load_stage(c & 1, (c + 2) * BK);
    }

    const int group = lane >> 2, tid4 = lane & 3;
    #pragma unroll
    for (int mi = 0; mi < 2; mi++) {
        int r0 = bm + wm + mi * 16 + group;
        #pragma unroll
        for (int nj = 0; nj < 8; nj++) {
            int cc = bn + wn + nj * 8 + tid4 * 2;
            float2 bb = *(const float2*)(bias + cc);
            *(float2*)(C + (size_t)r0 * N + cc) =
                make_float2(acc[mi][nj][0] + bb.x, acc[mi][nj][1] + bb.y);
            *(float2*)(C + (size_t)(r0 + 8) * N + cc) =
                make_float2(acc[mi][nj][2] + bb.x, acc[mi][nj][3] + bb.y);
        }
    }
}

// ---------------------------------------------------------------------------
// fp32 -> fp16 round (x input)
// ---------------------------------------------------------------------------
__global__ __launch_bounds__(256) void round_h_kernel(
    const float* __restrict__ in, __half* __restrict__ o, int n4)
{
    int i = blockIdx.x * 256 + threadIdx.x;
    if (i >= n4) return;
    float4 v = ((const float4*)in)[i];
    __half h[4];
    h[0] = __float2half_rn(v.x);
    h[1] = __float2half_rn(v.y);
    h[2] = __float2half_rn(v.z);
    h[3] = __float2half_rn(v.w);
    ((uint2*)o)[i] = *(uint2*)h;
}

// ---------------------------------------------------------------------------
// W[K,N] fp32 -> Wt[N,K] fp16 single (transpose + round)
// ---------------------------------------------------------------------------
__global__ __launch_bounds__(256) void transpose_h_kernel(
    const float* __restrict__ W, __half* __restrict__ o16, int K, int N)
{
    __shared__ float tile[32][33];
    const int nx = blockIdx.x * 32;
    const int ky = blockIdx.y * 32;
    const int tx = threadIdx.x & 31;
    const int ty = threadIdx.x >> 5;
    #pragma unroll
    for (int i = 0; i < 4; i++)
        tile[ty + 8 * i][tx] = W[(size_t)(ky + ty + 8 * i) * N + nx + tx];
    __syncthreads();
    #pragma unroll
    for (int i = 0; i < 4; i++) {
        float v = tile[tx][ty + 8 * i];
        o16[(size_t)(nx + ty + 8 * i) * K + ky + tx] = __float2half_rn(v);
    }
}

// ---------------------------------------------------------------------------
// W[K,N] fp32 -> Wt[N,K] bf16 hi/lo (transpose + split) — for W_h
// ---------------------------------------------------------------------------
__global__ __launch_bounds__(256) void transpose_split_kernel(
    const float* __restrict__ W, bf16* __restrict__ hi,
    bf16* __restrict__ lo, int K, int N)
{
    __shared__ float tile[32][33];
    const int nx = blockIdx.x * 32;
    const int ky = blockIdx.y * 32;
    const int tx = threadIdx.x & 31;
    const int ty = threadIdx.x >> 5;
    #pragma unroll
    for (int i = 0; i < 4; i++)
        tile[ty + 8 * i][tx] = W[(size_t)(ky + ty + 8 * i) * N + nx + tx];
    __syncthreads();
    #pragma unroll
    for (int i = 0; i < 4; i++) {
        float v = tile[tx][ty + 8 * i];
        bf16 h = __float2bfloat16(v);
        bf16 l = __float2bfloat16(v - __bfloat162float(h));
        size_t o = (size_t)(nx + ty + 8 * i) * K + ky + tx;
        hi[o] = h;
        lo[o] = l;
    }
}

// ---------------------------------------------------------------------------
extern "C" void kernel_launch(void* const* d_in, const int* in_sizes, int n_in,
                              void* d_out, int out_size)
{
    const float* x     = (const float*)d_in[0];
    const float* mask  = (const float*)d_in[1];
    const float* W_qkv = (const float*)d_in[2];
    const float* W_h   = (const float*)d_in[3];
    const float* b_h   = (const float*)d_in[4];

    float* out  = (float*)d_out;
    float* attn = out + (size_t)BL * D_MODEL;

    bf16 *whhi, *whlo, *aohi, *aolo;
    __half *x16, *wq16, *q16, *e16;
    float *psum, *inv;
    cudaGetSymbolAddress((void**)&x16, g_x16);
    cudaGetSymbolAddress((void**)&wq16, g_wq16);
    cudaGetSymbolAddress((void**)&whhi, g_whT_hi);
    cudaGetSymbolAddress((void**)&whlo, g_whT_lo);
    cudaGetSymbolAddress((void**)&q16, g_q16);
    cudaGetSymbolAddress((void**)&aohi, g_ao_hi);
    cudaGetSymbolAddress((void**)&aolo, g_ao_lo);
    cudaGetSymbolAddress((void**)&psum, g_psum);
    cudaGetSymbolAddress((void**)&inv, g_inv);
    cudaGetSymbolAddress((void**)&e16, g_e16);

    cudaFuncSetAttribute(qkv_gemm_f16_kernel, cudaFuncAttributeMaxDynamicSharedMemorySize, SMEM_QKV);
    cudaFuncSetAttribute(mma_gemm_bias_kernel, cudaFuncAttributeMaxDynamicSharedMemorySize, SMEM_GEMM);
    cudaFuncSetAttribute(scores_mma_kernel, cudaFuncAttributeMaxDynamicSharedMemorySize, SMEM_SCORES);
    cudaFuncSetAttribute(av_mma_kernel, cudaFuncAttributeMaxDynamicSharedMemorySize, SMEM_AV);

    // 0) input conversions
    round_h_kernel<<<(BL * D_MODEL / 4 + 255) / 256, 256>>>(x, x16, BL * D_MODEL / 4);
    transpose_h_kernel<<<dim3(D3 / 32, D_MODEL / 32), 256>>>(W_qkv, wq16, D_MODEL, D3);
    transpose_split_kernel<<<dim3(D_MODEL / 32, D_MODEL / 32), 256>>>(W_h, whhi, whlo, D_MODEL, D_MODEL);

    // 1) QKV = x @ W_qkv (fp16 1-term) -> fp16
    qkv_gemm_f16_kernel<<<dim3(D3 / 128, BL / 128), 256, SMEM_QKV>>>(
        x16, wq16, q16, BL, D3, D_MODEL);

    // 2) scores (fp16 1-term) + fused exp -> fp16 scratch + psums
    scores_mma_kernel<<<dim3(SEQ / 128, SEQ / 128, BATCH * HEADS), 256, SMEM_SCORES>>>(
        mask, e16, q16, psum);

    // 3) row-sum inverse
    rowinv_kernel<<<NROWS / 256, 256>>>(psum, inv);

    // 4) attn @ V (1-term fp16) + normalized fp32 attn write -> ao bf16 hi/lo
    av_mma_kernel<<<dim3(SEQ / 128, BATCH * HEADS), 256, SMEM_AV>>>(
        e16, attn, q16, aohi, aolo, inv);

    // 5) output = ao @ W_h + b_h (bf16 3-term)
    mma_gemm_bias_kernel<<<dim3(D_MODEL / 128, BL / 128), 256, SMEM_GEMM>>>(
        aohi, aolo, whhi, whlo, out, b_h, BL, D_MODEL, D_MODEL);
}

// round 12
// speedup vs baseline: 2.7191x; 1.0514x over previous
#include <cuda_runtime.h>
#include <cuda_bf16.h>
#include <cuda_fp16.h>
#include <math.h>
#include <stdint.h>

#define D_MODEL 1024
#define HEADS 16
#define HD 64
#define BATCH 2
#define SEQ 2048
#define BL (BATCH * SEQ)      /* 4096 */
#define D3 (3 * D_MODEL)      /* 3072 */
#define NROWS (BATCH * HEADS * SEQ)

typedef __nv_bfloat16 bf16;

// ---------------------------------------------------------------------------
// Scratch (allocation-free: __device__ globals)
// ---------------------------------------------------------------------------
__device__ __half g_x16[(size_t)BL * D_MODEL];
__device__ __half g_wq16[(size_t)D3 * D_MODEL];
__device__ __half g_wh16[(size_t)D_MODEL * D_MODEL];
__device__ __half g_q16[(size_t)BL * D3];        // QKV fp16
__device__ __half g_ao16h[(size_t)BL * D_MODEL]; // attn_out fp16 hi
__device__ __half g_ao16l[(size_t)BL * D_MODEL]; // attn_out fp16 lo
__device__ float g_psum[(size_t)NROWS * 16];
__device__ float g_inv[(size_t)NROWS];
__device__ __half g_e16[(size_t)NROWS * SEQ];    // unnormalized exp, fp16

// ---------------------------------------------------------------------------
// Portable PTX helpers
// ---------------------------------------------------------------------------
__device__ __forceinline__ uint32_t smem_u32(const void* p) {
    uint32_t a;
    asm("{ .reg .u64 t; cvta.to.shared.u64 t, %1; cvt.u32.u64 %0, t; }"
        : "=r"(a) : "l"(p));
    return a;
}
__device__ __forceinline__ void cp_async16(uint32_t s, const void* g) {
    asm volatile("cp.async.cg.shared.global [%0], [%1], 16;" :: "r"(s), "l"(g));
}
#define CP_COMMIT() asm volatile("cp.async.commit_group;" ::: "memory")
#define CP_WAIT(n)  asm volatile("cp.async.wait_group %0;" :: "n"(n) : "memory")

__device__ __forceinline__ void ldm_x4(uint32_t addr, uint32_t* r) {
    asm volatile("ldmatrix.sync.aligned.m8n8.x4.shared.b16 {%0,%1,%2,%3}, [%4];"
        : "=r"(r[0]), "=r"(r[1]), "=r"(r[2]), "=r"(r[3]) : "r"(addr));
}
__device__ __forceinline__ void ldm_x4_trans(uint32_t addr, uint32_t* r) {
    asm volatile("ldmatrix.sync.aligned.m8n8.x4.trans.shared.b16 {%0,%1,%2,%3}, [%4];"
        : "=r"(r[0]), "=r"(r[1]), "=r"(r[2]), "=r"(r[3]) : "r"(addr));
}
__device__ __forceinline__ void mma_f16(float* c, const uint32_t* a, const uint32_t* b) {
    asm volatile(
        "mma.sync.aligned.m16n8k16.row.col.f32.f16.f16.f32 "
        "{%0,%1,%2,%3}, {%4,%5,%6,%7}, {%8,%9}, {%0,%1,%2,%3};"
        : "+f"(c[0]), "+f"(c[1]), "+f"(c[2]), "+f"(c[3])
        : "r"(a[0]), "r"(a[1]), "r"(a[2]), "r"(a[3]), "r"(b[0]), "r"(b[1]));
}
__device__ __forceinline__ void split_store2_h(__half* hi, __half* lo, size_t idx,
                                               float a, float b) {
    __half ha = __float2half_rn(a), hb = __float2half_rn(b);
    __half la = __float2half_rn(a - __half2float(ha));
    __half lb = __float2half_rn(b - __half2float(hb));
    __half2 hv; hv.x = ha; hv.y = hb;
    __half2 lv; lv.x = la; lv.y = lb;
    *(__half2*)(hi + idx) = hv;
    *(__half2*)(lo + idx) = lv;
}
__device__ __forceinline__ float fexp(float x) {
    float t = x * 1.4426950408889634f;
    t = fmaxf(t, -126.0f);
    float n = rintf(t);
    float f = t - n;
    float p = 1.5403530e-4f;
    p = fmaf(p, f, 1.3333558e-3f);
    p = fmaf(p, f, 9.6181291e-3f);
    p = fmaf(p, f, 5.5504109e-2f);
    p = fmaf(p, f, 2.4022651e-1f);
    p = fmaf(p, f, 6.9314718e-1f);
    p = fmaf(p, f, 1.0f);
    return p * __int_as_float(((int)n + 127) << 23);
}

// ---------------------------------------------------------------------------
// fp16 1-term QKV GEMM (R11-proven): C = A @ B^T, fp16 out.
// ---------------------------------------------------------------------------
#define BK 32
#define GP 40
#define GT_ELEMS (128 * GP)
#define QS_ELEMS (2 * GT_ELEMS)
#define SMEM_QKV (2 * QS_ELEMS * 2)

__global__ __launch_bounds__(256, 2) void qkv_gemm_f16_kernel(
    const __half* __restrict__ A, const __half* __restrict__ B,
    __half* __restrict__ C, int M, int N, int K)
{
    extern __shared__ __half smq[];
    const uint32_t sbase = smem_u32(smq);
    const int t = threadIdx.x;
    const int warp = t >> 5, lane = t & 31;
    const int bm = blockIdx.y * 128;
    const int bn = blockIdx.x * 128;
    const int wm = (warp >> 1) * 32;
    const int wn = (warp & 1) * 64;

    const __half* srcs[2] = { A, B };

    auto load_stage = [&](int buf, int k0) {
        uint32_t sdst = sbase + (uint32_t)buf * QS_ELEMS * 2;
        #pragma unroll
        for (int m = 0; m < 2; m++) {
            const int rbase = (m == 0) ? bm : bn;
            const __half* S = srcs[m] + (size_t)rbase * K + k0;
            uint32_t td = sdst + (uint32_t)m * GT_ELEMS * 2;
            #pragma unroll
            for (int i = 0; i < 2; i++) {
                int id = t + i * 256;
                int row = id >> 2, c = id & 3;
                cp_async16(td + (uint32_t)(row * GP + c * 8) * 2,
                           S + (size_t)row * K + c * 8);
            }
        }
        CP_COMMIT();
    };

    float acc[2][8][4];
    #pragma unroll
    for (int mi = 0; mi < 2; mi++)
        #pragma unroll
        for (int nj = 0; nj < 8; nj++)
            #pragma unroll
            for (int e = 0; e < 4; e++) acc[mi][nj][e] = 0.0f;

    const int nch = K >> 5;
    load_stage(0, 0);
    load_stage(1, BK);

    const int a_r = (lane & 7) + ((lane >> 3) & 1) * 8;
    const int a_c = (lane >> 4) * 8;
    const int b_r = (lane & 7) + (lane >> 4) * 8;
    const int b_c = ((lane >> 3) & 1) * 8;

    for (int c = 0; c < nch; c++) {
        if (c < nch - 1) { CP_WAIT(1); } else { CP_WAIT(0); }
        __syncthreads();

        const uint32_t stg = sbase + (uint32_t)(c & 1) * QS_ELEMS * 2;
        const uint32_t tA = stg;
        const uint32_t tB = stg + GT_ELEMS * 2;

        #pragma unroll
        for (int ks = 0; ks < BK; ks += 16) {
            uint32_t ah[2][4], bh[16];
            #pragma unroll
            for (int mi = 0; mi < 2; mi++) {
                uint32_t off = (uint32_t)((wm + mi * 16 + a_r) * GP + ks + a_c) * 2;
                ldm_x4(tA + off, ah[mi]);
            }
            #pragma unroll
            for (int nj2 = 0; nj2 < 4; nj2++) {
                uint32_t off = (uint32_t)((wn + nj2 * 16 + b_r) * GP + ks + b_c) * 2;
                ldm_x4(tB + off, bh + nj2 * 4);
            }
            #pragma unroll
            for (int mi = 0; mi < 2; mi++)
                #pragma unroll
                for (int nj = 0; nj < 8; nj++)
                    mma_f16(acc[mi][nj], ah[mi], bh + nj * 2);
        }
        __syncthreads();
        if (c + 2 < nch) load_stage(c & 1, (c + 2) * BK);
    }

    const int group = lane >> 2, tid4 = lane & 3;
    #pragma unroll
    for (int mi = 0; mi < 2; mi++) {
        int r0 = bm + wm + mi * 16 + group;
        #pragma unroll
        for (int nj = 0; nj < 8; nj++) {
            int cc = bn + wn + nj * 8 + tid4 * 2;
            __half2 v0; v0.x = __float2half_rn(acc[mi][nj][0]);
            v0.y = __float2half_rn(acc[mi][nj][1]);
            __half2 v1; v1.x = __float2half_rn(acc[mi][nj][2]);
            v1.y = __float2half_rn(acc[mi][nj][3]);
            *(__half2*)(C + (size_t)r0 * N + cc) = v0;
            *(__half2*)(C + (size_t)(r0 + 8) * N + cc) = v1;
        }
    }
}

// ---------------------------------------------------------------------------
// fp16 2-term out-proj GEMM: C = (Ahi+Alo) @ B^T + bias, fp32 out.
// 3 smem tiles/stage (R9-proven pattern).
// ---------------------------------------------------------------------------
#define OS_ELEMS (3 * GT_ELEMS)
#define SMEM_OP (2 * OS_ELEMS * 2)       /* 61440 B */

__global__ __launch_bounds__(256, 2) void outproj_gemm_f16_kernel(
    const __half* __restrict__ Ahi, const __half* __restrict__ Alo,
    const __half* __restrict__ B, float* __restrict__ C,
    const float* __restrict__ bias, int M, int N, int K)
{
    extern __shared__ __half smq[];
    const uint32_t sbase = smem_u32(smq);
    const int t = threadIdx.x;
    const int warp = t >> 5, lane = t & 31;
    const int bm = blockIdx.y * 128;
    const int bn = blockIdx.x * 128;
    const int wm = (warp >> 1) * 32;
    const int wn = (warp & 1) * 64;

    const __half* srcs[3] = { Ahi, Alo, B };

    auto load_stage = [&](int buf, int k0) {
        uint32_t sdst = sbase + (uint32_t)buf * OS_ELEMS * 2;
        #pragma unroll
        for (int m = 0; m < 3; m++) {
            const int rbase = (m < 2) ? bm : bn;
            const __half* S = srcs[m] + (size_t)rbase * K + k0;
            uint32_t td = sdst + (uint32_t)m * GT_ELEMS * 2;
            #pragma unroll
            for (int i = 0; i < 2; i++) {
                int id = t + i * 256;
                int row = id >> 2, c = id & 3;
                cp_async16(td + (uint32_t)(row * GP + c * 8) * 2,
                           S + (size_t)row * K + c * 8);
            }
        }
        CP_COMMIT();
    };

    float acc[2][8][4];
    #pragma unroll
    for (int mi = 0; mi < 2; mi++)
        #pragma unroll
        for (int nj = 0; nj < 8; nj++)
            #pragma unroll
            for (int e = 0; e < 4; e++) acc[mi][nj][e] = 0.0f;

    const int nch = K >> 5;
    load_stage(0, 0);
    load_stage(1, BK);

    const int a_r = (lane & 7) + ((lane >> 3) & 1) * 8;
    const int a_c = (lane >> 4) * 8;
    const int b_r = (lane & 7) + (lane >> 4) * 8;
    const int b_c = ((lane >> 3) & 1) * 8;

    for (int c = 0; c < nch; c++) {
        if (c < nch - 1) { CP_WAIT(1); } else { CP_WAIT(0); }
        __syncthreads();

        const uint32_t stg = sbase + (uint32_t)(c & 1) * OS_ELEMS * 2;
        const uint32_t tAhi = stg;
        const uint32_t tAlo = stg + GT_ELEMS * 2;
        const uint32_t tB = stg + 2 * GT_ELEMS * 2;

        #pragma unroll
        for (int ks = 0; ks < BK; ks += 16) {
            uint32_t ah[2][4], al[2][4], bh[16];
            #pragma unroll
            for (int mi = 0; mi < 2; mi++) {
                uint32_t off = (uint32_t)((wm + mi * 16 + a_r) * GP + ks + a_c) * 2;
                ldm_x4(tAhi + off, ah[mi]);
                ldm_x4(tAlo + off, al[mi]);
            }
            #pragma unroll
            for (int nj2 = 0; nj2 < 4; nj2++) {
                uint32_t off = (uint32_t)((wn + nj2 * 16 + b_r) * GP + ks + b_c) * 2;
                ldm_x4(tB + off, bh + nj2 * 4);
            }
            #pragma unroll
            for (int mi = 0; mi < 2; mi++)
                #pragma unroll
                for (int nj = 0; nj < 8; nj++) {
                    mma_f16(acc[mi][nj], ah[mi], bh + nj * 2);
                    mma_f16(acc[mi][nj], al[mi], bh + nj * 2);
                }
        }
        __syncthreads();
        if (c + 2 < nch) load_stage(c & 1, (c + 2) * BK);
    }

    const int group = lane >> 2, tid4 = lane & 3;
    #pragma unroll
    for (int mi = 0; mi < 2; mi++) {
        int r0 = bm + wm + mi * 16 + group;
        #pragma unroll
        for (int nj = 0; nj < 8; nj++) {
            int cc = bn + wn + nj * 8 + tid4 * 2;
            float2 bb = *(const float2*)(bias + cc);
            *(float2*)(C + (size_t)r0 * N + cc) =
                make_float2(acc[mi][nj][0] + bb.x, acc[mi][nj][1] + bb.y);
            *(float2*)(C + (size_t)(r0 + 8) * N + cc) =
                make_float2(acc[mi][nj][2] + bb.x, acc[mi][nj][3] + bb.y);
        }
    }
}

// ---------------------------------------------------------------------------
// Scores via fp16 HMMA 1-term (R11-proven).
// ---------------------------------------------------------------------------
#define SP 72
#define ST_ELEMS (128 * SP)
#define SMEM_SCORES (2 * ST_ELEMS * 2)

__global__ __launch_bounds__(256) void scores_mma_kernel(
    const float* __restrict__ mask, __half* __restrict__ e16,
    const __half* __restrict__ q16, float* __restrict__ psum)
{
    extern __shared__ __half smh[];
    const uint32_t sbase = smem_u32(smh);
    const int t = threadIdx.x;
    const int warp = t >> 5, lane = t & 31;
    const int bh = blockIdx.z;
    const int b = bh / HEADS, h = bh % HEADS;
    const int bm = blockIdx.y * 128;
    const int bn = blockIdx.x * 128;
    const int wm = (warp >> 1) * 32;
    const int wn = (warp & 1) * 64;

    const __half* bases[2] = {
        q16 + ((size_t)(b * SEQ + bm)) * D3 + h * HD,
        q16 + ((size_t)(b * SEQ + bn)) * D3 + D_MODEL + h * HD };
    #pragma unroll
    for (int m = 0; m < 2; m++) {
        uint32_t td = sbase + (uint32_t)m * ST_ELEMS * 2;
        #pragma unroll
        for (int i = 0; i < 4; i++) {
            int id = t + i * 256;
            int r = id >> 3, c = id & 7;
            cp_async16(td + (uint32_t)(r * SP + c * 8) * 2,
                       bases[m] + (size_t)r * D3 + c * 8);
        }
    }
    CP_COMMIT();

    float acc[2][8][4];
    #pragma unroll
    for (int mi = 0; mi < 2; mi++)
        #pragma unroll
        for (int nj = 0; nj < 8; nj++)
            #pragma unroll
            for (int e = 0; e < 4; e++) acc[mi][nj][e] = 0.0f;

    const int a_r = (lane & 7) + ((lane >> 3) & 1) * 8;
    const int a_c = (lane >> 4) * 8;
    const int b_r = (lane & 7) + (lane >> 4) * 8;
    const int b_c = ((lane >> 3) & 1) * 8;

    const uint32_t tQ = sbase;
    const uint32_t tK = sbase + ST_ELEMS * 2;

    CP_WAIT(0);
    __syncthreads();

    #pragma unroll
    for (int ks = 0; ks < 4; ks++) {
        uint32_t ah[2][4], bhf[16];
        #pragma unroll
        for (int mi = 0; mi < 2; mi++) {
            uint32_t off = (uint32_t)((wm + mi * 16 + a_r) * SP + ks * 16 + a_c) * 2;
            ldm_x4(tQ + off, ah[mi]);
        }
        #pragma unroll
        for (int nj2 = 0; nj2 < 4; nj2++) {
            uint32_t off = (uint32_t)((wn + nj2 * 16 + b_r) * SP + ks * 16 + b_c) * 2;
            ldm_x4(tK + off, bhf + nj2 * 4);
        }
        #pragma unroll
        for (int mi = 0; mi < 2; mi++)
            #pragma unroll
            for (int nj = 0; nj < 8; nj++)
                mma_f16(acc[mi][nj], ah[mi], bhf + nj * 2);
    }

    const int group = lane >> 2, tid4 = lane & 3;
    float mq[4];
    #pragma unroll
    for (int mi = 0; mi < 2; mi++) {
        mq[mi * 2 + 0] = mask[b * SEQ + bm + wm + mi * 16 + group];
        mq[mi * 2 + 1] = mask[b * SEQ + bm + wm + mi * 16 + group + 8];
    }
    __half* out = e16 + (size_t)bh * SEQ * SEQ;
    float srow[2][2];
    srow[0][0] = srow[0][1] = srow[1][0] = srow[1][1] = 0.0f;
    #pragma unroll
    for (int nj = 0; nj < 8; nj++) {
        int cc = bn + wn + nj * 8 + tid4 * 2;
        float2 mk = *(const float2*)(mask + b * SEQ + cc);
        #pragma unroll
        for (int mi = 0; mi < 2; mi++) {
            int r0 = bm + wm + mi * 16 + group;
            float v0 = acc[mi][nj][0], v1 = acc[mi][nj][1];
            float v2 = acc[mi][nj][2], v3 = acc[mi][nj][3];
            if (mq[mi * 2 + 0] * mk.x == 0.0f) v0 = -100000.0f;
            if (mq[mi * 2 + 0] * mk.y == 0.0f) v1 = -100000.0f;
            if (mq[mi * 2 + 1] * mk.x == 0.0f) v2 = -100000.0f;
            if (mq[mi * 2 + 1] * mk.y == 0.0f) v3 = -100000.0f;
            __half h0 = __float2half_rn(fmaxf(fexp(v0 * 0.03125f), 1e-7f));
            __half h1 = __float2half_rn(fmaxf(fexp(v1 * 0.03125f), 1e-7f));
            __half h2 = __float2half_rn(fmaxf(fexp(v2 * 0.03125f), 1e-7f));
            __half h3 = __float2half_rn(fmaxf(fexp(v3 * 0.03125f), 1e-7f));
            __half2 p01; p01.x = h0; p01.y = h1;
            __half2 p23; p23.x = h2; p23.y = h3;
            *(__half2*)(out + (size_t)r0 * SEQ + cc) = p01;
            *(__half2*)(out + (size_t)(r0 + 8) * SEQ + cc) = p23;
            srow[mi][0] += __half2float(h0) + __half2float(h1);
            srow[mi][1] += __half2float(h2) + __half2float(h3);
        }
    }
    #pragma unroll
    for (int mi = 0; mi < 2; mi++) {
        #pragma unroll
        for (int s = 0; s < 2; s++) {
            srow[mi][s] += __shfl_xor_sync(0xffffffffu, srow[mi][s], 1);
            srow[mi][s] += __shfl_xor_sync(0xffffffffu, srow[mi][s], 2);
        }
    }
    __syncthreads();
    float* rs = (float*)smh;
    if (tid4 == 0) {
        #pragma unroll
        for (int mi = 0; mi < 2; mi++) {
            rs[(wm + mi * 16 + group) * 2 + (warp & 1)] = srow[mi][0];
            rs[(wm + mi * 16 + group + 8) * 2 + (warp & 1)] = srow[mi][1];
        }
    }
    __syncthreads();
    if (t < 128)
        psum[((size_t)bh * SEQ + bm + t) * 16 + blockIdx.x] = rs[t * 2] + rs[t * 2 + 1];
}

// ---------------------------------------------------------------------------
__global__ __launch_bounds__(256) void rowinv_kernel(
    const float* __restrict__ psum, float* __restrict__ inv)
{
    int r = blockIdx.x * 256 + threadIdx.x;
    if (r >= NROWS) return;
    float4 a = *(const float4*)(psum + (size_t)r * 16);
    float4 b2 = *(const float4*)(psum + (size_t)r * 16 + 4);
    float4 c = *(const float4*)(psum + (size_t)r * 16 + 8);
    float4 d = *(const float4*)(psum + (size_t)r * 16 + 12);
    float s = a.x + a.y + a.z + a.w + b2.x + b2.y + b2.z + b2.w
            + c.x + c.y + c.z + c.w + d.x + d.y + d.z + d.w;
    inv[r] = 1.0f / s;
}

// ---------------------------------------------------------------------------
// av (R11-proven, epilogue now fp16 hi/lo): reads fp16 e-scratch (1-term MMA
// with V), writes normalized fp32 attn, split-stores ao fp16 hi/lo.
// ---------------------------------------------------------------------------
#define EP 72
#define AVE(i) ((i) * 18432)
#define AVV(i) (36864 + (i) * 9216)
#define AVINV  55296
#define SMEM_AV (55296 + 512)

__global__ __launch_bounds__(256) void av_mma_kernel(
    const __half* __restrict__ e16, float* __restrict__ attn,
    const __half* __restrict__ q16,
    __half* __restrict__ aohi, __half* __restrict__ aolo,
    const float* __restrict__ inv)
{
    extern __shared__ char smc[];
    const uint32_t sbase = smem_u32(smc);
    const int t = threadIdx.x;
    const int warp = t >> 5, lane = t & 31;
    const int bh = blockIdx.y;
    const int b = bh / HEADS, h = bh % HEADS;
    const int bm = blockIdx.x * 128;
    const int wm = warp * 16;

    const __half* Ebase = e16 + (size_t)bh * SEQ * SEQ + (size_t)bm * SEQ;
    float* Abase = attn + (size_t)bh * SEQ * SEQ + (size_t)bm * SEQ;
    const __half* V = q16 + (size_t)b * SEQ * D3 + 2 * D_MODEL + h * HD;

    float* inv_s = (float*)(smc + AVINV);
    if (t < 128) inv_s[t] = inv[(size_t)bh * SEQ + bm + t];
    __syncthreads();

    auto load_chunk = [&](int c) {
        const int k0 = c * 64;
        const uint32_t buf = c & 1;
        #pragma unroll
        for (int i = 0; i < 4; i++) {
            int id = t + i * 256;
            int r = id >> 3, cs = id & 7;
            cp_async16(sbase + AVE(buf) + (uint32_t)(r * EP + cs * 8) * 2,
                       Ebase + (size_t)r * SEQ + k0 + cs * 8);
        }
        #pragma unroll
        for (int i = 0; i < 2; i++) {
            int id = t + i * 256;
            int r = id >> 3, cs = id & 7;
            cp_async16(sbase + AVV(buf) + (uint32_t)(r * EP + cs * 8) * 2,
                       V + (size_t)(k0 + r) * D3 + cs * 8);
        }
        CP_COMMIT();
    };

    float acc[8][4];
    #pragma unroll
    for (int nj = 0; nj < 8; nj++)
        #pragma unroll
        for (int e = 0; e < 4; e++) acc[nj][e] = 0.0f;

    load_chunk(0);

    const int a_r = (lane & 7) + ((lane >> 3) & 1) * 8;
    const int a_c = (lane >> 4) * 8;
    const int tb_r = lane & 15;
    const int tb_c = (lane >> 4) * 8;

    for (int c = 0; c < SEQ / 64; c++) {
        CP_WAIT(0);
        __syncthreads();
        const int k0 = c * 64;
        const uint32_t buf = c & 1;
        if (c + 1 < SEQ / 64) load_chunk(c + 1);

        const __half* Es = (const __half*)(smc + AVE(buf));
        #pragma unroll
        for (int i = 0; i < 8; i++) {
            int id = t + i * 256;
            int r = id >> 4, c4 = id & 15;
            uint2 raw = *(const uint2*)(Es + r * EP + c4 * 4);
            __half2 p01 = *(__half2*)&raw.x;
            __half2 p23 = *(__half2*)&raw.y;
            float s = inv_s[r];
            float4 o;
            o.x = __half2float(p01.x) * s;
            o.y = __half2float(p01.y) * s;
            o.z = __half2float(p23.x) * s;
            o.w = __half2float(p23.y) * s;
            *(float4*)(Abase + (size_t)r * SEQ + k0 + c4 * 4) = o;
        }

        const uint32_t tA = sbase + AVE(buf);
        const uint32_t tV = sbase + AVV(buf);
        #pragma unroll
        for (int ks = 0; ks < 4; ks++) {
            uint32_t ah[4], bhf[16];
            uint32_t aoff = (uint32_t)((wm + a_r) * EP + ks * 16 + a_c) * 2;
            ldm_x4(tA + aoff, ah);
            #pragma unroll
            for (int nj2 = 0; nj2 < 4; nj2++) {
                uint32_t boff =
                    (uint32_t)((ks * 16 + tb_r) * EP + nj2 * 16 + tb_c) * 2;
                ldm_x4_trans(tV + boff, bhf + nj2 * 4);
            }
            #pragma unroll
            for (int nj = 0; nj < 8; nj++)
                mma_f16(acc[nj], ah, bhf + nj * 2);
        }
    }

    const int group = lane >> 2, tid4 = lane & 3;
    const float ia = inv_s[wm + group];
    const float ib = inv_s[wm + group + 8];
    #pragma unroll
    for (int nj = 0; nj < 8; nj++) {
        int cc = h * HD + nj * 8 + tid4 * 2;
        size_t r0 = (size_t)(b * SEQ + bm + wm + group) * D_MODEL + cc;
        size_t r1 = r0 + (size_t)8 * D_MODEL;
        split_store2_h(aohi, aolo, r0, acc[nj][0] * ia, acc[nj][1] * ia);
        split_store2_h(aohi, aolo, r1, acc[nj][2] * ib, acc[nj][3] * ib);
    }
}

// ---------------------------------------------------------------------------
// fp32 -> fp16 round (x input)
// ---------------------------------------------------------------------------
__global__ __launch_bounds__(256) void round_h_kernel(
    const float* __restrict__ in, __half* __restrict__ o, int n4)
{
    int i = blockIdx.x * 256 + threadIdx.x;
    if (i >= n4) return;
    float4 v = ((const float4*)in)[i];
    __half h[4];
    h[0] = __float2half_rn(v.x);
    h[1] = __float2half_rn(v.y);
    h[2] = __float2half_rn(v.z);
    h[3] = __float2half_rn(v.w);
    ((uint2*)o)[i] = *(uint2*)h;
}

// ---------------------------------------------------------------------------
// W[K,N] fp32 -> Wt[N,K] fp16 single (transpose + round)
// ---------------------------------------------------------------------------
__global__ __launch_bounds__(256) void transpose_h_kernel(
    const float* __restrict__ W, __half* __restrict__ o16, int K, int N)
{
    __shared__ float tile[32][33];
    const int nx = blockIdx.x * 32;
    const int ky = blockIdx.y * 32;
    const int tx = threadIdx.x & 31;
    const int ty = threadIdx.x >> 5;
    #pragma unroll
    for (int i = 0; i < 4; i++)
        tile[ty + 8 * i][tx] = W[(size_t)(ky + ty + 8 * i) * N + nx + tx];
    __syncthreads();
    #pragma unroll
    for (int i = 0; i < 4; i++) {
        float v = tile[tx][ty + 8 * i];
        o16[(size_t)(nx + ty + 8 * i) * K + ky + tx] = __float2half_rn(v);
    }
}

// ---------------------------------------------------------------------------
extern "C" void kernel_launch(void* const* d_in, const int* in_sizes, int n_in,
                              void* d_out, int out_size)
{
    const float* x     = (const float*)d_in[0];
    const float* mask  = (const float*)d_in[1];
    const float* W_qkv = (const float*)d_in[2];
    const float* W_h   = (const float*)d_in[3];
    const float* b_h   = (const float*)d_in[4];

    float* out  = (float*)d_out;
    float* attn = out + (size_t)BL * D_MODEL;

    __half *x16, *wq16, *wh16, *q16, *e16, *aohi, *aolo;
    float *psum, *inv;
    cudaGetSymbolAddress((void**)&x16, g_x16);
    cudaGetSymbolAddress((void**)&wq16, g_wq16);
    cudaGetSymbolAddress((void**)&wh16, g_wh16);
    cudaGetSymbolAddress((void**)&q16, g_q16);
    cudaGetSymbolAddress((void**)&aohi, g_ao16h);
    cudaGetSymbolAddress((void**)&aolo, g_ao16l);
    cudaGetSymbolAddress((void**)&psum, g_psum);
    cudaGetSymbolAddress((void**)&inv, g_inv);
    cudaGetSymbolAddress((void**)&e16, g_e16);

    cudaFuncSetAttribute(qkv_gemm_f16_kernel, cudaFuncAttributeMaxDynamicSharedMemorySize, SMEM_QKV);
    cudaFuncSetAttribute(outproj_gemm_f16_kernel, cudaFuncAttributeMaxDynamicSharedMemorySize, SMEM_OP);
    cudaFuncSetAttribute(scores_mma_kernel, cudaFuncAttributeMaxDynamicSharedMemorySize, SMEM_SCORES);
    cudaFuncSetAttribute(av_mma_kernel, cudaFuncAttributeMaxDynamicSharedMemorySize, SMEM_AV);

    // 0) input conversions
    round_h_kernel<<<(BL * D_MODEL / 4 + 255) / 256, 256>>>(x, x16, BL * D_MODEL / 4);
    transpose_h_kernel<<<dim3(D3 / 32, D_MODEL / 32), 256>>>(W_qkv, wq16, D_MODEL, D3);
    transpose_h_kernel<<<dim3(D_MODEL / 32, D_MODEL / 32), 256>>>(W_h, wh16, D_MODEL, D_MODEL);

    // 1) QKV = x @ W_qkv (fp16 1-term) -> fp16
    qkv_gemm_f16_kernel<<<dim3(D3 / 128, BL / 128), 256, SMEM_QKV>>>(
        x16, wq16, q16, BL, D3, D_MODEL);

    // 2) scores (fp16 1-term) + fused exp -> fp16 scratch + psums
    scores_mma_kernel<<<dim3(SEQ / 128, SEQ / 128, BATCH * HEADS), 256, SMEM_SCORES>>>(
        mask, e16, q16, psum);

    // 3) row-sum inverse
    rowinv_kernel<<<NROWS / 256, 256>>>(psum, inv);

    // 4) attn @ V (1-term fp16) + normalized fp32 attn write -> ao fp16 hi/lo
    av_mma_kernel<<<dim3(SEQ / 128, BATCH * HEADS), 256, SMEM_AV>>>(
        e16, attn, q16, aohi, aolo, inv);

    // 5) output = ao @ W_h + b_h (fp16 2-term)
    outproj_gemm_f16_kernel<<<dim3(D_MODEL / 128, BL / 128), 256, SMEM_OP>>>(
        aohi, aolo, wh16, out, b_h, BL, D_MODEL, D_MODEL);
}

// round 13
// speedup vs baseline: 2.7792x; 1.0221x over previous
#include <cuda_runtime.h>
#include <cuda_bf16.h>
#include <cuda_fp16.h>
#include <math.h>
#include <stdint.h>

#define D_MODEL 1024
#define HEADS 16
#define HD 64
#define BATCH 2
#define SEQ 2048
#define BL (BATCH * SEQ)      /* 4096 */
#define D3 (3 * D_MODEL)      /* 3072 */
#define NROWS (BATCH * HEADS * SEQ)

typedef __nv_bfloat16 bf16;

// ---------------------------------------------------------------------------
// Scratch (allocation-free: __device__ globals)
// ---------------------------------------------------------------------------
__device__ __half g_x16[(size_t)BL * D_MODEL];
__device__ __half g_wq16[(size_t)D3 * D_MODEL];
__device__ __half g_wh16[(size_t)D_MODEL * D_MODEL];
__device__ __half g_q16[(size_t)BL * D3];        // QKV fp16
__device__ __half g_ao16h[(size_t)BL * D_MODEL]; // attn_out fp16 hi
__device__ __half g_ao16l[(size_t)BL * D_MODEL]; // attn_out fp16 lo
__device__ float g_psum[(size_t)NROWS * 16];
__device__ float g_inv[(size_t)NROWS];
__device__ __half g_e16[(size_t)NROWS * SEQ];    // unnormalized exp, fp16

// ---------------------------------------------------------------------------
// Portable PTX helpers
// ---------------------------------------------------------------------------
__device__ __forceinline__ uint32_t smem_u32(const void* p) {
    uint32_t a;
    asm("{ .reg .u64 t; cvta.to.shared.u64 t, %1; cvt.u32.u64 %0, t; }"
        : "=r"(a) : "l"(p));
    return a;
}
__device__ __forceinline__ void cp_async16(uint32_t s, const void* g) {
    asm volatile("cp.async.cg.shared.global [%0], [%1], 16;" :: "r"(s), "l"(g));
}
#define CP_COMMIT() asm volatile("cp.async.commit_group;" ::: "memory")
#define CP_WAIT(n)  asm volatile("cp.async.wait_group %0;" :: "n"(n) : "memory")

__device__ __forceinline__ void ldm_x4(uint32_t addr, uint32_t* r) {
    asm volatile("ldmatrix.sync.aligned.m8n8.x4.shared.b16 {%0,%1,%2,%3}, [%4];"
        : "=r"(r[0]), "=r"(r[1]), "=r"(r[2]), "=r"(r[3]) : "r"(addr));
}
__device__ __forceinline__ void ldm_x4_trans(uint32_t addr, uint32_t* r) {
    asm volatile("ldmatrix.sync.aligned.m8n8.x4.trans.shared.b16 {%0,%1,%2,%3}, [%4];"
        : "=r"(r[0]), "=r"(r[1]), "=r"(r[2]), "=r"(r[3]) : "r"(addr));
}
__device__ __forceinline__ void mma_f16(float* c, const uint32_t* a, const uint32_t* b) {
    asm volatile(
        "mma.sync.aligned.m16n8k16.row.col.f32.f16.f16.f32 "
        "{%0,%1,%2,%3}, {%4,%5,%6,%7}, {%8,%9}, {%0,%1,%2,%3};"
        : "+f"(c[0]), "+f"(c[1]), "+f"(c[2]), "+f"(c[3])
        : "r"(a[0]), "r"(a[1]), "r"(a[2]), "r"(a[3]), "r"(b[0]), "r"(b[1]));
}
__device__ __forceinline__ void split_store2_h(__half* hi, __half* lo, size_t idx,
                                               float a, float b) {
    __half ha = __float2half_rn(a), hb = __float2half_rn(b);
    __half la = __float2half_rn(a - __half2float(ha));
    __half lb = __float2half_rn(b - __half2float(hb));
    __half2 hv; hv.x = ha; hv.y = hb;
    __half2 lv; lv.x = la; lv.y = lb;
    *(__half2*)(hi + idx) = hv;
    *(__half2*)(lo + idx) = lv;
}
__device__ __forceinline__ float fexp(float x) {
    float t = x * 1.4426950408889634f;
    t = fmaxf(t, -126.0f);
    float n = rintf(t);
    float f = t - n;
    float p = 1.5403530e-4f;
    p = fmaf(p, f, 1.3333558e-3f);
    p = fmaf(p, f, 9.6181291e-3f);
    p = fmaf(p, f, 5.5504109e-2f);
    p = fmaf(p, f, 2.4022651e-1f);
    p = fmaf(p, f, 6.9314718e-1f);
    p = fmaf(p, f, 1.0f);
    return p * __int_as_float(((int)n + 127) << 23);
}

// ---------------------------------------------------------------------------
// fp16 1-term QKV GEMM: C = A @ B^T, fp16 out. BK=64, double buffer.
// ---------------------------------------------------------------------------
#define QBK 64
#define QGP 72
#define QT_ELEMS (128 * QGP)             /* 9216 halfs / tile */
#define QS_ELEMS (2 * QT_ELEMS)
#define SMEM_QKV (2 * QS_ELEMS * 2)      /* 73728 B */

__global__ __launch_bounds__(256, 2) void qkv_gemm_f16_kernel(
    const __half* __restrict__ A, const __half* __restrict__ B,
    __half* __restrict__ C, int M, int N, int K)
{
    extern __shared__ __half smq[];
    const uint32_t sbase = smem_u32(smq);
    const int t = threadIdx.x;
    const int warp = t >> 5, lane = t & 31;
    const int bm = blockIdx.y * 128;
    const int bn = blockIdx.x * 128;
    const int wm = (warp >> 1) * 32;
    const int wn = (warp & 1) * 64;

    const __half* srcs[2] = { A, B };

    auto load_stage = [&](int buf, int k0) {
        uint32_t sdst = sbase + (uint32_t)buf * QS_ELEMS * 2;
        #pragma unroll
        for (int m = 0; m < 2; m++) {
            const int rbase = (m == 0) ? bm : bn;
            const __half* S = srcs[m] + (size_t)rbase * K + k0;
            uint32_t td = sdst + (uint32_t)m * QT_ELEMS * 2;
            #pragma unroll
            for (int i = 0; i < 4; i++) {
                int id = t + i * 256;          // 0..1023
                int row = id >> 3, c = id & 7;
                cp_async16(td + (uint32_t)(row * QGP + c * 8) * 2,
                           S + (size_t)row * K + c * 8);
            }
        }
        CP_COMMIT();
    };

    float acc[2][8][4];
    #pragma unroll
    for (int mi = 0; mi < 2; mi++)
        #pragma unroll
        for (int nj = 0; nj < 8; nj++)
            #pragma unroll
            for (int e = 0; e < 4; e++) acc[mi][nj][e] = 0.0f;

    const int nch = K >> 6;
    load_stage(0, 0);
    load_stage(1, QBK);

    const int a_r = (lane & 7) + ((lane >> 3) & 1) * 8;
    const int a_c = (lane >> 4) * 8;
    const int b_r = (lane & 7) + (lane >> 4) * 8;
    const int b_c = ((lane >> 3) & 1) * 8;

    for (int c = 0; c < nch; c++) {
        if (c < nch - 1) { CP_WAIT(1); } else { CP_WAIT(0); }
        __syncthreads();

        const uint32_t stg = sbase + (uint32_t)(c & 1) * QS_ELEMS * 2;
        const uint32_t tA = stg;
        const uint32_t tB = stg + QT_ELEMS * 2;

        #pragma unroll
        for (int ks = 0; ks < QBK; ks += 16) {
            uint32_t ah[2][4], bh[16];
            #pragma unroll
            for (int mi = 0; mi < 2; mi++) {
                uint32_t off = (uint32_t)((wm + mi * 16 + a_r) * QGP + ks + a_c) * 2;
                ldm_x4(tA + off, ah[mi]);
            }
            #pragma unroll
            for (int nj2 = 0; nj2 < 4; nj2++) {
                uint32_t off = (uint32_t)((wn + nj2 * 16 + b_r) * QGP + ks + b_c) * 2;
                ldm_x4(tB + off, bh + nj2 * 4);
            }
            #pragma unroll
            for (int mi = 0; mi < 2; mi++)
                #pragma unroll
                for (int nj = 0; nj < 8; nj++)
                    mma_f16(acc[mi][nj], ah[mi], bh + nj * 2);
        }
        __syncthreads();
        if (c + 2 < nch) load_stage(c & 1, (c + 2) * QBK);
    }

    const int group = lane >> 2, tid4 = lane & 3;
    #pragma unroll
    for (int mi = 0; mi < 2; mi++) {
        int r0 = bm + wm + mi * 16 + group;
        #pragma unroll
        for (int nj = 0; nj < 8; nj++) {
            int cc = bn + wn + nj * 8 + tid4 * 2;
            __half2 v0; v0.x = __float2half_rn(acc[mi][nj][0]);
            v0.y = __float2half_rn(acc[mi][nj][1]);
            __half2 v1; v1.x = __float2half_rn(acc[mi][nj][2]);
            v1.y = __float2half_rn(acc[mi][nj][3]);
            *(__half2*)(C + (size_t)r0 * N + cc) = v0;
            *(__half2*)(C + (size_t)(r0 + 8) * N + cc) = v1;
        }
    }
}

// ---------------------------------------------------------------------------
// fp16 2-term out-proj GEMM (R12-proven): C = (Ahi+Alo) @ B^T + bias.
// ---------------------------------------------------------------------------
#define BK 32
#define GP 40
#define GT_ELEMS (128 * GP)
#define OS_ELEMS (3 * GT_ELEMS)
#define SMEM_OP (2 * OS_ELEMS * 2)

__global__ __launch_bounds__(256, 2) void outproj_gemm_f16_kernel(
    const __half* __restrict__ Ahi, const __half* __restrict__ Alo,
    const __half* __restrict__ B, float* __restrict__ C,
    const float* __restrict__ bias, int M, int N, int K)
{
    extern __shared__ __half smq[];
    const uint32_t sbase = smem_u32(smq);
    const int t = threadIdx.x;
    const int warp = t >> 5, lane = t & 31;
    const int bm = blockIdx.y * 128;
    const int bn = blockIdx.x * 128;
    const int wm = (warp >> 1) * 32;
    const int wn = (warp & 1) * 64;

    const __half* srcs[3] = { Ahi, Alo, B };

    auto load_stage = [&](int buf, int k0) {
        uint32_t sdst = sbase + (uint32_t)buf * OS_ELEMS * 2;
        #pragma unroll
        for (int m = 0; m < 3; m++) {
            const int rbase = (m < 2) ? bm : bn;
            const __half* S = srcs[m] + (size_t)rbase * K + k0;
            uint32_t td = sdst + (uint32_t)m * GT_ELEMS * 2;
            #pragma unroll
            for (int i = 0; i < 2; i++) {
                int id = t + i * 256;
                int row = id >> 2, c = id & 3;
                cp_async16(td + (uint32_t)(row * GP + c * 8) * 2,
                           S + (size_t)row * K + c * 8);
            }
        }
        CP_COMMIT();
    };

    float acc[2][8][4];
    #pragma unroll
    for (int mi = 0; mi < 2; mi++)
        #pragma unroll
        for (int nj = 0; nj < 8; nj++)
            #pragma unroll
            for (int e = 0; e < 4; e++) acc[mi][nj][e] = 0.0f;

    const int nch = K >> 5;
    load_stage(0, 0);
    load_stage(1, BK);

    const int a_r = (lane & 7) + ((lane >> 3) & 1) * 8;
    const int a_c = (lane >> 4) * 8;
    const int b_r = (lane & 7) + (lane >> 4) * 8;
    const int b_c = ((lane >> 3) & 1) * 8;

    for (int c = 0; c < nch; c++) {
        if (c < nch - 1) { CP_WAIT(1); } else { CP_WAIT(0); }
        __syncthreads();

        const uint32_t stg = sbase + (uint32_t)(c & 1) * OS_ELEMS * 2;
        const uint32_t tAhi = stg;
        const uint32_t tAlo = stg + GT_ELEMS * 2;
        const uint32_t tB = stg + 2 * GT_ELEMS * 2;

        #pragma unroll
        for (int ks = 0; ks < BK; ks += 16) {
            uint32_t ah[2][4], al[2][4], bh[16];
            #pragma unroll
            for (int mi = 0; mi < 2; mi++) {
                uint32_t off = (uint32_t)((wm + mi * 16 + a_r) * GP + ks + a_c) * 2;
                ldm_x4(tAhi + off, ah[mi]);
                ldm_x4(tAlo + off, al[mi]);
            }
            #pragma unroll
            for (int nj2 = 0; nj2 < 4; nj2++) {
                uint32_t off = (uint32_t)((wn + nj2 * 16 + b_r) * GP + ks + b_c) * 2;
                ldm_x4(tB + off, bh + nj2 * 4);
            }
            #pragma unroll
            for (int mi = 0; mi < 2; mi++)
                #pragma unroll
                for (int nj = 0; nj < 8; nj++) {
                    mma_f16(acc[mi][nj], ah[mi], bh + nj * 2);
                    mma_f16(acc[mi][nj], al[mi], bh + nj * 2);
                }
        }
        __syncthreads();
        if (c + 2 < nch) load_stage(c & 1, (c + 2) * BK);
    }

    const int group = lane >> 2, tid4 = lane & 3;
    #pragma unroll
    for (int mi = 0; mi < 2; mi++) {
        int r0 = bm + wm + mi * 16 + group;
        #pragma unroll
        for (int nj = 0; nj < 8; nj++) {
            int cc = bn + wn + nj * 8 + tid4 * 2;
            float2 bb = *(const float2*)(bias + cc);
            *(float2*)(C + (size_t)r0 * N + cc) =
                make_float2(acc[mi][nj][0] + bb.x, acc[mi][nj][1] + bb.y);
            *(float2*)(C + (size_t)(r0 + 8) * N + cc) =
                make_float2(acc[mi][nj][2] + bb.x, acc[mi][nj][3] + bb.y);
        }
    }
}

// ---------------------------------------------------------------------------
// Scores via fp16 HMMA 1-term (R11-proven) + occupancy hint.
// ---------------------------------------------------------------------------
#define SP 72
#define ST_ELEMS (128 * SP)
#define SMEM_SCORES (2 * ST_ELEMS * 2)

__global__ __launch_bounds__(256, 2) void scores_mma_kernel(
    const float* __restrict__ mask, __half* __restrict__ e16,
    const __half* __restrict__ q16, float* __restrict__ psum)
{
    extern __shared__ __half smh[];
    const uint32_t sbase = smem_u32(smh);
    const int t = threadIdx.x;
    const int warp = t >> 5, lane = t & 31;
    const int bh = blockIdx.z;
    const int b = bh / HEADS, h = bh % HEADS;
    const int bm = blockIdx.y * 128;
    const int bn = blockIdx.x * 128;
    const int wm = (warp >> 1) * 32;
    const int wn = (warp & 1) * 64;

    const __half* bases[2] = {
        q16 + ((size_t)(b * SEQ + bm)) * D3 + h * HD,
        q16 + ((size_t)(b * SEQ + bn)) * D3 + D_MODEL + h * HD };
    #pragma unroll
    for (int m = 0; m < 2; m++) {
        uint32_t td = sbase + (uint32_t)m * ST_ELEMS * 2;
        #pragma unroll
        for (int i = 0; i < 4; i++) {
            int id = t + i * 256;
            int r = id >> 3, c = id & 7;
            cp_async16(td + (uint32_t)(r * SP + c * 8) * 2,
                       bases[m] + (size_t)r * D3 + c * 8);
        }
    }
    CP_COMMIT();

    float acc[2][8][4];
    #pragma unroll
    for (int mi = 0; mi < 2; mi++)
        #pragma unroll
        for (int nj = 0; nj < 8; nj++)
            #pragma unroll
            for (int e = 0; e < 4; e++) acc[mi][nj][e] = 0.0f;

    const int a_r = (lane & 7) + ((lane >> 3) & 1) * 8;
    const int a_c = (lane >> 4) * 8;
    const int b_r = (lane & 7) + (lane >> 4) * 8;
    const int b_c = ((lane >> 3) & 1) * 8;

    const uint32_t tQ = sbase;
    const uint32_t tK = sbase + ST_ELEMS * 2;

    CP_WAIT(0);
    __syncthreads();

    #pragma unroll
    for (int ks = 0; ks < 4; ks++) {
        uint32_t ah[2][4], bhf[16];
        #pragma unroll
        for (int mi = 0; mi < 2; mi++) {
            uint32_t off = (uint32_t)((wm + mi * 16 + a_r) * SP + ks * 16 + a_c) * 2;
            ldm_x4(tQ + off, ah[mi]);
        }
        #pragma unroll
        for (int nj2 = 0; nj2 < 4; nj2++) {
            uint32_t off = (uint32_t)((wn + nj2 * 16 + b_r) * SP + ks * 16 + b_c) * 2;
            ldm_x4(tK + off, bhf + nj2 * 4);
        }
        #pragma unroll
        for (int mi = 0; mi < 2; mi++)
            #pragma unroll
            for (int nj = 0; nj < 8; nj++)
                mma_f16(acc[mi][nj], ah[mi], bhf + nj * 2);
    }

    const int group = lane >> 2, tid4 = lane & 3;
    float mq[4];
    #pragma unroll
    for (int mi = 0; mi < 2; mi++) {
        mq[mi * 2 + 0] = mask[b * SEQ + bm + wm + mi * 16 + group];
        mq[mi * 2 + 1] = mask[b * SEQ + bm + wm + mi * 16 + group + 8];
    }
    __half* out = e16 + (size_t)bh * SEQ * SEQ;
    float srow[2][2];
    srow[0][0] = srow[0][1] = srow[1][0] = srow[1][1] = 0.0f;
    #pragma unroll
    for (int nj = 0; nj < 8; nj++) {
        int cc = bn + wn + nj * 8 + tid4 * 2;
        float2 mk = *(const float2*)(mask + b * SEQ + cc);
        #pragma unroll
        for (int mi = 0; mi < 2; mi++) {
            int r0 = bm + wm + mi * 16 + group;
            float v0 = acc[mi][nj][0], v1 = acc[mi][nj][1];
            float v2 = acc[mi][nj][2], v3 = acc[mi][nj][3];
            if (mq[mi * 2 + 0] * mk.x == 0.0f) v0 = -100000.0f;
            if (mq[mi * 2 + 0] * mk.y == 0.0f) v1 = -100000.0f;
            if (mq[mi * 2 + 1] * mk.x == 0.0f) v2 = -100000.0f;
            if (mq[mi * 2 + 1] * mk.y == 0.0f) v3 = -100000.0f;
            __half h0 = __float2half_rn(fmaxf(fexp(v0 * 0.03125f), 1e-7f));
            __half h1 = __float2half_rn(fmaxf(fexp(v1 * 0.03125f), 1e-7f));
            __half h2 = __float2half_rn(fmaxf(fexp(v2 * 0.03125f), 1e-7f));
            __half h3 = __float2half_rn(fmaxf(fexp(v3 * 0.03125f), 1e-7f));
            __half2 p01; p01.x = h0; p01.y = h1;
            __half2 p23; p23.x = h2; p23.y = h3;
            *(__half2*)(out + (size_t)r0 * SEQ + cc) = p01;
            *(__half2*)(out + (size_t)(r0 + 8) * SEQ + cc) = p23;
            srow[mi][0] += __half2float(h0) + __half2float(h1);
            srow[mi][1] += __half2float(h2) + __half2float(h3);
        }
    }
    #pragma unroll
    for (int mi = 0; mi < 2; mi++) {
        #pragma unroll
        for (int s = 0; s < 2; s++) {
            srow[mi][s] += __shfl_xor_sync(0xffffffffu, srow[mi][s], 1);
            srow[mi][s] += __shfl_xor_sync(0xffffffffu, srow[mi][s], 2);
        }
    }
    __syncthreads();
    float* rs = (float*)smh;
    if (tid4 == 0) {
        #pragma unroll
        for (int mi = 0; mi < 2; mi++) {
            rs[(wm + mi * 16 + group) * 2 + (warp & 1)] = srow[mi][0];
            rs[(wm + mi * 16 + group + 8) * 2 + (warp & 1)] = srow[mi][1];
        }
    }
    __syncthreads();
    if (t < 128)
        psum[((size_t)bh * SEQ + bm + t) * 16 + blockIdx.x] = rs[t * 2] + rs[t * 2 + 1];
}

// ---------------------------------------------------------------------------
__global__ __launch_bounds__(256) void rowinv_kernel(
    const float* __restrict__ psum, float* __restrict__ inv)
{
    int r = blockIdx.x * 256 + threadIdx.x;
    if (r >= NROWS) return;
    float4 a = *(const float4*)(psum + (size_t)r * 16);
    float4 b2 = *(const float4*)(psum + (size_t)r * 16 + 4);
    float4 c = *(const float4*)(psum + (size_t)r * 16 + 8);
    float4 d = *(const float4*)(psum + (size_t)r * 16 + 12);
    float s = a.x + a.y + a.z + a.w + b2.x + b2.y + b2.z + b2.w
            + c.x + c.y + c.z + c.w + d.x + d.y + d.z + d.w;
    inv[r] = 1.0f / s;
}

// ---------------------------------------------------------------------------
// av (R12-proven) + occupancy hint.
// ---------------------------------------------------------------------------
#define EP 72
#define AVE(i) ((i) * 18432)
#define AVV(i) (36864 + (i) * 9216)
#define AVINV  55296
#define SMEM_AV (55296 + 512)

__global__ __launch_bounds__(256, 2) void av_mma_kernel(
    const __half* __restrict__ e16, float* __restrict__ attn,
    const __half* __restrict__ q16,
    __half* __restrict__ aohi, __half* __restrict__ aolo,
    const float* __restrict__ inv)
{
    extern __shared__ char smc[];
    const uint32_t sbase = smem_u32(smc);
    const int t = threadIdx.x;
    const int warp = t >> 5, lane = t & 31;
    const int bh = blockIdx.y;
    const int b = bh / HEADS, h = bh % HEADS;
    const int bm = blockIdx.x * 128;
    const int wm = warp * 16;

    const __half* Ebase = e16 + (size_t)bh * SEQ * SEQ + (size_t)bm * SEQ;
    float* Abase = attn + (size_t)bh * SEQ * SEQ + (size_t)bm * SEQ;
    const __half* V = q16 + (size_t)b * SEQ * D3 + 2 * D_MODEL + h * HD;

    float* inv_s = (float*)(smc + AVINV);
    if (t < 128) inv_s[t] = inv[(size_t)bh * SEQ + bm + t];
    __syncthreads();

    auto load_chunk = [&](int c) {
        const int k0 = c * 64;
        const uint32_t buf = c & 1;
        #pragma unroll
        for (int i = 0; i < 4; i++) {
            int id = t + i * 256;
            int r = id >> 3, cs = id & 7;
            cp_async16(sbase + AVE(buf) + (uint32_t)(r * EP + cs * 8) * 2,
                       Ebase + (size_t)r * SEQ + k0 + cs * 8);
        }
        #pragma unroll
        for (int i = 0; i < 2; i++) {
            int id = t + i * 256;
            int r = id >> 3, cs = id & 7;
            cp_async16(sbase + AVV(buf) + (uint32_t)(r * EP + cs * 8) * 2,
                       V + (size_t)(k0 + r) * D3 + cs * 8);
        }
        CP_COMMIT();
    };

    float acc[8][4];
    #pragma unroll
    for (int nj = 0; nj < 8; nj++)
        #pragma unroll
        for (int e = 0; e < 4; e++) acc[nj][e] = 0.0f;

    load_chunk(0);

    const int a_r = (lane & 7) + ((lane >> 3) & 1) * 8;
    const int a_c = (lane >> 4) * 8;
    const int tb_r = lane & 15;
    const int tb_c = (lane >> 4) * 8;

    for (int c = 0; c < SEQ / 64; c++) {
        CP_WAIT(0);
        __syncthreads();
        const int k0 = c * 64;
        const uint32_t buf = c & 1;
        if (c + 1 < SEQ / 64) load_chunk(c + 1);

        const __half* Es = (const __half*)(smc + AVE(buf));
        #pragma unroll
        for (int i = 0; i < 8; i++) {
            int id = t + i * 256;
            int r = id >> 4, c4 = id & 15;
            uint2 raw = *(const uint2*)(Es + r * EP + c4 * 4);
            __half2 p01 = *(__half2*)&raw.x;
            __half2 p23 = *(__half2*)&raw.y;
            float s = inv_s[r];
            float4 o;
            o.x = __half2float(p01.x) * s;
            o.y = __half2float(p01.y) * s;
            o.z = __half2float(p23.x) * s;
            o.w = __half2float(p23.y) * s;
            *(float4*)(Abase + (size_t)r * SEQ + k0 + c4 * 4) = o;
        }

        const uint32_t tA = sbase + AVE(buf);
        const uint32_t tV = sbase + AVV(buf);
        #pragma unroll
        for (int ks = 0; ks < 4; ks++) {
            uint32_t ah[4], bhf[16];
            uint32_t aoff = (uint32_t)((wm + a_r) * EP + ks * 16 + a_c) * 2;
            ldm_x4(tA + aoff, ah);
            #pragma unroll
            for (int nj2 = 0; nj2 < 4; nj2++) {
                uint32_t boff =
                    (uint32_t)((ks * 16 + tb_r) * EP + nj2 * 16 + tb_c) * 2;
                ldm_x4_trans(tV + boff, bhf + nj2 * 4);
            }
            #pragma unroll
            for (int nj = 0; nj < 8; nj++)
                mma_f16(acc[nj], ah, bhf + nj * 2);
        }
    }

    const int group = lane >> 2, tid4 = lane & 3;
    const float ia = inv_s[wm + group];
    const float ib = inv_s[wm + group + 8];
    #pragma unroll
    for (int nj = 0; nj < 8; nj++) {
        int cc = h * HD + nj * 8 + tid4 * 2;
        size_t r0 = (size_t)(b * SEQ + bm + wm + group) * D_MODEL + cc;
        size_t r1 = r0 + (size_t)8 * D_MODEL;
        split_store2_h(aohi, aolo, r0, acc[nj][0] * ia, acc[nj][1] * ia);
        split_store2_h(aohi, aolo, r1, acc[nj][2] * ib, acc[nj][3] * ib);
    }
}

// ---------------------------------------------------------------------------
// fp32 -> fp16 round (x input)
// ---------------------------------------------------------------------------
__global__ __launch_bounds__(256) void round_h_kernel(
    const float* __restrict__ in, __half* __restrict__ o, int n4)
{
    int i = blockIdx.x * 256 + threadIdx.x;
    if (i >= n4) return;
    float4 v = ((const float4*)in)[i];
    __half h[4];
    h[0] = __float2half_rn(v.x);
    h[1] = __float2half_rn(v.y);
    h[2] = __float2half_rn(v.z);
    h[3] = __float2half_rn(v.w);
    ((uint2*)o)[i] = *(uint2*)h;
}

// ---------------------------------------------------------------------------
// W[K,N] fp32 -> Wt[N,K] fp16 single (transpose + round)
// ---------------------------------------------------------------------------
__global__ __launch_bounds__(256) void transpose_h_kernel(
    const float* __restrict__ W, __half* __restrict__ o16, int K, int N)
{
    __shared__ float tile[32][33];
    const int nx = blockIdx.x * 32;
    const int ky = blockIdx.y * 32;
    const int tx = threadIdx.x & 31;
    const int ty = threadIdx.x >> 5;
    #pragma unroll
    for (int i = 0; i < 4; i++)
        tile[ty + 8 * i][tx] = W[(size_t)(ky + ty + 8 * i) * N + nx + tx];
    __syncthreads();
    #pragma unroll
    for (int i = 0; i < 4; i++) {
        float v = tile[tx][ty + 8 * i];
        o16[(size_t)(nx + ty + 8 * i) * K + ky + tx] = __float2half_rn(v);
    }
}

// ---------------------------------------------------------------------------
extern "C" void kernel_launch(void* const* d_in, const int* in_sizes, int n_in,
                              void* d_out, int out_size)
{
    const float* x     = (const float*)d_in[0];
    const float* mask  = (const float*)d_in[1];
    const float* W_qkv = (const float*)d_in[2];
    const float* W_h   = (const float*)d_in[3];
    const float* b_h   = (const float*)d_in[4];

    float* out  = (float*)d_out;
    float* attn = out + (size_t)BL * D_MODEL;

    __half *x16, *wq16, *wh16, *q16, *e16, *aohi, *aolo;
    float *psum, *inv;
    cudaGetSymbolAddress((void**)&x16, g_x16);
    cudaGetSymbolAddress((void**)&wq16, g_wq16);
    cudaGetSymbolAddress((void**)&wh16, g_wh16);
    cudaGetSymbolAddress((void**)&q16, g_q16);
    cudaGetSymbolAddress((void**)&aohi, g_ao16h);
    cudaGetSymbolAddress((void**)&aolo, g_ao16l);
    cudaGetSymbolAddress((void**)&psum, g_psum);
    cudaGetSymbolAddress((void**)&inv, g_inv);
    cudaGetSymbolAddress((void**)&e16, g_e16);

    cudaFuncSetAttribute(qkv_gemm_f16_kernel, cudaFuncAttributeMaxDynamicSharedMemorySize, SMEM_QKV);
    cudaFuncSetAttribute(outproj_gemm_f16_kernel, cudaFuncAttributeMaxDynamicSharedMemorySize, SMEM_OP);
    cudaFuncSetAttribute(scores_mma_kernel, cudaFuncAttributeMaxDynamicSharedMemorySize, SMEM_SCORES);
    cudaFuncSetAttribute(av_mma_kernel, cudaFuncAttributeMaxDynamicSharedMemorySize, SMEM_AV);

    // 0) input conversions
    round_h_kernel<<<(BL * D_MODEL / 4 + 255) / 256, 256>>>(x, x16, BL * D_MODEL / 4);
    transpose_h_kernel<<<dim3(D3 / 32, D_MODEL / 32), 256>>>(W_qkv, wq16, D_MODEL, D3);
    transpose_h_kernel<<<dim3(D_MODEL / 32, D_MODEL / 32), 256>>>(W_h, wh16, D_MODEL, D_MODEL);

    // 1) QKV = x @ W_qkv (fp16 1-term, BK=64) -> fp16
    qkv_gemm_f16_kernel<<<dim3(D3 / 128, BL / 128), 256, SMEM_QKV>>>(
        x16, wq16, q16, BL, D3, D_MODEL);

    // 2) scores (fp16 1-term) + fused exp -> fp16 scratch + psums
    scores_mma_kernel<<<dim3(SEQ / 128, SEQ / 128, BATCH * HEADS), 256, SMEM_SCORES>>>(
        mask, e16, q16, psum);

    // 3) row-sum inverse
    rowinv_kernel<<<NROWS / 256, 256>>>(psum, inv);

    // 4) attn @ V (1-term fp16) + normalized fp32 attn write -> ao fp16 hi/lo
    av_mma_kernel<<<dim3(SEQ / 128, BATCH * HEADS), 256, SMEM_AV>>>(
        e16, attn, q16, aohi, aolo, inv);

    // 5) output = ao @ W_h + b_h (fp16 2-term)
    outproj_gemm_f16_kernel<<<dim3(D_MODEL / 128, BL / 128), 256, SMEM_OP>>>(
        aohi, aolo, wh16, out, b_h, BL, D_MODEL, D_MODEL);
}

// round 14
// speedup vs baseline: 2.7865x; 1.0026x over previous
#include <cuda_runtime.h>
#include <cuda_bf16.h>
#include <cuda_fp16.h>
#include <math.h>
#include <stdint.h>

#define D_MODEL 1024
#define HEADS 16
#define HD 64
#define BATCH 2
#define SEQ 2048
#define BL (BATCH * SEQ)      /* 4096 */
#define D3 (3 * D_MODEL)      /* 3072 */
#define NROWS (BATCH * HEADS * SEQ)

typedef __nv_bfloat16 bf16;

// ---------------------------------------------------------------------------
// Scratch (allocation-free: __device__ globals)
// ---------------------------------------------------------------------------
__device__ __half g_x16[(size_t)BL * D_MODEL];
__device__ __half g_wq16[(size_t)D3 * D_MODEL];
__device__ __half g_wh16[(size_t)D_MODEL * D_MODEL];
__device__ __half g_q16[(size_t)BL * D3];        // QKV fp16
__device__ __half g_ao16h[(size_t)BL * D_MODEL]; // attn_out fp16 hi
__device__ __half g_ao16l[(size_t)BL * D_MODEL]; // attn_out fp16 lo
__device__ float g_psum[(size_t)NROWS * 16];
__device__ __half g_e16[(size_t)NROWS * SEQ];    // unnormalized exp, fp16

// ---------------------------------------------------------------------------
// Portable PTX helpers
// ---------------------------------------------------------------------------
__device__ __forceinline__ uint32_t smem_u32(const void* p) {
    uint32_t a;
    asm("{ .reg .u64 t; cvta.to.shared.u64 t, %1; cvt.u32.u64 %0, t; }"
        : "=r"(a) : "l"(p));
    return a;
}
__device__ __forceinline__ void cp_async16(uint32_t s, const void* g) {
    asm volatile("cp.async.cg.shared.global [%0], [%1], 16;" :: "r"(s), "l"(g));
}
#define CP_COMMIT() asm volatile("cp.async.commit_group;" ::: "memory")
#define CP_WAIT(n)  asm volatile("cp.async.wait_group %0;" :: "n"(n) : "memory")

__device__ __forceinline__ void ldm_x4(uint32_t addr, uint32_t* r) {
    asm volatile("ldmatrix.sync.aligned.m8n8.x4.shared.b16 {%0,%1,%2,%3}, [%4];"
        : "=r"(r[0]), "=r"(r[1]), "=r"(r[2]), "=r"(r[3]) : "r"(addr));
}
__device__ __forceinline__ void ldm_x4_trans(uint32_t addr, uint32_t* r) {
    asm volatile("ldmatrix.sync.aligned.m8n8.x4.trans.shared.b16 {%0,%1,%2,%3}, [%4];"
        : "=r"(r[0]), "=r"(r[1]), "=r"(r[2]), "=r"(r[3]) : "r"(addr));
}
__device__ __forceinline__ void mma_f16(float* c, const uint32_t* a, const uint32_t* b) {
    asm volatile(
        "mma.sync.aligned.m16n8k16.row.col.f32.f16.f16.f32 "
        "{%0,%1,%2,%3}, {%4,%5,%6,%7}, {%8,%9}, {%0,%1,%2,%3};"
        : "+f"(c[0]), "+f"(c[1]), "+f"(c[2]), "+f"(c[3])
        : "r"(a[0]), "r"(a[1]), "r"(a[2]), "r"(a[3]), "r"(b[0]), "r"(b[1]));
}
__device__ __forceinline__ void split_store2_h(__half* hi, __half* lo, size_t idx,
                                               float a, float b) {
    __half ha = __float2half_rn(a), hb = __float2half_rn(b);
    __half la = __float2half_rn(a - __half2float(ha));
    __half lb = __float2half_rn(b - __half2float(hb));
    __half2 hv; hv.x = ha; hv.y = hb;
    __half2 lv; lv.x = la; lv.y = lb;
    *(__half2*)(hi + idx) = hv;
    *(__half2*)(lo + idx) = lv;
}
__device__ __forceinline__ float fexp(float x) {
    float t = x * 1.4426950408889634f;
    t = fmaxf(t, -126.0f);
    float n = rintf(t);
    float f = t - n;
    float p = 1.5403530e-4f;
    p = fmaf(p, f, 1.3333558e-3f);
    p = fmaf(p, f, 9.6181291e-3f);
    p = fmaf(p, f, 5.5504109e-2f);
    p = fmaf(p, f, 2.4022651e-1f);
    p = fmaf(p, f, 6.9314718e-1f);
    p = fmaf(p, f, 1.0f);
    return p * __int_as_float(((int)n + 127) << 23);
}

// ---------------------------------------------------------------------------
// fp16 1-term QKV GEMM: C = A @ B^T, fp16 out. BK=64, 3-stage pipeline.
// ---------------------------------------------------------------------------
#define QBK 64
#define QGP 72
#define QT_ELEMS (128 * QGP)             /* 9216 halfs / tile */
#define QS_ELEMS (2 * QT_ELEMS)
#define SMEM_QKV (3 * QS_ELEMS * 2)      /* 110592 B */

__global__ __launch_bounds__(256, 2) void qkv_gemm_f16_kernel(
    const __half* __restrict__ A, const __half* __restrict__ B,
    __half* __restrict__ C, int M, int N, int K)
{
    extern __shared__ __half smq[];
    const uint32_t sbase = smem_u32(smq);
    const int t = threadIdx.x;
    const int warp = t >> 5, lane = t & 31;
    const int bm = blockIdx.y * 128;
    const int bn = blockIdx.x * 128;
    const int wm = (warp >> 1) * 32;
    const int wn = (warp & 1) * 64;

    const __half* srcs[2] = { A, B };

    auto load_stage = [&](int buf, int k0) {
        uint32_t sdst = sbase + (uint32_t)buf * QS_ELEMS * 2;
        #pragma unroll
        for (int m = 0; m < 2; m++) {
            const int rbase = (m == 0) ? bm : bn;
            const __half* S = srcs[m] + (size_t)rbase * K + k0;
            uint32_t td = sdst + (uint32_t)m * QT_ELEMS * 2;
            #pragma unroll
            for (int i = 0; i < 4; i++) {
                int id = t + i * 256;
                int row = id >> 3, c = id & 7;
                cp_async16(td + (uint32_t)(row * QGP + c * 8) * 2,
                           S + (size_t)row * K + c * 8);
            }
        }
        CP_COMMIT();
    };

    float acc[2][8][4];
    #pragma unroll
    for (int mi = 0; mi < 2; mi++)
        #pragma unroll
        for (int nj = 0; nj < 8; nj++)
            #pragma unroll
            for (int e = 0; e < 4; e++) acc[mi][nj][e] = 0.0f;

    const int nch = K >> 6;                 /* 16 */
    load_stage(0, 0);
    load_stage(1, QBK);

    const int a_r = (lane & 7) + ((lane >> 3) & 1) * 8;
    const int a_c = (lane >> 4) * 8;
    const int b_r = (lane & 7) + (lane >> 4) * 8;
    const int b_c = ((lane >> 3) & 1) * 8;

    int buf = 0;
    for (int c = 0; c < nch; c++) {
        CP_WAIT(1);
        __syncthreads();

        const uint32_t stg = sbase + (uint32_t)buf * QS_ELEMS * 2;
        const uint32_t tA = stg;
        const uint32_t tB = stg + QT_ELEMS * 2;

        #pragma unroll
        for (int ks = 0; ks < QBK; ks += 16) {
            uint32_t ah[2][4], bh[16];
            #pragma unroll
            for (int mi = 0; mi < 2; mi++) {
                uint32_t off = (uint32_t)((wm + mi * 16 + a_r) * QGP + ks + a_c) * 2;
                ldm_x4(tA + off, ah[mi]);
            }
            #pragma unroll
            for (int nj2 = 0; nj2 < 4; nj2++) {
                uint32_t off = (uint32_t)((wn + nj2 * 16 + b_r) * QGP + ks + b_c) * 2;
                ldm_x4(tB + off, bh + nj2 * 4);
            }
            #pragma unroll
            for (int mi = 0; mi < 2; mi++)
                #pragma unroll
                for (int nj = 0; nj < 8; nj++)
                    mma_f16(acc[mi][nj], ah[mi], bh + nj * 2);
        }
        __syncthreads();
        if (c + 2 < nch) {
            int nb = buf + 2;
            if (nb >= 3) nb -= 3;
            load_stage(nb, (c + 2) * QBK);
        } else {
            CP_COMMIT();                    /* empty group keeps count uniform */
        }
        buf = (buf + 1 == 3) ? 0 : buf + 1;
    }

    const int group = lane >> 2, tid4 = lane & 3;
    #pragma unroll
    for (int mi = 0; mi < 2; mi++) {
        int r0 = bm + wm + mi * 16 + group;
        #pragma unroll
        for (int nj = 0; nj < 8; nj++) {
            int cc = bn + wn + nj * 8 + tid4 * 2;
            __half2 v0; v0.x = __float2half_rn(acc[mi][nj][0]);
            v0.y = __float2half_rn(acc[mi][nj][1]);
            __half2 v1; v1.x = __float2half_rn(acc[mi][nj][2]);
            v1.y = __float2half_rn(acc[mi][nj][3]);
            *(__half2*)(C + (size_t)r0 * N + cc) = v0;
            *(__half2*)(C + (size_t)(r0 + 8) * N + cc) = v1;
        }
    }
}

// ---------------------------------------------------------------------------
// fp16 2-term out-proj GEMM (R12-proven): C = (Ahi+Alo) @ B^T + bias.
// ---------------------------------------------------------------------------
#define BK 32
#define GP 40
#define GT_ELEMS (128 * GP)
#define OS_ELEMS (3 * GT_ELEMS)
#define SMEM_OP (2 * OS_ELEMS * 2)

__global__ __launch_bounds__(256, 2) void outproj_gemm_f16_kernel(
    const __half* __restrict__ Ahi, const __half* __restrict__ Alo,
    const __half* __restrict__ B, float* __restrict__ C,
    const float* __restrict__ bias, int M, int N, int K)
{
    extern __shared__ __half smq[];
    const uint32_t sbase = smem_u32(smq);
    const int t = threadIdx.x;
    const int warp = t >> 5, lane = t & 31;
    const int bm = blockIdx.y * 128;
    const int bn = blockIdx.x * 128;
    const int wm = (warp >> 1) * 32;
    const int wn = (warp & 1) * 64;

    const __half* srcs[3] = { Ahi, Alo, B };

    auto load_stage = [&](int buf, int k0) {
        uint32_t sdst = sbase + (uint32_t)buf * OS_ELEMS * 2;
        #pragma unroll
        for (int m = 0; m < 3; m++) {
            const int rbase = (m < 2) ? bm : bn;
            const __half* S = srcs[m] + (size_t)rbase * K + k0;
            uint32_t td = sdst + (uint32_t)m * GT_ELEMS * 2;
            #pragma unroll
            for (int i = 0; i < 2; i++) {
                int id = t + i * 256;
                int row = id >> 2, c = id & 3;
                cp_async16(td + (uint32_t)(row * GP + c * 8) * 2,
                           S + (size_t)row * K + c * 8);
            }
        }
        CP_COMMIT();
    };

    float acc[2][8][4];
    #pragma unroll
    for (int mi = 0; mi < 2; mi++)
        #pragma unroll
        for (int nj = 0; nj < 8; nj++)
            #pragma unroll
            for (int e = 0; e < 4; e++) acc[mi][nj][e] = 0.0f;

    const int nch = K >> 5;
    load_stage(0, 0);
    load_stage(1, BK);

    const int a_r = (lane & 7) + ((lane >> 3) & 1) * 8;
    const int a_c = (lane >> 4) * 8;
    const int b_r = (lane & 7) + (lane >> 4) * 8;
    const int b_c = ((lane >> 3) & 1) * 8;

    for (int c = 0; c < nch; c++) {
        if (c < nch - 1) { CP_WAIT(1); } else { CP_WAIT(0); }
        __syncthreads();

        const uint32_t stg = sbase + (uint32_t)(c & 1) * OS_ELEMS * 2;
        const uint32_t tAhi = stg;
        const uint32_t tAlo = stg + GT_ELEMS * 2;
        const uint32_t tB = stg + 2 * GT_ELEMS * 2;

        #pragma unroll
        for (int ks = 0; ks < BK; ks += 16) {
            uint32_t ah[2][4], al[2][4], bh[16];
            #pragma unroll
            for (int mi = 0; mi < 2; mi++) {
                uint32_t off = (uint32_t)((wm + mi * 16 + a_r) * GP + ks + a_c) * 2;
                ldm_x4(tAhi + off, ah[mi]);
                ldm_x4(tAlo + off, al[mi]);
            }
            #pragma unroll
            for (int nj2 = 0; nj2 < 4; nj2++) {
                uint32_t off = (uint32_t)((wn + nj2 * 16 + b_r) * GP + ks + b_c) * 2;
                ldm_x4(tB + off, bh + nj2 * 4);
            }
            #pragma unroll
            for (int mi = 0; mi < 2; mi++)
                #pragma unroll
                for (int nj = 0; nj < 8; nj++) {
                    mma_f16(acc[mi][nj], ah[mi], bh + nj * 2);
                    mma_f16(acc[mi][nj], al[mi], bh + nj * 2);
                }
        }
        __syncthreads();
        if (c + 2 < nch) load_stage(c & 1, (c + 2) * BK);
    }

    const int group = lane >> 2, tid4 = lane & 3;
    #pragma unroll
    for (int mi = 0; mi < 2; mi++) {
        int r0 = bm + wm + mi * 16 + group;
        #pragma unroll
        for (int nj = 0; nj < 8; nj++) {
            int cc = bn + wn + nj * 8 + tid4 * 2;
            float2 bb = *(const float2*)(bias + cc);
            *(float2*)(C + (size_t)r0 * N + cc) =
                make_float2(acc[mi][nj][0] + bb.x, acc[mi][nj][1] + bb.y);
            *(float2*)(C + (size_t)(r0 + 8) * N + cc) =
                make_float2(acc[mi][nj][2] + bb.x, acc[mi][nj][3] + bb.y);
        }
    }
}

// ---------------------------------------------------------------------------
// Scores via fp16 HMMA 1-term (R11-proven).
// ---------------------------------------------------------------------------
#define SP 72
#define ST_ELEMS (128 * SP)
#define SMEM_SCORES (2 * ST_ELEMS * 2)

__global__ __launch_bounds__(256, 2) void scores_mma_kernel(
    const float* __restrict__ mask, __half* __restrict__ e16,
    const __half* __restrict__ q16, float* __restrict__ psum)
{
    extern __shared__ __half smh[];
    const uint32_t sbase = smem_u32(smh);
    const int t = threadIdx.x;
    const int warp = t >> 5, lane = t & 31;
    const int bh = blockIdx.z;
    const int b = bh / HEADS, h = bh % HEADS;
    const int bm = blockIdx.y * 128;
    const int bn = blockIdx.x * 128;
    const int wm = (warp >> 1) * 32;
    const int wn = (warp & 1) * 64;

    const __half* bases[2] = {
        q16 + ((size_t)(b * SEQ + bm)) * D3 + h * HD,
        q16 + ((size_t)(b * SEQ + bn)) * D3 + D_MODEL + h * HD };
    #pragma unroll
    for (int m = 0; m < 2; m++) {
        uint32_t td = sbase + (uint32_t)m * ST_ELEMS * 2;
        #pragma unroll
        for (int i = 0; i < 4; i++) {
            int id = t + i * 256;
            int r = id >> 3, c = id & 7;
            cp_async16(td + (uint32_t)(r * SP + c * 8) * 2,
                       bases[m] + (size_t)r * D3 + c * 8);
        }
    }
    CP_COMMIT();

    float acc[2][8][4];
    #pragma unroll
    for (int mi = 0; mi < 2; mi++)
        #pragma unroll
        for (int nj = 0; nj < 8; nj++)
            #pragma unroll
            for (int e = 0; e < 4; e++) acc[mi][nj][e] = 0.0f;

    const int a_r = (lane & 7) + ((lane >> 3) & 1) * 8;
    const int a_c = (lane >> 4) * 8;
    const int b_r = (lane & 7) + (lane >> 4) * 8;
    const int b_c = ((lane >> 3) & 1) * 8;

    const uint32_t tQ = sbase;
    const uint32_t tK = sbase + ST_ELEMS * 2;

    CP_WAIT(0);
    __syncthreads();

    #pragma unroll
    for (int ks = 0; ks < 4; ks++) {
        uint32_t ah[2][4], bhf[16];
        #pragma unroll
        for (int mi = 0; mi < 2; mi++) {
            uint32_t off = (uint32_t)((wm + mi * 16 + a_r) * SP + ks * 16 + a_c) * 2;
            ldm_x4(tQ + off, ah[mi]);
        }
        #pragma unroll
        for (int nj2 = 0; nj2 < 4; nj2++) {
            uint32_t off = (uint32_t)((wn + nj2 * 16 + b_r) * SP + ks * 16 + b_c) * 2;
            ldm_x4(tK + off, bhf + nj2 * 4);
        }
        #pragma unroll
        for (int mi = 0; mi < 2; mi++)
            #pragma unroll
            for (int nj = 0; nj < 8; nj++)
                mma_f16(acc[mi][nj], ah[mi], bhf + nj * 2);
    }

    const int group = lane >> 2, tid4 = lane & 3;
    float mq[4];
    #pragma unroll
    for (int mi = 0; mi < 2; mi++) {
        mq[mi * 2 + 0] = mask[b * SEQ + bm + wm + mi * 16 + group];
        mq[mi * 2 + 1] = mask[b * SEQ + bm + wm + mi * 16 + group + 8];
    }
    __half* out = e16 + (size_t)bh * SEQ * SEQ;
    float srow[2][2];
    srow[0][0] = srow[0][1] = srow[1][0] = srow[1][1] = 0.0f;
    #pragma unroll
    for (int nj = 0; nj < 8; nj++) {
        int cc = bn + wn + nj * 8 + tid4 * 2;
        float2 mk = *(const float2*)(mask + b * SEQ + cc);
        #pragma unroll
        for (int mi = 0; mi < 2; mi++) {
            int r0 = bm + wm + mi * 16 + group;
            float v0 = acc[mi][nj][0], v1 = acc[mi][nj][1];
            float v2 = acc[mi][nj][2], v3 = acc[mi][nj][3];
            if (mq[mi * 2 + 0] * mk.x == 0.0f) v0 = -100000.0f;
            if (mq[mi * 2 + 0] * mk.y == 0.0f) v1 = -100000.0f;
            if (mq[mi * 2 + 1] * mk.x == 0.0f) v2 = -100000.0f;
            if (mq[mi * 2 + 1] * mk.y == 0.0f) v3 = -100000.0f;
            __half h0 = __float2half_rn(fmaxf(fexp(v0 * 0.03125f), 1e-7f));
            __half h1 = __float2half_rn(fmaxf(fexp(v1 * 0.03125f), 1e-7f));
            __half h2 = __float2half_rn(fmaxf(fexp(v2 * 0.03125f), 1e-7f));
            __half h3 = __float2half_rn(fmaxf(fexp(v3 * 0.03125f), 1e-7f));
            __half2 p01; p01.x = h0; p01.y = h1;
            __half2 p23; p23.x = h2; p23.y = h3;
            *(__half2*)(out + (size_t)r0 * SEQ + cc) = p01;
            *(__half2*)(out + (size_t)(r0 + 8) * SEQ + cc) = p23;
            srow[mi][0] += __half2float(h0) + __half2float(h1);
            srow[mi][1] += __half2float(h2) + __half2float(h3);
        }
    }
    #pragma unroll
    for (int mi = 0; mi < 2; mi++) {
        #pragma unroll
        for (int s = 0; s < 2; s++) {
            srow[mi][s] += __shfl_xor_sync(0xffffffffu, srow[mi][s], 1);
            srow[mi][s] += __shfl_xor_sync(0xffffffffu, srow[mi][s], 2);
        }
    }
    __syncthreads();
    float* rs = (float*)smh;
    if (tid4 == 0) {
        #pragma unroll
        for (int mi = 0; mi < 2; mi++) {
            rs[(wm + mi * 16 + group) * 2 + (warp & 1)] = srow[mi][0];
            rs[(wm + mi * 16 + group + 8) * 2 + (warp & 1)] = srow[mi][1];
        }
    }
    __syncthreads();
    if (t < 128)
        psum[((size_t)bh * SEQ + bm + t) * 16 + blockIdx.x] = rs[t * 2] + rs[t * 2 + 1];
}

// ---------------------------------------------------------------------------
// av (R13-proven) with FUSED row-sum inverse (reads psum directly).
// ---------------------------------------------------------------------------
#define EP 72
#define AVE(i) ((i) * 18432)
#define AVV(i) (36864 + (i) * 9216)
#define AVINV  55296
#define SMEM_AV (55296 + 512)

__global__ __launch_bounds__(256, 2) void av_mma_kernel(
    const __half* __restrict__ e16, float* __restrict__ attn,
    const __half* __restrict__ q16,
    __half* __restrict__ aohi, __half* __restrict__ aolo,
    const float* __restrict__ psum)
{
    extern __shared__ char smc[];
    const uint32_t sbase = smem_u32(smc);
    const int t = threadIdx.x;
    const int warp = t >> 5, lane = t & 31;
    const int bh = blockIdx.y;
    const int b = bh / HEADS, h = bh % HEADS;
    const int bm = blockIdx.x * 128;
    const int wm = warp * 16;

    const __half* Ebase = e16 + (size_t)bh * SEQ * SEQ + (size_t)bm * SEQ;
    float* Abase = attn + (size_t)bh * SEQ * SEQ + (size_t)bm * SEQ;
    const __half* V = q16 + (size_t)b * SEQ * D3 + 2 * D_MODEL + h * HD;

    float* inv_s = (float*)(smc + AVINV);
    if (t < 128) {
        const float* p = psum + ((size_t)bh * SEQ + bm + t) * 16;
        float4 a = *(const float4*)(p);
        float4 b2 = *(const float4*)(p + 4);
        float4 cc = *(const float4*)(p + 8);
        float4 d = *(const float4*)(p + 12);
        float s = a.x + a.y + a.z + a.w + b2.x + b2.y + b2.z + b2.w
                + cc.x + cc.y + cc.z + cc.w + d.x + d.y + d.z + d.w;
        inv_s[t] = 1.0f / s;
    }
    __syncthreads();

    auto load_chunk = [&](int c) {
        const int k0 = c * 64;
        const uint32_t buf = c & 1;
        #pragma unroll
        for (int i = 0; i < 4; i++) {
            int id = t + i * 256;
            int r = id >> 3, cs = id & 7;
            cp_async16(sbase + AVE(buf) + (uint32_t)(r * EP + cs * 8) * 2,
                       Ebase + (size_t)r * SEQ + k0 + cs * 8);
        }
        #pragma unroll
        for (int i = 0; i < 2; i++) {
            int id = t + i * 256;
            int r = id >> 3, cs = id & 7;
            cp_async16(sbase + AVV(buf) + (uint32_t)(r * EP + cs * 8) * 2,
                       V + (size_t)(k0 + r) * D3 + cs * 8);
        }
        CP_COMMIT();
    };

    float acc[8][4];
    #pragma unroll
    for (int nj = 0; nj < 8; nj++)
        #pragma unroll
        for (int e = 0; e < 4; e++) acc[nj][e] = 0.0f;

    load_chunk(0);

    const int a_r = (lane & 7) + ((lane >> 3) & 1) * 8;
    const int a_c = (lane >> 4) * 8;
    const int tb_r = lane & 15;
    const int tb_c = (lane >> 4) * 8;

    for (int c = 0; c < SEQ / 64; c++) {
        CP_WAIT(0);
        __syncthreads();
        const int k0 = c * 64;
        const uint32_t buf = c & 1;
        if (c + 1 < SEQ / 64) load_chunk(c + 1);

        const __half* Es = (const __half*)(smc + AVE(buf));
        #pragma unroll
        for (int i = 0; i < 8; i++) {
            int id = t + i * 256;
            int r = id >> 4, c4 = id & 15;
            uint2 raw = *(const uint2*)(Es + r * EP + c4 * 4);
            __half2 p01 = *(__half2*)&raw.x;
            __half2 p23 = *(__half2*)&raw.y;
            float s = inv_s[r];
            float4 o;
            o.x = __half2float(p01.x) * s;
            o.y = __half2float(p01.y) * s;
            o.z = __half2float(p23.x) * s;
            o.w = __half2float(p23.y) * s;
            *(float4*)(Abase + (size_t)r * SEQ + k0 + c4 * 4) = o;
        }

        const uint32_t tA = sbase + AVE(buf);
        const uint32_t tV = sbase + AVV(buf);
        #pragma unroll
        for (int ks = 0; ks < 4; ks++) {
            uint32_t ah[4], bhf[16];
            uint32_t aoff = (uint32_t)((wm + a_r) * EP + ks * 16 + a_c) * 2;
            ldm_x4(tA + aoff, ah);
            #pragma unroll
            for (int nj2 = 0; nj2 < 4; nj2++) {
                uint32_t boff =
                    (uint32_t)((ks * 16 + tb_r) * EP + nj2 * 16 + tb_c) * 2;
                ldm_x4_trans(tV + boff, bhf + nj2 * 4);
            }
            #pragma unroll
            for (int nj = 0; nj < 8; nj++)
                mma_f16(acc[nj], ah, bhf + nj * 2);
        }
    }

    const int group = lane >> 2, tid4 = lane & 3;
    const float ia = inv_s[wm + group];
    const float ib = inv_s[wm + group + 8];
    #pragma unroll
    for (int nj = 0; nj < 8; nj++) {
        int cc = h * HD + nj * 8 + tid4 * 2;
        size_t r0 = (size_t)(b * SEQ + bm + wm + group) * D_MODEL + cc;
        size_t r1 = r0 + (size_t)8 * D_MODEL;
        split_store2_h(aohi, aolo, r0, acc[nj][0] * ia, acc[nj][1] * ia);
        split_store2_h(aohi, aolo, r1, acc[nj][2] * ib, acc[nj][3] * ib);
    }
}

// ---------------------------------------------------------------------------
// fp32 -> fp16 round (x input)
// ---------------------------------------------------------------------------
__global__ __launch_bounds__(256) void round_h_kernel(
    const float* __restrict__ in, __half* __restrict__ o, int n4)
{
    int i = blockIdx.x * 256 + threadIdx.x;
    if (i >= n4) return;
    float4 v = ((const float4*)in)[i];
    __half h[4];
    h[0] = __float2half_rn(v.x);
    h[1] = __float2half_rn(v.y);
    h[2] = __float2half_rn(v.z);
    h[3] = __float2half_rn(v.w);
    ((uint2*)o)[i] = *(uint2*)h;
}

// ---------------------------------------------------------------------------
// W[K,N] fp32 -> Wt[N,K] fp16 single (transpose + round)
// ---------------------------------------------------------------------------
__global__ __launch_bounds__(256) void transpose_h_kernel(
    const float* __restrict__ W, __half* __restrict__ o16, int K, int N)
{
    __shared__ float tile[32][33];
    const int nx = blockIdx.x * 32;
    const int ky = blockIdx.y * 32;
    const int tx = threadIdx.x & 31;
    const int ty = threadIdx.x >> 5;
    #pragma unroll
    for (int i = 0; i < 4; i++)
        tile[ty + 8 * i][tx] = W[(size_t)(ky + ty + 8 * i) * N + nx + tx];
    __syncthreads();
    #pragma unroll
    for (int i = 0; i < 4; i++) {
        float v = tile[tx][ty + 8 * i];
        o16[(size_t)(nx + ty + 8 * i) * K + ky + tx] = __float2half_rn(v);
    }
}

// ---------------------------------------------------------------------------
extern "C" void kernel_launch(void* const* d_in, const int* in_sizes, int n_in,
                              void* d_out, int out_size)
{
    const float* x     = (const float*)d_in[0];
    const float* mask  = (const float*)d_in[1];
    const float* W_qkv = (const float*)d_in[2];
    const float* W_h   = (const float*)d_in[3];
    const float* b_h   = (const float*)d_in[4];

    float* out  = (float*)d_out;
    float* attn = out + (size_t)BL * D_MODEL;

    __half *x16, *wq16, *wh16, *q16, *e16, *aohi, *aolo;
    float *psum;
    cudaGetSymbolAddress((void**)&x16, g_x16);
    cudaGetSymbolAddress((void**)&wq16, g_wq16);
    cudaGetSymbolAddress((void**)&wh16, g_wh16);
    cudaGetSymbolAddress((void**)&q16, g_q16);
    cudaGetSymbolAddress((void**)&aohi, g_ao16h);
    cudaGetSymbolAddress((void**)&aolo, g_ao16l);
    cudaGetSymbolAddress((void**)&psum, g_psum);
    cudaGetSymbolAddress((void**)&e16, g_e16);

    cudaFuncSetAttribute(qkv_gemm_f16_kernel, cudaFuncAttributeMaxDynamicSharedMemorySize, SMEM_QKV);
    cudaFuncSetAttribute(outproj_gemm_f16_kernel, cudaFuncAttributeMaxDynamicSharedMemorySize, SMEM_OP);
    cudaFuncSetAttribute(scores_mma_kernel, cudaFuncAttributeMaxDynamicSharedMemorySize, SMEM_SCORES);
    cudaFuncSetAttribute(av_mma_kernel, cudaFuncAttributeMaxDynamicSharedMemorySize, SMEM_AV);

    // 0) input conversions
    round_h_kernel<<<(BL * D_MODEL / 4 + 255) / 256, 256>>>(x, x16, BL * D_MODEL / 4);
    transpose_h_kernel<<<dim3(D3 / 32, D_MODEL / 32), 256>>>(W_qkv, wq16, D_MODEL, D3);
    transpose_h_kernel<<<dim3(D_MODEL / 32, D_MODEL / 32), 256>>>(W_h, wh16, D_MODEL, D_MODEL);

    // 1) QKV = x @ W_qkv (fp16 1-term, BK=64, 3-stage) -> fp16
    qkv_gemm_f16_kernel<<<dim3(D3 / 128, BL / 128), 256, SMEM_QKV>>>(
        x16, wq16, q16, BL, D3, D_MODEL);

    // 2) scores (fp16 1-term) + fused exp -> fp16 scratch + psums
    scores_mma_kernel<<<dim3(SEQ / 128, SEQ / 128, BATCH * HEADS), 256, SMEM_SCORES>>>(
        mask, e16, q16, psum);

    // 3) attn @ V (fused rowinv, 1-term fp16) + normalized fp32 attn write
    av_mma_kernel<<<dim3(SEQ / 128, BATCH * HEADS), 256, SMEM_AV>>>(
        e16, attn, q16, aohi, aolo, psum);

    // 4) output = ao @ W_h + b_h (fp16 2-term)
    outproj_gemm_f16_kernel<<<dim3(D_MODEL / 128, BL / 128), 256, SMEM_OP>>>(
        aohi, aolo, wh16, out, b_h, BL, D_MODEL, D_MODEL);
}